// round 1
// baseline (speedup 1.0000x reference)
#include <cuda_runtime.h>
#include <math.h>

#define SEQ 1024
#define DM  768
#define NHEAD 12
#define HDIM 64
#define NLAYERS 4
#define DFF 3072

// ---------------- scratch (static device memory; no runtime allocs) ----------------
__device__ float g_relsum[(size_t)SEQ * SEQ * HDIM];          // 256 MB
__device__ float g_q[NHEAD * SEQ * HDIM];
__device__ float g_k[NHEAD * SEQ * HDIM];
__device__ float g_v[NHEAD * SEQ * HDIM];
__device__ float g_scores[(size_t)NHEAD * SEQ * SEQ];         // 48 MB
__device__ float g_ctx[SEQ * DM];
__device__ float g_proj[SEQ * DM];
__device__ float g_attn[SEQ * DM];
__device__ float g_inter[SEQ * DFF];
__device__ float g_ffn[SEQ * DM];
__device__ float g_h[SEQ * DM];

// ---------------- helpers ----------------
__device__ __forceinline__ float warpRedMax(float v) {
#pragma unroll
    for (int o = 16; o > 0; o >>= 1) v = fmaxf(v, __shfl_xor_sync(0xffffffffu, v, o));
    return v;
}
__device__ __forceinline__ float warpRedSum(float v) {
#pragma unroll
    for (int o = 16; o > 0; o >>= 1) v += __shfl_xor_sync(0xffffffffu, v, o);
    return v;
}

// ---------------- relsum = rel_pos + rel_2d_pos + rel_2d_angle ----------------
__global__ void __launch_bounds__(256) relsum_kernel(
    const float4* __restrict__ a, const float4* __restrict__ b,
    const float4* __restrict__ c, float4* __restrict__ out, int n4)
{
    int i = blockIdx.x * blockDim.x + threadIdx.x;
    int stride = gridDim.x * blockDim.x;
    for (; i < n4; i += stride) {
        float4 x = a[i], y = b[i], z = c[i];
        x.x += y.x + z.x; x.y += y.y + z.y; x.z += y.z + z.z; x.w += y.w + z.w;
        out[i] = x;
    }
}

// ---------------- generic NT GEMM: C[m,n] = sum_k A[m,k]*W[n,k] (+bias) ----------------
// EPI: 0=none, 1=exact GELU.  OUTMODE: 0 -> C[m*ldC+n]; 1 -> head layout C[(head*SEQ+m)*64+hd]
template<int EPI, int OUTMODE>
__global__ void __launch_bounds__(256) gemm_nt(
    const float* __restrict__ A, const float* __restrict__ W,
    const float* __restrict__ bias, float* __restrict__ C,
    int M, int N, int K, int ldC,
    long long sA, long long sW, long long sC, float scale)
{
    const int bz = blockIdx.z;
    A += sA * bz; W += sW * bz; C += sC * bz;

    __shared__ float As[16][65];
    __shared__ float Bs[16][65];

    const int tid = threadIdx.x;
    const int tx = tid & 15, ty = tid >> 4;
    const int m0 = blockIdx.y << 6, n0 = blockIdx.x << 6;
    const int lr = tid >> 2;            // 0..63
    const int lk = (tid & 3) << 2;      // 0,4,8,12

    float acc[4][4];
#pragma unroll
    for (int i = 0; i < 4; i++)
#pragma unroll
        for (int j = 0; j < 4; j++) acc[i][j] = 0.f;

    const float* Ap = A + (long long)(m0 + lr) * K + lk;
    const float* Wp = W + (long long)(n0 + lr) * K + lk;

    for (int kt = 0; kt < K; kt += 16) {
        float4 av = *(const float4*)(Ap + kt);
        float4 wv = *(const float4*)(Wp + kt);
        As[lk + 0][lr] = av.x; As[lk + 1][lr] = av.y; As[lk + 2][lr] = av.z; As[lk + 3][lr] = av.w;
        Bs[lk + 0][lr] = wv.x; Bs[lk + 1][lr] = wv.y; Bs[lk + 2][lr] = wv.z; Bs[lk + 3][lr] = wv.w;
        __syncthreads();
#pragma unroll
        for (int kk = 0; kk < 16; kk++) {
            float a0 = As[kk][ty * 4 + 0], a1 = As[kk][ty * 4 + 1];
            float a2 = As[kk][ty * 4 + 2], a3 = As[kk][ty * 4 + 3];
            float b0 = Bs[kk][tx * 4 + 0], b1 = Bs[kk][tx * 4 + 1];
            float b2 = Bs[kk][tx * 4 + 2], b3 = Bs[kk][tx * 4 + 3];
            acc[0][0] += a0 * b0; acc[0][1] += a0 * b1; acc[0][2] += a0 * b2; acc[0][3] += a0 * b3;
            acc[1][0] += a1 * b0; acc[1][1] += a1 * b1; acc[1][2] += a1 * b2; acc[1][3] += a1 * b3;
            acc[2][0] += a2 * b0; acc[2][1] += a2 * b1; acc[2][2] += a2 * b2; acc[2][3] += a2 * b3;
            acc[3][0] += a3 * b0; acc[3][1] += a3 * b1; acc[3][2] += a3 * b2; acc[3][3] += a3 * b3;
        }
        __syncthreads();
    }

#pragma unroll
    for (int i = 0; i < 4; i++) {
        const int m = m0 + ty * 4 + i;
#pragma unroll
        for (int j = 0; j < 4; j++) {
            const int n = n0 + tx * 4 + j;
            float v = acc[i][j];
            if (bias) v += bias[n];
            if (EPI == 1) v = 0.5f * v * (1.0f + erff(v * 0.70710678118654752f));
            v *= scale;
            if (OUTMODE == 0) {
                C[(long long)m * ldC + n] = v;
            } else {
                const int head = n >> 6, hd = n & 63;
                C[((head << 10) + m) * 64 + hd] = v;
            }
        }
    }
}

// ---------------- NN GEMM: C[m,n] = sum_k A[m,k]*B[k,n] (ctx = probs @ V) ----------------
__global__ void __launch_bounds__(256) gemm_nn(
    const float* __restrict__ A, const float* __restrict__ B, float* __restrict__ C,
    int M, int N, int K, int ldC, long long sA, long long sB, long long sC)
{
    const int bz = blockIdx.z;
    A += sA * bz; B += sB * bz; C += sC * bz;

    __shared__ float As[16][65];
    __shared__ float Bs[16][65];

    const int tid = threadIdx.x;
    const int tx = tid & 15, ty = tid >> 4;
    const int m0 = blockIdx.y << 6, n0 = blockIdx.x << 6;
    const int lr = tid >> 2;
    const int lk = (tid & 3) << 2;
    const int bk = tid >> 4;            // 0..15
    const int bn = (tid & 15) << 2;     // 0..60

    float acc[4][4];
#pragma unroll
    for (int i = 0; i < 4; i++)
#pragma unroll
        for (int j = 0; j < 4; j++) acc[i][j] = 0.f;

    const float* Ap = A + (long long)(m0 + lr) * K + lk;

    for (int kt = 0; kt < K; kt += 16) {
        float4 av = *(const float4*)(Ap + kt);
        As[lk + 0][lr] = av.x; As[lk + 1][lr] = av.y; As[lk + 2][lr] = av.z; As[lk + 3][lr] = av.w;
        float4 bv = *(const float4*)(B + (long long)(kt + bk) * N + n0 + bn);
        Bs[bk][bn + 0] = bv.x; Bs[bk][bn + 1] = bv.y; Bs[bk][bn + 2] = bv.z; Bs[bk][bn + 3] = bv.w;
        __syncthreads();
#pragma unroll
        for (int kk = 0; kk < 16; kk++) {
            float a0 = As[kk][ty * 4 + 0], a1 = As[kk][ty * 4 + 1];
            float a2 = As[kk][ty * 4 + 2], a3 = As[kk][ty * 4 + 3];
            float b0 = Bs[kk][tx * 4 + 0], b1 = Bs[kk][tx * 4 + 1];
            float b2 = Bs[kk][tx * 4 + 2], b3 = Bs[kk][tx * 4 + 3];
            acc[0][0] += a0 * b0; acc[0][1] += a0 * b1; acc[0][2] += a0 * b2; acc[0][3] += a0 * b3;
            acc[1][0] += a1 * b0; acc[1][1] += a1 * b1; acc[1][2] += a1 * b2; acc[1][3] += a1 * b3;
            acc[2][0] += a2 * b0; acc[2][1] += a2 * b1; acc[2][2] += a2 * b2; acc[2][3] += a2 * b3;
            acc[3][0] += a3 * b0; acc[3][1] += a3 * b1; acc[3][2] += a3 * b2; acc[3][3] += a3 * b3;
        }
        __syncthreads();
    }

#pragma unroll
    for (int i = 0; i < 4; i++) {
        const int m = m0 + ty * 4 + i;
#pragma unroll
        for (int j = 0; j < 4; j++) {
            const int n = n0 + tx * 4 + j;
            C[(long long)m * ldC + n] = acc[i][j];
        }
    }
}

// ---------------- rel term: scores[n,s,k] += sum_h q[n,s,h] * relsum[s,k,h] ----------------
// block = (k-tile of 128, one s). smem tile of relsum amortized across all 12 heads.
__global__ void __launch_bounds__(256) rel_add_kernel(
    const float* __restrict__ rel, const float* __restrict__ qb, float* __restrict__ scores)
{
    const int s  = blockIdx.y;
    const int kt = blockIdx.x << 7;   // *128

    __shared__ __align__(16) float relb[128][76];   // pitch 76 -> conflict-free LDS.128
    __shared__ __align__(16) float qs[12][64];

    const int tid = threadIdx.x;

    // load q for this s: q[n][s][h]
    for (int i = tid; i < 12 * 64; i += 256)
        qs[i >> 6][i & 63] = qb[((i >> 6) << 16) + (s << 6) + (i & 63)];

    // stage relsum[s, kt..kt+127, 0..63] (coalesced float4)
    const float4* rp = (const float4*)(rel + (((long long)s << 10) + kt) * 64);
    for (int i = tid; i < 128 * 16; i += 256) {
        float4 t = rp[i];
        *(float4*)&relb[i >> 4][(i & 15) << 2] = t;
    }
    __syncthreads();

    const int hg = tid >> 6;          // head group 0..3 -> heads hg*3 .. hg*3+2
    const int k0 = tid & 63;          // this thread handles k0 and k0+64

    float acc[3][2];
#pragma unroll
    for (int j = 0; j < 3; j++) { acc[j][0] = 0.f; acc[j][1] = 0.f; }

#pragma unroll
    for (int h4 = 0; h4 < 64; h4 += 4) {
        float4 r0 = *(const float4*)&relb[k0][h4];
        float4 r1 = *(const float4*)&relb[k0 + 64][h4];
#pragma unroll
        for (int j = 0; j < 3; j++) {
            float4 qv = *(const float4*)&qs[hg * 3 + j][h4];
            acc[j][0] += qv.x * r0.x + qv.y * r0.y + qv.z * r0.z + qv.w * r0.w;
            acc[j][1] += qv.x * r1.x + qv.y * r1.y + qv.z * r1.z + qv.w * r1.w;
        }
    }

#pragma unroll
    for (int j = 0; j < 3; j++) {
        const int n = hg * 3 + j;
        const long long base = (((long long)n << 10) + s) * 1024 + kt;
        scores[base + k0]      += acc[j][0];
        scores[base + k0 + 64] += acc[j][1];
    }
}

// ---------------- safe softmax per row (CogView PB-relax == standard safe softmax) ----------------
__global__ void __launch_bounds__(256) softmax_kernel(
    float* __restrict__ scores, const float* __restrict__ mask)
{
    const long long row = blockIdx.x;
    float4* p = (float4*)(scores + row * 1024);
    const int tid = threadIdx.x;
    const int lane = tid & 31, wid = tid >> 5;
    __shared__ float red[8];

    float4 v = p[tid];
    const float4 mk = ((const float4*)mask)[tid];
    v.x += mk.x; v.y += mk.y; v.z += mk.z; v.w += mk.w;

    float m = fmaxf(fmaxf(v.x, v.y), fmaxf(v.z, v.w));
    m = warpRedMax(m);
    if (lane == 0) red[wid] = m;
    __syncthreads();
    float mall = red[0];
#pragma unroll
    for (int i = 1; i < 8; i++) mall = fmaxf(mall, red[i]);
    __syncthreads();

    float e0 = __expf(v.x - mall), e1 = __expf(v.y - mall);
    float e2 = __expf(v.z - mall), e3 = __expf(v.w - mall);
    float ssum = e0 + e1 + e2 + e3;
    ssum = warpRedSum(ssum);
    if (lane == 0) red[wid] = ssum;
    __syncthreads();
    float tot = 0.f;
#pragma unroll
    for (int i = 0; i < 8; i++) tot += red[i];
    const float inv = 1.0f / tot;
    p[tid] = make_float4(e0 * inv, e1 * inv, e2 * inv, e3 * inv);
}

// ---------------- residual + LayerNorm (two-pass, 1 block per row) ----------------
__global__ void __launch_bounds__(256) ln_kernel(
    const float* __restrict__ x, const float* __restrict__ res,
    const float* __restrict__ g, const float* __restrict__ b, float* __restrict__ out)
{
    const int s = blockIdx.x;
    const int tid = threadIdx.x;
    const int lane = tid & 31, wid = tid >> 5;
    __shared__ float red[8];

    float v[3];
    float lsum = 0.f;
#pragma unroll
    for (int i = 0; i < 3; i++) {
        const int idx = tid + i * 256;
        v[i] = x[s * 768 + idx] + res[s * 768 + idx];
        lsum += v[i];
    }
    lsum = warpRedSum(lsum);
    if (lane == 0) red[wid] = lsum;
    __syncthreads();
    float tot = 0.f;
#pragma unroll
    for (int i = 0; i < 8; i++) tot += red[i];
    const float mu = tot * (1.0f / 768.0f);
    __syncthreads();

    float ls2 = 0.f;
#pragma unroll
    for (int i = 0; i < 3; i++) { const float d = v[i] - mu; ls2 += d * d; }
    ls2 = warpRedSum(ls2);
    if (lane == 0) red[wid] = ls2;
    __syncthreads();
    float tot2 = 0.f;
#pragma unroll
    for (int i = 0; i < 8; i++) tot2 += red[i];
    const float rs = rsqrtf(tot2 * (1.0f / 768.0f) + 1e-12f);

#pragma unroll
    for (int i = 0; i < 3; i++) {
        const int idx = tid + i * 256;
        out[s * 768 + idx] = (v[i] - mu) * rs * g[idx] + b[idx];
    }
}

// ---------------- launcher ----------------
extern "C" void kernel_launch(void* const* d_in, const int* in_sizes, int n_in,
                              void* d_out, int out_size)
{
    const float* hid  = (const float*)d_in[0];
    const float* mask = (const float*)d_in[1];
    const float* rel  = (const float*)d_in[2];
    const float* rel2 = (const float*)d_in[3];
    const float* rela = (const float*)d_in[4];
    const float* Wq = (const float*)d_in[5];   const float* bq = (const float*)d_in[6];
    const float* Wk = (const float*)d_in[7];   const float* bk = (const float*)d_in[8];
    const float* Wv = (const float*)d_in[9];   const float* bv = (const float*)d_in[10];
    const float* Wo = (const float*)d_in[11];  const float* bo = (const float*)d_in[12];
    const float* g1 = (const float*)d_in[13];  const float* b1 = (const float*)d_in[14];
    const float* Wi = (const float*)d_in[15];  const float* bi = (const float*)d_in[16];
    const float* W2 = (const float*)d_in[17];  const float* b2 = (const float*)d_in[18];
    const float* g2 = (const float*)d_in[19];  const float* b2g = (const float*)d_in[20];

    float *relsum, *q, *k, *v, *scores, *ctx, *proj, *attn, *inter, *ffn, *hbuf;
    cudaGetSymbolAddress((void**)&relsum, g_relsum);
    cudaGetSymbolAddress((void**)&q, g_q);
    cudaGetSymbolAddress((void**)&k, g_k);
    cudaGetSymbolAddress((void**)&v, g_v);
    cudaGetSymbolAddress((void**)&scores, g_scores);
    cudaGetSymbolAddress((void**)&ctx, g_ctx);
    cudaGetSymbolAddress((void**)&proj, g_proj);
    cudaGetSymbolAddress((void**)&attn, g_attn);
    cudaGetSymbolAddress((void**)&inter, g_inter);
    cudaGetSymbolAddress((void**)&ffn, g_ffn);
    cudaGetSymbolAddress((void**)&hbuf, g_h);

    relsum_kernel<<<4096, 256>>>((const float4*)rel, (const float4*)rel2,
                                 (const float4*)rela, (float4*)relsum,
                                 (int)((size_t)SEQ * SEQ * HDIM / 4));

    const float* h = hid;
    for (int l = 0; l < NLAYERS; l++) {
        const size_t wofs  = (size_t)l * 768 * 768;
        const size_t wiofs = (size_t)l * 3072 * 768;

        // Q/K/V projections -> head layout; q pre-scaled by 1/sqrt(64)
        gemm_nt<0, 1><<<dim3(12, 16, 1), 256>>>(h, Wq + wofs, bq + l * 768, q,
                                                1024, 768, 768, 0, 0, 0, 0, 0.125f);
        gemm_nt<0, 1><<<dim3(12, 16, 1), 256>>>(h, Wk + wofs, bk + l * 768, k,
                                                1024, 768, 768, 0, 0, 0, 0, 1.0f);
        gemm_nt<0, 1><<<dim3(12, 16, 1), 256>>>(h, Wv + wofs, bv + l * 768, v,
                                                1024, 768, 768, 0, 0, 0, 0, 1.0f);

        // scores = q @ k^T (batched per head)
        gemm_nt<0, 0><<<dim3(16, 16, 12), 256>>>(q, k, nullptr, scores,
                                                 1024, 1024, 64, 1024,
                                                 65536LL, 65536LL, 1048576LL, 1.0f);

        // scores += q @ relsum[s]^T
        rel_add_kernel<<<dim3(8, 1024), 256>>>(relsum, q, scores);

        // safe softmax (+ mask)
        softmax_kernel<<<12 * 1024, 256>>>(scores, mask);

        // ctx = probs @ v, written directly into (s, head*64+hd) flat layout
        gemm_nn<<<dim3(1, 16, 12), 256>>>(scores, v, ctx,
                                          1024, 64, 1024, 768,
                                          1048576LL, 65536LL, 64LL);

        // output projection + residual LN
        gemm_nt<0, 0><<<dim3(12, 16, 1), 256>>>(ctx, Wo + wofs, bo + l * 768, proj,
                                                1024, 768, 768, 768, 0, 0, 0, 1.0f);
        ln_kernel<<<1024, 256>>>(proj, h, g1 + l * 768, b1 + l * 768, attn);

        // FFN
        gemm_nt<1, 0><<<dim3(48, 16, 1), 256>>>(attn, Wi + wiofs, bi + l * 3072, inter,
                                                1024, 3072, 768, 3072, 0, 0, 0, 1.0f);
        gemm_nt<0, 0><<<dim3(12, 16, 1), 256>>>(inter, W2 + wiofs, b2 + l * 768, ffn,
                                                1024, 768, 3072, 768, 0, 0, 0, 1.0f);

        float* outp = (l == NLAYERS - 1) ? (float*)d_out : hbuf;
        ln_kernel<<<1024, 256>>>(ffn, attn, g2 + l * 768, b2g + l * 768, outp);
        h = hbuf;
    }
}

// round 2
// speedup vs baseline: 1.9835x; 1.9835x over previous
#include <cuda_runtime.h>
#include <math.h>
#include <stdint.h>

#define SEQ 1024
#define DM  768
#define NHEAD 12
#define HDIM 64
#define NLAYERS 4
#define DFF 3072

// ---------------- scratch (static device memory; no runtime allocs) ----------------
__device__ float g_relsum[(size_t)SEQ * SEQ * HDIM];          // 256 MB
__device__ float g_q[NHEAD * SEQ * HDIM];
__device__ float g_k[NHEAD * SEQ * HDIM];
__device__ float g_vt[NHEAD * HDIM * SEQ];                    // V transposed per head
__device__ float g_scores[(size_t)NHEAD * SEQ * SEQ];         // 48 MB
__device__ float g_ctx[SEQ * DM];
__device__ float g_proj[SEQ * DM];
__device__ float g_attn[SEQ * DM];
__device__ float g_inter[SEQ * DFF];
__device__ float g_ffn[SEQ * DM];
__device__ float g_h[SEQ * DM];

// ---------------- helpers ----------------
__device__ __forceinline__ float warpRedMax(float v) {
#pragma unroll
    for (int o = 16; o > 0; o >>= 1) v = fmaxf(v, __shfl_xor_sync(0xffffffffu, v, o));
    return v;
}
__device__ __forceinline__ float warpRedSum(float v) {
#pragma unroll
    for (int o = 16; o > 0; o >>= 1) v += __shfl_xor_sync(0xffffffffu, v, o);
    return v;
}

__device__ __forceinline__ uint32_t f2tf(float x) {
    uint32_t r;
    asm("cvt.rna.tf32.f32 %0, %1;" : "=r"(r) : "f"(x));
    return r;
}

__device__ __forceinline__ void cp16(uint32_t dst, const void* src) {
    asm volatile("cp.async.cg.shared.global [%0], [%1], 16;" :: "r"(dst), "l"(src));
}

__device__ __forceinline__ void mma_tf32(float* c, const uint32_t* a, const uint32_t* b) {
    asm volatile(
        "mma.sync.aligned.m16n8k8.row.col.f32.tf32.tf32.f32 "
        "{%0,%1,%2,%3}, {%4,%5,%6,%7}, {%8,%9}, {%0,%1,%2,%3};"
        : "+f"(c[0]), "+f"(c[1]), "+f"(c[2]), "+f"(c[3])
        : "r"(a[0]), "r"(a[1]), "r"(a[2]), "r"(a[3]), "r"(b[0]), "r"(b[1]));
}

// ---------------- relsum = rel_pos + rel_2d_pos + rel_2d_angle ----------------
__global__ void __launch_bounds__(256) relsum_kernel(
    const float4* __restrict__ a, const float4* __restrict__ b,
    const float4* __restrict__ c, float4* __restrict__ out, int n4)
{
    int i = blockIdx.x * blockDim.x + threadIdx.x;
    int stride = gridDim.x * blockDim.x;
    for (; i < n4; i += stride) {
        float4 x = a[i], y = b[i], z = c[i];
        x.x += y.x + z.x; x.y += y.y + z.y; x.z += y.z + z.z; x.w += y.w + z.w;
        out[i] = x;
    }
}

// ---------------- tf32 tensor-core NT GEMM ----------------
// C[m,n] = sum_k A[m,k] * W[n,k]  (+bias, optional GELU, scale)
// BM=128, BN=64, BK=16, 256 threads (8 warps: 4 along M x 2 along N, warp tile 32x32)
// OUTMODE: 0 -> C[m*ldC+n]; 1 -> q/k head layout; 2 -> v transposed per head
template<int EPI, int OUTMODE>
__global__ void __launch_bounds__(256) gemm_tc(
    const float* __restrict__ A, const float* __restrict__ W,
    const float* __restrict__ bias, float* __restrict__ C,
    int K, int ldC, long long sA, long long sW, long long sC, float scale)
{
    const int bz = blockIdx.z;
    A += sA * bz; W += sW * bz; C += sC * bz;
    const int m0 = blockIdx.y << 7;
    const int n0 = blockIdx.x << 6;

    __shared__ float As[2][128][20];
    __shared__ float Ws[2][64][20];

    const int tid  = threadIdx.x;
    const int wid  = tid >> 5, lane = tid & 31;
    const int wm   = wid & 3,  wn   = wid >> 2;
    const int g    = lane >> 2, t   = lane & 3;

    float acc[2][4][4];
#pragma unroll
    for (int i = 0; i < 2; i++)
#pragma unroll
        for (int j = 0; j < 4; j++)
#pragma unroll
            for (int l = 0; l < 4; l++) acc[i][j][l] = 0.f;

    // staging indices (all shapes are exact multiples: no bounds checks)
    const int ar0 = tid >> 2;              // 0..63
    const int ac  = (tid & 3) << 2;        // 0,4,8,12
    const float* Ag  = A + (long long)(m0 + ar0) * K + ac;
    const float* Ag2 = Ag + 64LL * K;
    const float* Wg  = W + (long long)(n0 + ar0) * K + ac;

    uint32_t sa = (uint32_t)__cvta_generic_to_shared(&As[0][ar0][ac]);
    uint32_t sw = (uint32_t)__cvta_generic_to_shared(&Ws[0][ar0][ac]);
    const uint32_t A_BUF = 128 * 20 * 4;   // 10240 B
    const uint32_t W_BUF = 64 * 20 * 4;    // 5120 B
    const uint32_t A_HALF = 64 * 20 * 4;   // rows +64

    // prologue: tile 0 -> buf 0
    cp16(sa, Ag);
    cp16(sa + A_HALF, Ag2);
    cp16(sw, Wg);
    asm volatile("cp.async.commit_group;");

    const int KT = K >> 4;
    int buf = 0;

    for (int kt = 0; kt < KT; kt++) {
        asm volatile("cp.async.wait_group 0;");
        __syncthreads();

        if (kt + 1 < KT) {
            const int nb = buf ^ 1;
            const float* a0 = Ag  + (kt + 1) * 16;
            const float* a1 = Ag2 + (kt + 1) * 16;
            const float* w0 = Wg  + (kt + 1) * 16;
            cp16(sa + nb * A_BUF, a0);
            cp16(sa + nb * A_BUF + A_HALF, a1);
            cp16(sw + nb * W_BUF, w0);
            asm volatile("cp.async.commit_group;");
        }

        const float (*Asb)[20] = As[buf];
        const float (*Wsb)[20] = Ws[buf];

#pragma unroll
        for (int ks = 0; ks < 16; ks += 8) {
            uint32_t a[2][4], b[4][2];
#pragma unroll
            for (int mt = 0; mt < 2; mt++) {
                const int r = wm * 32 + mt * 16 + g;
                a[mt][0] = f2tf(Asb[r][ks + t]);
                a[mt][1] = f2tf(Asb[r + 8][ks + t]);
                a[mt][2] = f2tf(Asb[r][ks + t + 4]);
                a[mt][3] = f2tf(Asb[r + 8][ks + t + 4]);
            }
#pragma unroll
            for (int nt = 0; nt < 4; nt++) {
                const int cc = wn * 32 + nt * 8 + g;
                b[nt][0] = f2tf(Wsb[cc][ks + t]);
                b[nt][1] = f2tf(Wsb[cc][ks + t + 4]);
            }
#pragma unroll
            for (int mt = 0; mt < 2; mt++)
#pragma unroll
                for (int nt = 0; nt < 4; nt++)
                    mma_tf32(acc[mt][nt], a[mt], b[nt]);
        }
        buf ^= 1;
    }

    // epilogue
#pragma unroll
    for (int mt = 0; mt < 2; mt++) {
        const int rb = m0 + wm * 32 + mt * 16 + g;
#pragma unroll
        for (int nt = 0; nt < 4; nt++) {
            const int cb = n0 + wn * 32 + nt * 8 + 2 * t;
#pragma unroll
            for (int half = 0; half < 2; half++) {
                const int m = rb + half * 8;
                float v0 = acc[mt][nt][half * 2 + 0];
                float v1 = acc[mt][nt][half * 2 + 1];
                if (bias) { v0 += bias[cb]; v1 += bias[cb + 1]; }
                if (EPI == 1) {
                    v0 = 0.5f * v0 * (1.0f + erff(v0 * 0.70710678118654752f));
                    v1 = 0.5f * v1 * (1.0f + erff(v1 * 0.70710678118654752f));
                }
                v0 *= scale; v1 *= scale;
                if (OUTMODE == 0) {
                    *(float2*)&C[(long long)m * ldC + cb] = make_float2(v0, v1);
                } else if (OUTMODE == 1) {
                    const long long idx = ((long long)(cb >> 6) << 16) + (long long)m * 64 + (cb & 63);
                    *(float2*)&C[idx] = make_float2(v0, v1);
                } else {
                    C[(long long)cb * 1024 + m]       = v0;
                    C[(long long)(cb + 1) * 1024 + m] = v1;
                }
            }
        }
    }
}

// ---------------- rel term: scores[n,s,k] += sum_h q[n,s,h] * relsum[s,k,h] ----------------
__global__ void __launch_bounds__(256) rel_add_kernel(
    const float* __restrict__ rel, const float* __restrict__ qb, float* __restrict__ scores)
{
    const int s  = blockIdx.y;
    const int kt = blockIdx.x << 7;   // *128

    __shared__ __align__(16) float relb[128][76];   // pitch 76 -> conflict-free LDS.128
    __shared__ __align__(16) float qs[12][64];

    const int tid = threadIdx.x;

    for (int i = tid; i < 12 * 64; i += 256)
        qs[i >> 6][i & 63] = qb[((i >> 6) << 16) + (s << 6) + (i & 63)];

    const float4* rp = (const float4*)(rel + (((long long)s << 10) + kt) * 64);
    for (int i = tid; i < 128 * 16; i += 256) {
        float4 t = rp[i];
        *(float4*)&relb[i >> 4][(i & 15) << 2] = t;
    }
    __syncthreads();

    const int hg = tid >> 6;
    const int k0 = tid & 63;

    float acc[3][2];
#pragma unroll
    for (int j = 0; j < 3; j++) { acc[j][0] = 0.f; acc[j][1] = 0.f; }

#pragma unroll
    for (int h4 = 0; h4 < 64; h4 += 4) {
        float4 r0 = *(const float4*)&relb[k0][h4];
        float4 r1 = *(const float4*)&relb[k0 + 64][h4];
#pragma unroll
        for (int j = 0; j < 3; j++) {
            float4 qv = *(const float4*)&qs[hg * 3 + j][h4];
            acc[j][0] += qv.x * r0.x + qv.y * r0.y + qv.z * r0.z + qv.w * r0.w;
            acc[j][1] += qv.x * r1.x + qv.y * r1.y + qv.z * r1.z + qv.w * r1.w;
        }
    }

#pragma unroll
    for (int j = 0; j < 3; j++) {
        const int n = hg * 3 + j;
        const long long base = (((long long)n << 10) + s) * 1024 + kt;
        scores[base + k0]      += acc[j][0];
        scores[base + k0 + 64] += acc[j][1];
    }
}

// ---------------- safe softmax per row ----------------
__global__ void __launch_bounds__(256) softmax_kernel(
    float* __restrict__ scores, const float* __restrict__ mask)
{
    const long long row = blockIdx.x;
    float4* p = (float4*)(scores + row * 1024);
    const int tid = threadIdx.x;
    const int lane = tid & 31, wid = tid >> 5;
    __shared__ float red[8];

    float4 v = p[tid];
    const float4 mk = ((const float4*)mask)[tid];
    v.x += mk.x; v.y += mk.y; v.z += mk.z; v.w += mk.w;

    float m = fmaxf(fmaxf(v.x, v.y), fmaxf(v.z, v.w));
    m = warpRedMax(m);
    if (lane == 0) red[wid] = m;
    __syncthreads();
    float mall = red[0];
#pragma unroll
    for (int i = 1; i < 8; i++) mall = fmaxf(mall, red[i]);
    __syncthreads();

    float e0 = __expf(v.x - mall), e1 = __expf(v.y - mall);
    float e2 = __expf(v.z - mall), e3 = __expf(v.w - mall);
    float ssum = e0 + e1 + e2 + e3;
    ssum = warpRedSum(ssum);
    if (lane == 0) red[wid] = ssum;
    __syncthreads();
    float tot = 0.f;
#pragma unroll
    for (int i = 0; i < 8; i++) tot += red[i];
    const float inv = 1.0f / tot;
    p[tid] = make_float4(e0 * inv, e1 * inv, e2 * inv, e3 * inv);
}

// ---------------- residual + LayerNorm ----------------
__global__ void __launch_bounds__(256) ln_kernel(
    const float* __restrict__ x, const float* __restrict__ res,
    const float* __restrict__ g, const float* __restrict__ b, float* __restrict__ out)
{
    const int s = blockIdx.x;
    const int tid = threadIdx.x;
    const int lane = tid & 31, wid = tid >> 5;
    __shared__ float red[8];

    float v[3];
    float lsum = 0.f;
#pragma unroll
    for (int i = 0; i < 3; i++) {
        const int idx = tid + i * 256;
        v[i] = x[s * 768 + idx] + res[s * 768 + idx];
        lsum += v[i];
    }
    lsum = warpRedSum(lsum);
    if (lane == 0) red[wid] = lsum;
    __syncthreads();
    float tot = 0.f;
#pragma unroll
    for (int i = 0; i < 8; i++) tot += red[i];
    const float mu = tot * (1.0f / 768.0f);
    __syncthreads();

    float ls2 = 0.f;
#pragma unroll
    for (int i = 0; i < 3; i++) { const float d = v[i] - mu; ls2 += d * d; }
    ls2 = warpRedSum(ls2);
    if (lane == 0) red[wid] = ls2;
    __syncthreads();
    float tot2 = 0.f;
#pragma unroll
    for (int i = 0; i < 8; i++) tot2 += red[i];
    const float rs = rsqrtf(tot2 * (1.0f / 768.0f) + 1e-12f);

#pragma unroll
    for (int i = 0; i < 3; i++) {
        const int idx = tid + i * 256;
        out[s * 768 + idx] = (v[i] - mu) * rs * g[idx] + b[idx];
    }
}

// ---------------- launcher ----------------
extern "C" void kernel_launch(void* const* d_in, const int* in_sizes, int n_in,
                              void* d_out, int out_size)
{
    const float* hid  = (const float*)d_in[0];
    const float* mask = (const float*)d_in[1];
    const float* rel  = (const float*)d_in[2];
    const float* rel2 = (const float*)d_in[3];
    const float* rela = (const float*)d_in[4];
    const float* Wq = (const float*)d_in[5];   const float* bq = (const float*)d_in[6];
    const float* Wk = (const float*)d_in[7];   const float* bk = (const float*)d_in[8];
    const float* Wv = (const float*)d_in[9];   const float* bv = (const float*)d_in[10];
    const float* Wo = (const float*)d_in[11];  const float* bo = (const float*)d_in[12];
    const float* g1 = (const float*)d_in[13];  const float* b1 = (const float*)d_in[14];
    const float* Wi = (const float*)d_in[15];  const float* bi = (const float*)d_in[16];
    const float* W2 = (const float*)d_in[17];  const float* b2 = (const float*)d_in[18];
    const float* g2 = (const float*)d_in[19];  const float* b2g = (const float*)d_in[20];

    float *relsum, *q, *k, *vt, *scores, *ctx, *proj, *attn, *inter, *ffn, *hbuf;
    cudaGetSymbolAddress((void**)&relsum, g_relsum);
    cudaGetSymbolAddress((void**)&q, g_q);
    cudaGetSymbolAddress((void**)&k, g_k);
    cudaGetSymbolAddress((void**)&vt, g_vt);
    cudaGetSymbolAddress((void**)&scores, g_scores);
    cudaGetSymbolAddress((void**)&ctx, g_ctx);
    cudaGetSymbolAddress((void**)&proj, g_proj);
    cudaGetSymbolAddress((void**)&attn, g_attn);
    cudaGetSymbolAddress((void**)&inter, g_inter);
    cudaGetSymbolAddress((void**)&ffn, g_ffn);
    cudaGetSymbolAddress((void**)&hbuf, g_h);

    relsum_kernel<<<4096, 256>>>((const float4*)rel, (const float4*)rel2,
                                 (const float4*)rela, (float4*)relsum,
                                 (int)((size_t)SEQ * SEQ * HDIM / 4));

    const float* h = hid;
    for (int l = 0; l < NLAYERS; l++) {
        const size_t wofs  = (size_t)l * 768 * 768;
        const size_t wiofs = (size_t)l * 3072 * 768;

        // Q/K/V projections (tensor core). q pre-scaled by 1/sqrt(64); v written transposed.
        gemm_tc<0, 1><<<dim3(12, 8, 1), 256>>>(h, Wq + wofs, bq + l * 768, q,
                                               768, 0, 0, 0, 0, 0.125f);
        gemm_tc<0, 1><<<dim3(12, 8, 1), 256>>>(h, Wk + wofs, bk + l * 768, k,
                                               768, 0, 0, 0, 0, 1.0f);
        gemm_tc<0, 2><<<dim3(12, 8, 1), 256>>>(h, Wv + wofs, bv + l * 768, vt,
                                               768, 0, 0, 0, 0, 1.0f);

        // scores = q @ k^T (batched per head)
        gemm_tc<0, 0><<<dim3(16, 8, 12), 256>>>(q, k, nullptr, scores,
                                                64, 1024, 65536LL, 65536LL, 1048576LL, 1.0f);

        // scores += q @ relsum[s]^T
        rel_add_kernel<<<dim3(8, 1024), 256>>>(relsum, q, scores);

        // safe softmax (+ mask)
        softmax_kernel<<<12 * 1024, 256>>>(scores, mask);

        // ctx = probs @ v  (probs @ Vt^T, written into (s, head*64+hd) layout)
        gemm_tc<0, 0><<<dim3(1, 8, 12), 256>>>(scores, vt, nullptr, ctx,
                                               1024, 768, 1048576LL, 65536LL, 64LL, 1.0f);

        // output projection + residual LN
        gemm_tc<0, 0><<<dim3(12, 8, 1), 256>>>(ctx, Wo + wofs, bo + l * 768, proj,
                                               768, 768, 0, 0, 0, 1.0f);
        ln_kernel<<<1024, 256>>>(proj, h, g1 + l * 768, b1 + l * 768, attn);

        // FFN
        gemm_tc<1, 0><<<dim3(48, 8, 1), 256>>>(attn, Wi + wiofs, bi + l * 3072, inter,
                                               768, 3072, 0, 0, 0, 1.0f);
        gemm_tc<0, 0><<<dim3(12, 8, 1), 256>>>(inter, W2 + wiofs, b2 + l * 768, ffn,
                                               3072, 768, 0, 0, 0, 1.0f);

        float* outp = (l == NLAYERS - 1) ? (float*)d_out : hbuf;
        ln_kernel<<<1024, 256>>>(ffn, attn, g2 + l * 768, b2g + l * 768, outp);
        h = hbuf;
    }
}

// round 3
// speedup vs baseline: 2.5377x; 1.2794x over previous
#include <cuda_runtime.h>
#include <math.h>
#include <stdint.h>

#define SEQ 1024
#define DM  768
#define NHEAD 12
#define HDIM 64
#define NLAYERS 4
#define DFF 3072
#define STAGES 4

// ---------------- scratch (static device memory; no runtime allocs) ----------------
__device__ float g_relsum[(size_t)SEQ * SEQ * HDIM];          // 256 MB
__device__ float g_q[NHEAD * SEQ * HDIM];
__device__ float g_k[NHEAD * SEQ * HDIM];
__device__ float g_vt[NHEAD * HDIM * SEQ];                    // V transposed per head
__device__ float g_scores[(size_t)NHEAD * SEQ * SEQ];         // 48 MB
__device__ float g_ctx[SEQ * DM];
__device__ float g_proj[SEQ * DM];
__device__ float g_attn[SEQ * DM];
__device__ float g_inter[SEQ * DFF];
__device__ float g_ffn[SEQ * DM];
__device__ float g_h[SEQ * DM];

// ---------------- helpers ----------------
__device__ __forceinline__ float warpRedMax(float v) {
#pragma unroll
    for (int o = 16; o > 0; o >>= 1) v = fmaxf(v, __shfl_xor_sync(0xffffffffu, v, o));
    return v;
}
__device__ __forceinline__ float warpRedSum(float v) {
#pragma unroll
    for (int o = 16; o > 0; o >>= 1) v += __shfl_xor_sync(0xffffffffu, v, o);
    return v;
}
__device__ __forceinline__ uint32_t f2tf(float x) {
    uint32_t r;
    asm("cvt.rna.tf32.f32 %0, %1;" : "=r"(r) : "f"(x));
    return r;
}
__device__ __forceinline__ void cp16(uint32_t dst, const void* src) {
    asm volatile("cp.async.cg.shared.global [%0], [%1], 16;" :: "r"(dst), "l"(src));
}
__device__ __forceinline__ void mma_tf32(float* c, const uint32_t* a, const uint32_t* b) {
    asm volatile(
        "mma.sync.aligned.m16n8k8.row.col.f32.tf32.tf32.f32 "
        "{%0,%1,%2,%3}, {%4,%5,%6,%7}, {%8,%9}, {%0,%1,%2,%3};"
        : "+f"(c[0]), "+f"(c[1]), "+f"(c[2]), "+f"(c[3])
        : "r"(a[0]), "r"(a[1]), "r"(a[2]), "r"(a[3]), "r"(b[0]), "r"(b[1]));
}

// ---------------- relsum = rel_pos + rel_2d_pos + rel_2d_angle ----------------
__global__ void __launch_bounds__(256) relsum_kernel(
    const float4* __restrict__ a, const float4* __restrict__ b,
    const float4* __restrict__ c, float4* __restrict__ out, int n4)
{
    int i = blockIdx.x * blockDim.x + threadIdx.x;
    int stride = gridDim.x * blockDim.x;
    for (; i < n4; i += stride) {
        float4 x = a[i], y = b[i], z = c[i];
        x.x += y.x + z.x; x.y += y.y + z.y; x.z += y.z + z.z; x.w += y.w + z.w;
        out[i] = x;
    }
}

// ---------------- 64x64x32 tf32 GEMM mainloop (128 threads, 4-stage cp.async) ----------------
// C = A @ W^T : A rows at Ag (64 rows x K), W rows at Wg (64 rows x K)
// smem layout: As[STAGES][64][36], Ws[STAGES][64][36]  (floats)
__device__ __forceinline__ void gemm64_mainloop(
    const float* __restrict__ Ag, const float* __restrict__ Wg,
    float* __restrict__ sm, int K, float acc[2][4][4])
{
    const int tid = threadIdx.x;
    const int row = tid >> 3;            // 0..15
    const int cg  = (tid & 7) << 2;      // 0,4,...,28

    float* As = sm;
    float* Ws = sm + STAGES * 2304;

    const uint32_t sa0 = (uint32_t)__cvta_generic_to_shared(As) + (uint32_t)(row * 36 + cg) * 4u;
    const uint32_t sw0 = (uint32_t)__cvta_generic_to_shared(Ws) + (uint32_t)(row * 36 + cg) * 4u;

    const float* Agp = Ag + (long long)row * K + cg;
    const float* Wgp = Wg + (long long)row * K + cg;

    const int KT = K >> 5;

#pragma unroll
    for (int st = 0; st < STAGES - 1; st++) {
        if (st < KT) {
#pragma unroll
            for (int p = 0; p < 4; p++) {
                cp16(sa0 + (uint32_t)(st * 2304 + p * 16 * 36) * 4u, Agp + (long long)(p * 16) * K + st * 32);
                cp16(sw0 + (uint32_t)(st * 2304 + p * 16 * 36) * 4u, Wgp + (long long)(p * 16) * K + st * 32);
            }
        }
        asm volatile("cp.async.commit_group;");
    }

    const int wid = tid >> 5, lane = tid & 31;
    const int wm = wid & 1, wn = wid >> 1;
    const int g = lane >> 2, t = lane & 3;

    for (int kt = 0; kt < KT; kt++) {
        asm volatile("cp.async.wait_group 2;");
        __syncthreads();

        const int pf = kt + STAGES - 1;
        if (pf < KT) {
            const int st = pf & 3;
#pragma unroll
            for (int p = 0; p < 4; p++) {
                cp16(sa0 + (uint32_t)(st * 2304 + p * 16 * 36) * 4u, Agp + (long long)(p * 16) * K + pf * 32);
                cp16(sw0 + (uint32_t)(st * 2304 + p * 16 * 36) * 4u, Wgp + (long long)(p * 16) * K + pf * 32);
            }
        }
        asm volatile("cp.async.commit_group;");

        const float* Asb = As + (kt & 3) * 2304;
        const float* Wsb = Ws + (kt & 3) * 2304;

#pragma unroll
        for (int ks = 0; ks < 32; ks += 8) {
            uint32_t a[2][4], b[4][2];
#pragma unroll
            for (int mt = 0; mt < 2; mt++) {
                const int r = wm * 32 + mt * 16 + g;
                a[mt][0] = f2tf(Asb[r * 36 + ks + t]);
                a[mt][1] = f2tf(Asb[(r + 8) * 36 + ks + t]);
                a[mt][2] = f2tf(Asb[r * 36 + ks + t + 4]);
                a[mt][3] = f2tf(Asb[(r + 8) * 36 + ks + t + 4]);
            }
#pragma unroll
            for (int nt = 0; nt < 4; nt++) {
                const int c = wn * 32 + nt * 8 + g;
                b[nt][0] = f2tf(Wsb[c * 36 + ks + t]);
                b[nt][1] = f2tf(Wsb[c * 36 + ks + t + 4]);
            }
#pragma unroll
            for (int mt = 0; mt < 2; mt++)
#pragma unroll
                for (int nt = 0; nt < 4; nt++)
                    mma_tf32(acc[mt][nt], a[mt], b[nt]);
        }
    }
}

// ---------------- generic GEMM kernel (z-batched), OUTMODE 0: C[m*ldC+n] ----------------
template<int EPI>
__global__ void __launch_bounds__(128) gemm_g(
    const float* __restrict__ A, const float* __restrict__ W,
    const float* __restrict__ bias, float* __restrict__ C,
    int K, int ldC, long long sA, long long sW, long long sC, float scale)
{
    extern __shared__ float sm[];
    const int bz = blockIdx.z;
    const int m0 = blockIdx.y << 6, n0 = blockIdx.x << 6;

    float acc[2][4][4];
#pragma unroll
    for (int i = 0; i < 2; i++)
#pragma unroll
        for (int j = 0; j < 4; j++)
#pragma unroll
            for (int l = 0; l < 4; l++) acc[i][j][l] = 0.f;

    gemm64_mainloop(A + sA * bz + (long long)m0 * K,
                    W + sW * bz + (long long)n0 * K, sm, K, acc);
    C += sC * bz;

    const int tid = threadIdx.x, wid = tid >> 5, lane = tid & 31;
    const int wm = wid & 1, wn = wid >> 1, g = lane >> 2, t = lane & 3;

#pragma unroll
    for (int mt = 0; mt < 2; mt++) {
        const int rb = m0 + wm * 32 + mt * 16 + g;
#pragma unroll
        for (int nt = 0; nt < 4; nt++) {
            const int cb = n0 + wn * 32 + nt * 8 + 2 * t;
#pragma unroll
            for (int hf = 0; hf < 2; hf++) {
                const int m = rb + hf * 8;
                float v0 = acc[mt][nt][hf * 2 + 0];
                float v1 = acc[mt][nt][hf * 2 + 1];
                if (bias) { v0 += bias[cb]; v1 += bias[cb + 1]; }
                if (EPI == 1) {
                    v0 = 0.5f * v0 * (1.0f + erff(v0 * 0.70710678118654752f));
                    v1 = 0.5f * v1 * (1.0f + erff(v1 * 0.70710678118654752f));
                }
                v0 *= scale; v1 *= scale;
                *(float2*)&C[(long long)m * ldC + cb] = make_float2(v0, v1);
            }
        }
    }
}

// ---------------- fused QKV projection kernel ----------------
// z=0: q (scaled 0.125, head layout), z=1: k (head layout), z=2: v (transposed per head)
__global__ void __launch_bounds__(128) qkv_kernel(
    const float* __restrict__ h,
    const float* __restrict__ Wq, const float* __restrict__ Wk, const float* __restrict__ Wv,
    const float* __restrict__ bq, const float* __restrict__ bk, const float* __restrict__ bv,
    float* __restrict__ qo, float* __restrict__ ko, float* __restrict__ vto)
{
    extern __shared__ float sm[];
    const int z = blockIdx.z;
    const float* W    = (z == 0) ? Wq : (z == 1) ? Wk : Wv;
    const float* bias = (z == 0) ? bq : (z == 1) ? bk : bv;
    float* out        = (z == 0) ? qo : (z == 1) ? ko : vto;
    const float scale = (z == 0) ? 0.125f : 1.0f;
    const int m0 = blockIdx.y << 6, n0 = blockIdx.x << 6;

    float acc[2][4][4];
#pragma unroll
    for (int i = 0; i < 2; i++)
#pragma unroll
        for (int j = 0; j < 4; j++)
#pragma unroll
            for (int l = 0; l < 4; l++) acc[i][j][l] = 0.f;

    gemm64_mainloop(h + (long long)m0 * DM, W + (long long)n0 * DM, sm, DM, acc);

    const int tid = threadIdx.x, wid = tid >> 5, lane = tid & 31;
    const int wm = wid & 1, wn = wid >> 1, g = lane >> 2, t = lane & 3;

#pragma unroll
    for (int mt = 0; mt < 2; mt++) {
        const int rb = m0 + wm * 32 + mt * 16 + g;
#pragma unroll
        for (int nt = 0; nt < 4; nt++) {
            const int cb = n0 + wn * 32 + nt * 8 + 2 * t;
#pragma unroll
            for (int hf = 0; hf < 2; hf++) {
                const int m = rb + hf * 8;
                float v0 = (acc[mt][nt][hf * 2 + 0] + bias[cb]) * scale;
                float v1 = (acc[mt][nt][hf * 2 + 1] + bias[cb + 1]) * scale;
                if (z < 2) {
                    const long long idx = ((long long)(cb >> 6) << 16) + (long long)m * 64 + (cb & 63);
                    *(float2*)&out[idx] = make_float2(v0, v1);
                } else {
                    out[(long long)cb * 1024 + m]       = v0;
                    out[(long long)(cb + 1) * 1024 + m] = v1;
                }
            }
        }
    }
}

// ---------------- fused rel-score + mask + softmax kernel ----------------
// One block per s. Computes scores[n,s,:] += q[n,s,:] @ relsum[s,:,:]^T via tensor cores,
// then safe softmax (+mask) in place.
#define ACC_PITCH 1032
#define REL_STRIDE 8704   // 128*68 floats per staging buffer

__global__ void __launch_bounds__(256) rel_softmax_kernel(
    const float* __restrict__ rel, const float* __restrict__ qb,
    float* __restrict__ scores, const float* __restrict__ mask)
{
    extern __shared__ float sm[];
    float* qsA   = sm;                       // [16][68] = 1088
    float* accsc = sm + 1088;                // [12][ACC_PITCH] = 12384
    float* relb  = sm + 1088 + 12384;        // [2][128][68] = 17408
    float* redA  = relb + 2 * REL_STRIDE;    // [8]
    float* redB  = redA + 8;                 // [8]

    const int s = blockIdx.x;
    const int tid = threadIdx.x;
    const int wid = tid >> 5, lane = tid & 31;
    const int g = lane >> 2, t = lane & 3;

    // load q for this s into padded 16x64 tile (rows 12..15 zero)
    for (int i = tid; i < 16 * 64; i += 256) {
        const int r = i >> 6, c = i & 63;
        qsA[r * 68 + c] = (r < 12) ? qb[((long long)r << 16) + (s << 6) + c] : 0.f;
    }
    __syncthreads();

    // hoist q fragments into registers (K=64 -> 8 k-steps)
    uint32_t afrag[8][4];
#pragma unroll
    for (int ks8 = 0; ks8 < 8; ks8++) {
        afrag[ks8][0] = f2tf(qsA[g * 68 + ks8 * 8 + t]);
        afrag[ks8][1] = f2tf(qsA[(g + 8) * 68 + ks8 * 8 + t]);
        afrag[ks8][2] = f2tf(qsA[g * 68 + ks8 * 8 + t + 4]);
        afrag[ks8][3] = f2tf(qsA[(g + 8) * 68 + ks8 * 8 + t + 4]);
    }

    // cp.async staging setup: chunk = 128 rel rows x 64 floats = 2048 float4, 8 per thread
    const float* relS = rel + ((long long)s << 16);
    const uint32_t relb_s = (uint32_t)__cvta_generic_to_shared(relb);

    // prologue: chunk 0 -> buf 0
    {
#pragma unroll
        for (int p = 0; p < 8; p++) {
            const int idx = tid + 256 * p;
            const int r = idx >> 4, c4 = (idx & 15) << 2;
            cp16(relb_s + (uint32_t)(r * 68 + c4) * 4u, relS + (long long)r * 64 + c4);
        }
        asm volatile("cp.async.commit_group;");
    }

    for (int ch = 0; ch < 8; ch++) {
        asm volatile("cp.async.wait_group 0;");
        __syncthreads();

        if (ch + 1 < 8) {
            const uint32_t dstb = relb_s + (uint32_t)(((ch + 1) & 1) * REL_STRIDE) * 4u;
            const float* src = relS + (long long)(ch + 1) * 128 * 64;
#pragma unroll
            for (int p = 0; p < 8; p++) {
                const int idx = tid + 256 * p;
                const int r = idx >> 4, c4 = (idx & 15) << 2;
                cp16(dstb + (uint32_t)(r * 68 + c4) * 4u, src + (long long)r * 64 + c4);
            }
        }
        asm volatile("cp.async.commit_group;");

        const float* rb = relb + (ch & 1) * REL_STRIDE;
#pragma unroll
        for (int nt2 = 0; nt2 < 2; nt2++) {
            const int lrb = (wid * 2 + nt2) * 8;       // local k-col tile base
            const int lr = lrb + g;
            float c[4] = {0.f, 0.f, 0.f, 0.f};
#pragma unroll
            for (int ks8 = 0; ks8 < 8; ks8++) {
                uint32_t bb[2];
                bb[0] = f2tf(rb[lr * 68 + ks8 * 8 + t]);
                bb[1] = f2tf(rb[lr * 68 + ks8 * 8 + t + 4]);
                mma_tf32(c, afrag[ks8], bb);
            }
            const int kc = ch * 128 + lrb + 2 * t;
            *(float2*)&accsc[g * ACC_PITCH + kc] = make_float2(c[0], c[1]);
            if (g < 4)
                *(float2*)&accsc[(g + 8) * ACC_PITCH + kc] = make_float2(c[2], c[3]);
        }
    }
    __syncthreads();

    // mask + safe softmax per head, in place on scores
    const float4 mk = ((const float4*)mask)[tid];
    for (int n = 0; n < 12; n++) {
        float* srow = scores + (((long long)n << 10) + s) * 1024;
        float4 v = *(const float4*)&srow[tid * 4];
        const float4 ac = *(const float4*)&accsc[n * ACC_PITCH + tid * 4];
        v.x += ac.x + mk.x; v.y += ac.y + mk.y; v.z += ac.z + mk.z; v.w += ac.w + mk.w;

        float m = fmaxf(fmaxf(v.x, v.y), fmaxf(v.z, v.w));
        m = warpRedMax(m);
        if (lane == 0) redA[wid] = m;
        __syncthreads();
        float mall = redA[0];
#pragma unroll
        for (int i = 1; i < 8; i++) mall = fmaxf(mall, redA[i]);

        float e0 = __expf(v.x - mall), e1 = __expf(v.y - mall);
        float e2 = __expf(v.z - mall), e3 = __expf(v.w - mall);
        float ssum = warpRedSum(e0 + e1 + e2 + e3);
        if (lane == 0) redB[wid] = ssum;
        __syncthreads();
        float tot = 0.f;
#pragma unroll
        for (int i = 0; i < 8; i++) tot += redB[i];
        const float inv = 1.0f / tot;
        *(float4*)&srow[tid * 4] = make_float4(e0 * inv, e1 * inv, e2 * inv, e3 * inv);
    }
}

// ---------------- residual + LayerNorm ----------------
__global__ void __launch_bounds__(256) ln_kernel(
    const float* __restrict__ x, const float* __restrict__ res,
    const float* __restrict__ g, const float* __restrict__ b, float* __restrict__ out)
{
    const int s = blockIdx.x;
    const int tid = threadIdx.x;
    const int lane = tid & 31, wid = tid >> 5;
    __shared__ float red[8];

    float v[3];
    float lsum = 0.f;
#pragma unroll
    for (int i = 0; i < 3; i++) {
        const int idx = tid + i * 256;
        v[i] = x[s * 768 + idx] + res[s * 768 + idx];
        lsum += v[i];
    }
    lsum = warpRedSum(lsum);
    if (lane == 0) red[wid] = lsum;
    __syncthreads();
    float tot = 0.f;
#pragma unroll
    for (int i = 0; i < 8; i++) tot += red[i];
    const float mu = tot * (1.0f / 768.0f);
    __syncthreads();

    float ls2 = 0.f;
#pragma unroll
    for (int i = 0; i < 3; i++) { const float d = v[i] - mu; ls2 += d * d; }
    ls2 = warpRedSum(ls2);
    if (lane == 0) red[wid] = ls2;
    __syncthreads();
    float tot2 = 0.f;
#pragma unroll
    for (int i = 0; i < 8; i++) tot2 += red[i];
    const float rs = rsqrtf(tot2 * (1.0f / 768.0f) + 1e-12f);

#pragma unroll
    for (int i = 0; i < 3; i++) {
        const int idx = tid + i * 256;
        out[s * 768 + idx] = (v[i] - mu) * rs * g[idx] + b[idx];
    }
}

// ---------------- launcher ----------------
#define GEMM_SMEM  (STAGES * 2304 * 2 * 4)            // 73728 B
#define RS_SMEM    ((1088 + 12384 + 2 * 8704 + 16) * 4) // 123648 B

extern "C" void kernel_launch(void* const* d_in, const int* in_sizes, int n_in,
                              void* d_out, int out_size)
{
    const float* hid  = (const float*)d_in[0];
    const float* mask = (const float*)d_in[1];
    const float* rel  = (const float*)d_in[2];
    const float* rel2 = (const float*)d_in[3];
    const float* rela = (const float*)d_in[4];
    const float* Wq = (const float*)d_in[5];   const float* bq = (const float*)d_in[6];
    const float* Wk = (const float*)d_in[7];   const float* bk = (const float*)d_in[8];
    const float* Wv = (const float*)d_in[9];   const float* bv = (const float*)d_in[10];
    const float* Wo = (const float*)d_in[11];  const float* bo = (const float*)d_in[12];
    const float* g1 = (const float*)d_in[13];  const float* b1 = (const float*)d_in[14];
    const float* Wi = (const float*)d_in[15];  const float* bi = (const float*)d_in[16];
    const float* W2 = (const float*)d_in[17];  const float* b2 = (const float*)d_in[18];
    const float* g2 = (const float*)d_in[19];  const float* b2g = (const float*)d_in[20];

    float *relsum, *q, *k, *vt, *scores, *ctx, *proj, *attn, *inter, *ffn, *hbuf;
    cudaGetSymbolAddress((void**)&relsum, g_relsum);
    cudaGetSymbolAddress((void**)&q, g_q);
    cudaGetSymbolAddress((void**)&k, g_k);
    cudaGetSymbolAddress((void**)&vt, g_vt);
    cudaGetSymbolAddress((void**)&scores, g_scores);
    cudaGetSymbolAddress((void**)&ctx, g_ctx);
    cudaGetSymbolAddress((void**)&proj, g_proj);
    cudaGetSymbolAddress((void**)&attn, g_attn);
    cudaGetSymbolAddress((void**)&inter, g_inter);
    cudaGetSymbolAddress((void**)&ffn, g_ffn);
    cudaGetSymbolAddress((void**)&hbuf, g_h);

    cudaFuncSetAttribute(gemm_g<0>, cudaFuncAttributeMaxDynamicSharedMemorySize, GEMM_SMEM);
    cudaFuncSetAttribute(gemm_g<1>, cudaFuncAttributeMaxDynamicSharedMemorySize, GEMM_SMEM);
    cudaFuncSetAttribute(qkv_kernel, cudaFuncAttributeMaxDynamicSharedMemorySize, GEMM_SMEM);
    cudaFuncSetAttribute(rel_softmax_kernel, cudaFuncAttributeMaxDynamicSharedMemorySize, RS_SMEM);

    relsum_kernel<<<4096, 256>>>((const float4*)rel, (const float4*)rel2,
                                 (const float4*)rela, (float4*)relsum,
                                 (int)((size_t)SEQ * SEQ * HDIM / 4));

    const float* h = hid;
    for (int l = 0; l < NLAYERS; l++) {
        const size_t wofs  = (size_t)l * 768 * 768;
        const size_t wiofs = (size_t)l * 3072 * 768;

        // fused Q/K/V projections
        qkv_kernel<<<dim3(12, 16, 3), 128, GEMM_SMEM>>>(
            h, Wq + wofs, Wk + wofs, Wv + wofs,
            bq + l * 768, bk + l * 768, bv + l * 768, q, k, vt);

        // scores = q @ k^T (batched per head)
        gemm_g<0><<<dim3(16, 16, 12), 128, GEMM_SMEM>>>(
            q, k, nullptr, scores, 64, 1024, 65536LL, 65536LL, 1048576LL, 1.0f);

        // scores += q @ relsum^T; + mask; softmax  (fused)
        rel_softmax_kernel<<<1024, 256, RS_SMEM>>>(relsum, q, scores, mask);

        // ctx = probs @ v
        gemm_g<0><<<dim3(1, 16, 12), 128, GEMM_SMEM>>>(
            scores, vt, nullptr, ctx, 1024, 768, 1048576LL, 65536LL, 64LL, 1.0f);

        // output projection + residual LN
        gemm_g<0><<<dim3(12, 16, 1), 128, GEMM_SMEM>>>(
            ctx, Wo + wofs, bo + l * 768, proj, 768, 768, 0, 0, 0, 1.0f);
        ln_kernel<<<1024, 256>>>(proj, h, g1 + l * 768, b1 + l * 768, attn);

        // FFN
        gemm_g<1><<<dim3(48, 16, 1), 128, GEMM_SMEM>>>(
            attn, Wi + wiofs, bi + l * 3072, inter, 768, 3072, 0, 0, 0, 1.0f);
        gemm_g<0><<<dim3(12, 16, 1), 128, GEMM_SMEM>>>(
            inter, W2 + wiofs, b2 + l * 768, ffn, 3072, 768, 0, 0, 0, 1.0f);

        float* outp = (l == NLAYERS - 1) ? (float*)d_out : hbuf;
        ln_kernel<<<1024, 256>>>(ffn, attn, g2 + l * 768, b2g + l * 768, outp);
        h = hbuf;
    }
}

// round 4
// speedup vs baseline: 2.8455x; 1.1213x over previous
#include <cuda_runtime.h>
#include <cuda_fp16.h>
#include <math.h>
#include <stdint.h>

#define SEQ 1024
#define DM  768
#define NHEAD 12
#define HDIM 64
#define NLAYERS 4
#define DFF 3072
#define STAGES 4

// ---------------- scratch (static device memory; no runtime allocs) ----------------
__device__ __half g_relsum[(size_t)SEQ * SEQ * HDIM];         // 128 MB (fp16)
__device__ float g_q[NHEAD * SEQ * HDIM];
__device__ float g_k[NHEAD * SEQ * HDIM];
__device__ float g_vt[NHEAD * HDIM * SEQ];                    // V transposed per head
__device__ float g_scores[(size_t)NHEAD * SEQ * SEQ];         // 48 MB
__device__ float g_ctx[SEQ * DM];
__device__ float g_proj[SEQ * DM];
__device__ float g_attn[SEQ * DM];
__device__ float g_inter[SEQ * DFF];
__device__ float g_ffn[SEQ * DM];
__device__ float g_h[SEQ * DM];

// ---------------- helpers ----------------
__device__ __forceinline__ float warpRedMax(float v) {
#pragma unroll
    for (int o = 16; o > 0; o >>= 1) v = fmaxf(v, __shfl_xor_sync(0xffffffffu, v, o));
    return v;
}
__device__ __forceinline__ float warpRedSum(float v) {
#pragma unroll
    for (int o = 16; o > 0; o >>= 1) v += __shfl_xor_sync(0xffffffffu, v, o);
    return v;
}
__device__ __forceinline__ uint32_t f2tf(float x) {
    uint32_t r;
    asm("cvt.rna.tf32.f32 %0, %1;" : "=r"(r) : "f"(x));
    return r;
}
__device__ __forceinline__ void cp16(uint32_t dst, const void* src) {
    asm volatile("cp.async.cg.shared.global [%0], [%1], 16;" :: "r"(dst), "l"(src));
}
__device__ __forceinline__ void mma_tf32(float* c, const uint32_t* a, const uint32_t* b) {
    asm volatile(
        "mma.sync.aligned.m16n8k8.row.col.f32.tf32.tf32.f32 "
        "{%0,%1,%2,%3}, {%4,%5,%6,%7}, {%8,%9}, {%0,%1,%2,%3};"
        : "+f"(c[0]), "+f"(c[1]), "+f"(c[2]), "+f"(c[3])
        : "r"(a[0]), "r"(a[1]), "r"(a[2]), "r"(a[3]), "r"(b[0]), "r"(b[1]));
}
__device__ __forceinline__ void mma_f16(float* c, const uint32_t* a, const uint32_t* b) {
    asm volatile(
        "mma.sync.aligned.m16n8k16.row.col.f32.f16.f16.f32 "
        "{%0,%1,%2,%3}, {%4,%5,%6,%7}, {%8,%9}, {%0,%1,%2,%3};"
        : "+f"(c[0]), "+f"(c[1]), "+f"(c[2]), "+f"(c[3])
        : "r"(a[0]), "r"(a[1]), "r"(a[2]), "r"(a[3]), "r"(b[0]), "r"(b[1]));
}

// ---------------- relsum = rel_pos + rel_2d_pos + rel_2d_angle (fp16 out) ----------------
__global__ void __launch_bounds__(256) relsum_kernel(
    const float4* __restrict__ a, const float4* __restrict__ b,
    const float4* __restrict__ c, uint2* __restrict__ out, int n4)
{
    int i = blockIdx.x * blockDim.x + threadIdx.x;
    int stride = gridDim.x * blockDim.x;
    for (; i < n4; i += stride) {
        float4 x = a[i], y = b[i], z = c[i];
        x.x += y.x + z.x; x.y += y.y + z.y; x.z += y.z + z.z; x.w += y.w + z.w;
        __half2 h0 = __floats2half2_rn(x.x, x.y);
        __half2 h1 = __floats2half2_rn(x.z, x.w);
        uint2 o;
        o.x = *(uint32_t*)&h0;
        o.y = *(uint32_t*)&h1;
        out[i] = o;
    }
}

// ---------------- 64x64x32 tf32 GEMM mainloop (128 threads, 4-stage cp.async) ----------------
__device__ __forceinline__ void gemm64_mainloop(
    const float* __restrict__ Ag, const float* __restrict__ Wg,
    float* __restrict__ sm, int K, float acc[2][4][4])
{
    const int tid = threadIdx.x;
    const int row = tid >> 3;            // 0..15
    const int cg  = (tid & 7) << 2;      // 0,4,...,28

    float* As = sm;
    float* Ws = sm + STAGES * 2304;

    const uint32_t sa0 = (uint32_t)__cvta_generic_to_shared(As) + (uint32_t)(row * 36 + cg) * 4u;
    const uint32_t sw0 = (uint32_t)__cvta_generic_to_shared(Ws) + (uint32_t)(row * 36 + cg) * 4u;

    const float* Agp = Ag + (long long)row * K + cg;
    const float* Wgp = Wg + (long long)row * K + cg;

    const int KT = K >> 5;

#pragma unroll
    for (int st = 0; st < STAGES - 1; st++) {
        if (st < KT) {
#pragma unroll
            for (int p = 0; p < 4; p++) {
                cp16(sa0 + (uint32_t)(st * 2304 + p * 16 * 36) * 4u, Agp + (long long)(p * 16) * K + st * 32);
                cp16(sw0 + (uint32_t)(st * 2304 + p * 16 * 36) * 4u, Wgp + (long long)(p * 16) * K + st * 32);
            }
        }
        asm volatile("cp.async.commit_group;");
    }

    const int wid = tid >> 5, lane = tid & 31;
    const int wm = wid & 1, wn = wid >> 1;
    const int g = lane >> 2, t = lane & 3;

    for (int kt = 0; kt < KT; kt++) {
        asm volatile("cp.async.wait_group 2;");
        __syncthreads();

        const int pf = kt + STAGES - 1;
        if (pf < KT) {
            const int st = pf & 3;
#pragma unroll
            for (int p = 0; p < 4; p++) {
                cp16(sa0 + (uint32_t)(st * 2304 + p * 16 * 36) * 4u, Agp + (long long)(p * 16) * K + pf * 32);
                cp16(sw0 + (uint32_t)(st * 2304 + p * 16 * 36) * 4u, Wgp + (long long)(p * 16) * K + pf * 32);
            }
        }
        asm volatile("cp.async.commit_group;");

        const float* Asb = As + (kt & 3) * 2304;
        const float* Wsb = Ws + (kt & 3) * 2304;

#pragma unroll
        for (int ks = 0; ks < 32; ks += 8) {
            uint32_t a[2][4], b[4][2];
#pragma unroll
            for (int mt = 0; mt < 2; mt++) {
                const int r = wm * 32 + mt * 16 + g;
                a[mt][0] = f2tf(Asb[r * 36 + ks + t]);
                a[mt][1] = f2tf(Asb[(r + 8) * 36 + ks + t]);
                a[mt][2] = f2tf(Asb[r * 36 + ks + t + 4]);
                a[mt][3] = f2tf(Asb[(r + 8) * 36 + ks + t + 4]);
            }
#pragma unroll
            for (int nt = 0; nt < 4; nt++) {
                const int c = wn * 32 + nt * 8 + g;
                b[nt][0] = f2tf(Wsb[c * 36 + ks + t]);
                b[nt][1] = f2tf(Wsb[c * 36 + ks + t + 4]);
            }
#pragma unroll
            for (int mt = 0; mt < 2; mt++)
#pragma unroll
                for (int nt = 0; nt < 4; nt++)
                    mma_tf32(acc[mt][nt], a[mt], b[nt]);
        }
    }
}

// ---------------- generic GEMM kernel (z-batched) ----------------
template<int EPI>
__global__ void __launch_bounds__(128) gemm_g(
    const float* __restrict__ A, const float* __restrict__ W,
    const float* __restrict__ bias, float* __restrict__ C,
    int K, int ldC, long long sA, long long sW, long long sC, float scale)
{
    extern __shared__ float sm[];
    const int bz = blockIdx.z;
    const int m0 = blockIdx.y << 6, n0 = blockIdx.x << 6;

    float acc[2][4][4];
#pragma unroll
    for (int i = 0; i < 2; i++)
#pragma unroll
        for (int j = 0; j < 4; j++)
#pragma unroll
            for (int l = 0; l < 4; l++) acc[i][j][l] = 0.f;

    gemm64_mainloop(A + sA * bz + (long long)m0 * K,
                    W + sW * bz + (long long)n0 * K, sm, K, acc);
    C += sC * bz;

    const int tid = threadIdx.x, wid = tid >> 5, lane = tid & 31;
    const int wm = wid & 1, wn = wid >> 1, g = lane >> 2, t = lane & 3;

#pragma unroll
    for (int mt = 0; mt < 2; mt++) {
        const int rb = m0 + wm * 32 + mt * 16 + g;
#pragma unroll
        for (int nt = 0; nt < 4; nt++) {
            const int cb = n0 + wn * 32 + nt * 8 + 2 * t;
#pragma unroll
            for (int hf = 0; hf < 2; hf++) {
                const int m = rb + hf * 8;
                float v0 = acc[mt][nt][hf * 2 + 0];
                float v1 = acc[mt][nt][hf * 2 + 1];
                if (bias) { v0 += bias[cb]; v1 += bias[cb + 1]; }
                if (EPI == 1) {
                    v0 = 0.5f * v0 * (1.0f + erff(v0 * 0.70710678118654752f));
                    v1 = 0.5f * v1 * (1.0f + erff(v1 * 0.70710678118654752f));
                }
                v0 *= scale; v1 *= scale;
                *(float2*)&C[(long long)m * ldC + cb] = make_float2(v0, v1);
            }
        }
    }
}

// ---------------- fused QKV projection kernel ----------------
__global__ void __launch_bounds__(128) qkv_kernel(
    const float* __restrict__ h,
    const float* __restrict__ Wq, const float* __restrict__ Wk, const float* __restrict__ Wv,
    const float* __restrict__ bq, const float* __restrict__ bk, const float* __restrict__ bv,
    float* __restrict__ qo, float* __restrict__ ko, float* __restrict__ vto)
{
    extern __shared__ float sm[];
    const int z = blockIdx.z;
    const float* W    = (z == 0) ? Wq : (z == 1) ? Wk : Wv;
    const float* bias = (z == 0) ? bq : (z == 1) ? bk : bv;
    float* out        = (z == 0) ? qo : (z == 1) ? ko : vto;
    const float scale = (z == 0) ? 0.125f : 1.0f;
    const int m0 = blockIdx.y << 6, n0 = blockIdx.x << 6;

    float acc[2][4][4];
#pragma unroll
    for (int i = 0; i < 2; i++)
#pragma unroll
        for (int j = 0; j < 4; j++)
#pragma unroll
            for (int l = 0; l < 4; l++) acc[i][j][l] = 0.f;

    gemm64_mainloop(h + (long long)m0 * DM, W + (long long)n0 * DM, sm, DM, acc);

    const int tid = threadIdx.x, wid = tid >> 5, lane = tid & 31;
    const int wm = wid & 1, wn = wid >> 1, g = lane >> 2, t = lane & 3;

#pragma unroll
    for (int mt = 0; mt < 2; mt++) {
        const int rb = m0 + wm * 32 + mt * 16 + g;
#pragma unroll
        for (int nt = 0; nt < 4; nt++) {
            const int cb = n0 + wn * 32 + nt * 8 + 2 * t;
#pragma unroll
            for (int hf = 0; hf < 2; hf++) {
                const int m = rb + hf * 8;
                float v0 = (acc[mt][nt][hf * 2 + 0] + bias[cb]) * scale;
                float v1 = (acc[mt][nt][hf * 2 + 1] + bias[cb + 1]) * scale;
                if (z < 2) {
                    const long long idx = ((long long)(cb >> 6) << 16) + (long long)m * 64 + (cb & 63);
                    *(float2*)&out[idx] = make_float2(v0, v1);
                } else {
                    out[(long long)cb * 1024 + m]       = v0;
                    out[(long long)(cb + 1) * 1024 + m] = v1;
                }
            }
        }
    }
}

// ---------------- fused rel-score + mask + softmax kernel (fp16 rel, 4-deep pipeline) ----------------
// One block per s. scores[n,s,:] += q[n,s,:] @ relsum[s,:,:]^T ; then mask + safe softmax.
#define ACC_PITCH 1032
#define RS_QPITCH 72
#define RS_RPITCH 72                 // halves per relb row
#define RS_CHUNK_H (128 * RS_RPITCH) // halves per staging buffer (9216)
#define RS_NBUF 4

// smem layout (bytes):
//   accsc fp32 [12][ACC_PITCH]           = 49536
//   qs    fp16 [16][RS_QPITCH]           = 2304
//   relb  fp16 [RS_NBUF][128][RS_RPITCH] = 73728
//   red   fp32 [16]                      = 64
#define RS_SMEM (49536 + 2304 + 73728 + 64)

__global__ void __launch_bounds__(256) rel_softmax_kernel(
    const __half* __restrict__ rel, const float* __restrict__ qb,
    float* __restrict__ scores, const float* __restrict__ mask)
{
    extern __shared__ char smc[];
    float*  accsc = (float*)smc;
    __half* qs    = (__half*)(smc + 49536);
    __half* relb  = (__half*)(smc + 49536 + 2304);
    float*  redA  = (float*)(smc + 49536 + 2304 + 73728);
    float*  redB  = redA + 8;

    const int s = blockIdx.x;
    const int tid = threadIdx.x;
    const int wid = tid >> 5, lane = tid & 31;
    const int g = lane >> 2, t = lane & 3;

    // load q for this s into padded fp16 16x64 tile (rows 12..15 zero)
    for (int i = tid; i < 16 * 64; i += 256) {
        const int r = i >> 6, c = i & 63;
        qs[r * RS_QPITCH + c] = __float2half((r < 12) ? qb[((long long)r << 16) + (s << 6) + c] : 0.f);
    }
    __syncthreads();

    // hoist q fragments: K=64 -> 4 k16-steps
    uint32_t afrag[4][4];
#pragma unroll
    for (int ks = 0; ks < 4; ks++) {
        afrag[ks][0] = *(const uint32_t*)&qs[g * RS_QPITCH + ks * 16 + 2 * t];
        afrag[ks][1] = *(const uint32_t*)&qs[(g + 8) * RS_QPITCH + ks * 16 + 2 * t];
        afrag[ks][2] = *(const uint32_t*)&qs[g * RS_QPITCH + ks * 16 + 2 * t + 8];
        afrag[ks][3] = *(const uint32_t*)&qs[(g + 8) * RS_QPITCH + ks * 16 + 2 * t + 8];
    }

    const __half* relS = rel + ((long long)s << 16);
    const uint32_t relb_s = (uint32_t)__cvta_generic_to_shared(relb);

    // each chunk: 128 rel rows x 64 halves = 1024 x 16B; 4 cp16 per thread
    // prologue: chunks 0..2 -> bufs 0..2
#pragma unroll
    for (int ch = 0; ch < RS_NBUF - 1; ch++) {
        const uint32_t dstb = relb_s + (uint32_t)(ch * RS_CHUNK_H) * 2u;
        const __half* src = relS + (long long)ch * 128 * 64;
#pragma unroll
        for (int p = 0; p < 4; p++) {
            const int idx = tid + 256 * p;
            const int r = idx >> 3, c8 = (idx & 7) << 3;
            cp16(dstb + (uint32_t)(r * RS_RPITCH + c8) * 2u, src + (long long)r * 64 + c8);
        }
        asm volatile("cp.async.commit_group;");
    }

    for (int ch = 0; ch < 8; ch++) {
        asm volatile("cp.async.wait_group %0;" :: "n"(RS_NBUF - 2));
        __syncthreads();

        const int pf = ch + RS_NBUF - 1;
        if (pf < 8) {
            const uint32_t dstb = relb_s + (uint32_t)((pf & (RS_NBUF - 1)) * RS_CHUNK_H) * 2u;
            const __half* src = relS + (long long)pf * 128 * 64;
#pragma unroll
            for (int p = 0; p < 4; p++) {
                const int idx = tid + 256 * p;
                const int r = idx >> 3, c8 = (idx & 7) << 3;
                cp16(dstb + (uint32_t)(r * RS_RPITCH + c8) * 2u, src + (long long)r * 64 + c8);
            }
        }
        asm volatile("cp.async.commit_group;");

        const __half* rb = relb + (ch & (RS_NBUF - 1)) * RS_CHUNK_H;
#pragma unroll
        for (int nt2 = 0; nt2 < 2; nt2++) {
            const int lrb = (wid * 2 + nt2) * 8;       // local k-col tile base (0..120)
            const int lr = lrb + g;
            float c[4] = {0.f, 0.f, 0.f, 0.f};
#pragma unroll
            for (int ks = 0; ks < 4; ks++) {
                uint32_t bb[2];
                bb[0] = *(const uint32_t*)&rb[lr * RS_RPITCH + ks * 16 + 2 * t];
                bb[1] = *(const uint32_t*)&rb[lr * RS_RPITCH + ks * 16 + 2 * t + 8];
                mma_f16(c, afrag[ks], bb);
            }
            const int kc = ch * 128 + lrb + 2 * t;
            *(float2*)&accsc[g * ACC_PITCH + kc] = make_float2(c[0], c[1]);
            if (g < 4)
                *(float2*)&accsc[(g + 8) * ACC_PITCH + kc] = make_float2(c[2], c[3]);
        }
    }
    __syncthreads();

    // mask + safe softmax per head, in place on scores
    const float4 mk = ((const float4*)mask)[tid];
    for (int n = 0; n < 12; n++) {
        float* srow = scores + (((long long)n << 10) + s) * 1024;
        float4 v = *(const float4*)&srow[tid * 4];
        const float4 ac = *(const float4*)&accsc[n * ACC_PITCH + tid * 4];
        v.x += ac.x + mk.x; v.y += ac.y + mk.y; v.z += ac.z + mk.z; v.w += ac.w + mk.w;

        float m = fmaxf(fmaxf(v.x, v.y), fmaxf(v.z, v.w));
        m = warpRedMax(m);
        if (lane == 0) redA[wid] = m;
        __syncthreads();
        float mall = redA[0];
#pragma unroll
        for (int i = 1; i < 8; i++) mall = fmaxf(mall, redA[i]);

        float e0 = __expf(v.x - mall), e1 = __expf(v.y - mall);
        float e2 = __expf(v.z - mall), e3 = __expf(v.w - mall);
        float ssum = warpRedSum(e0 + e1 + e2 + e3);
        if (lane == 0) redB[wid] = ssum;
        __syncthreads();
        float tot = 0.f;
#pragma unroll
        for (int i = 0; i < 8; i++) tot += redB[i];
        const float inv = 1.0f / tot;
        *(float4*)&srow[tid * 4] = make_float4(e0 * inv, e1 * inv, e2 * inv, e3 * inv);
    }
}

// ---------------- residual + LayerNorm ----------------
__global__ void __launch_bounds__(256) ln_kernel(
    const float* __restrict__ x, const float* __restrict__ res,
    const float* __restrict__ g, const float* __restrict__ b, float* __restrict__ out)
{
    const int s = blockIdx.x;
    const int tid = threadIdx.x;
    const int lane = tid & 31, wid = tid >> 5;
    __shared__ float red[8];

    float v[3];
    float lsum = 0.f;
#pragma unroll
    for (int i = 0; i < 3; i++) {
        const int idx = tid + i * 256;
        v[i] = x[s * 768 + idx] + res[s * 768 + idx];
        lsum += v[i];
    }
    lsum = warpRedSum(lsum);
    if (lane == 0) red[wid] = lsum;
    __syncthreads();
    float tot = 0.f;
#pragma unroll
    for (int i = 0; i < 8; i++) tot += red[i];
    const float mu = tot * (1.0f / 768.0f);
    __syncthreads();

    float ls2 = 0.f;
#pragma unroll
    for (int i = 0; i < 3; i++) { const float d = v[i] - mu; ls2 += d * d; }
    ls2 = warpRedSum(ls2);
    if (lane == 0) red[wid] = ls2;
    __syncthreads();
    float tot2 = 0.f;
#pragma unroll
    for (int i = 0; i < 8; i++) tot2 += red[i];
    const float rs = rsqrtf(tot2 * (1.0f / 768.0f) + 1e-12f);

#pragma unroll
    for (int i = 0; i < 3; i++) {
        const int idx = tid + i * 256;
        out[s * 768 + idx] = (v[i] - mu) * rs * g[idx] + b[idx];
    }
}

// ---------------- launcher ----------------
#define GEMM_SMEM  (STAGES * 2304 * 2 * 4)            // 73728 B

extern "C" void kernel_launch(void* const* d_in, const int* in_sizes, int n_in,
                              void* d_out, int out_size)
{
    const float* hid  = (const float*)d_in[0];
    const float* mask = (const float*)d_in[1];
    const float* rel  = (const float*)d_in[2];
    const float* rel2 = (const float*)d_in[3];
    const float* rela = (const float*)d_in[4];
    const float* Wq = (const float*)d_in[5];   const float* bq = (const float*)d_in[6];
    const float* Wk = (const float*)d_in[7];   const float* bk = (const float*)d_in[8];
    const float* Wv = (const float*)d_in[9];   const float* bv = (const float*)d_in[10];
    const float* Wo = (const float*)d_in[11];  const float* bo = (const float*)d_in[12];
    const float* g1 = (const float*)d_in[13];  const float* b1 = (const float*)d_in[14];
    const float* Wi = (const float*)d_in[15];  const float* bi = (const float*)d_in[16];
    const float* W2 = (const float*)d_in[17];  const float* b2 = (const float*)d_in[18];
    const float* g2 = (const float*)d_in[19];  const float* b2g = (const float*)d_in[20];

    __half* relsum;
    float *q, *k, *vt, *scores, *ctx, *proj, *attn, *inter, *ffn, *hbuf;
    cudaGetSymbolAddress((void**)&relsum, g_relsum);
    cudaGetSymbolAddress((void**)&q, g_q);
    cudaGetSymbolAddress((void**)&k, g_k);
    cudaGetSymbolAddress((void**)&vt, g_vt);
    cudaGetSymbolAddress((void**)&scores, g_scores);
    cudaGetSymbolAddress((void**)&ctx, g_ctx);
    cudaGetSymbolAddress((void**)&proj, g_proj);
    cudaGetSymbolAddress((void**)&attn, g_attn);
    cudaGetSymbolAddress((void**)&inter, g_inter);
    cudaGetSymbolAddress((void**)&ffn, g_ffn);
    cudaGetSymbolAddress((void**)&hbuf, g_h);

    cudaFuncSetAttribute(gemm_g<0>, cudaFuncAttributeMaxDynamicSharedMemorySize, GEMM_SMEM);
    cudaFuncSetAttribute(gemm_g<1>, cudaFuncAttributeMaxDynamicSharedMemorySize, GEMM_SMEM);
    cudaFuncSetAttribute(qkv_kernel, cudaFuncAttributeMaxDynamicSharedMemorySize, GEMM_SMEM);
    cudaFuncSetAttribute(rel_softmax_kernel, cudaFuncAttributeMaxDynamicSharedMemorySize, RS_SMEM);

    relsum_kernel<<<4096, 256>>>((const float4*)rel, (const float4*)rel2,
                                 (const float4*)rela, (uint2*)relsum,
                                 (int)((size_t)SEQ * SEQ * HDIM / 4));

    const float* h = hid;
    for (int l = 0; l < NLAYERS; l++) {
        const size_t wofs  = (size_t)l * 768 * 768;
        const size_t wiofs = (size_t)l * 3072 * 768;

        // fused Q/K/V projections
        qkv_kernel<<<dim3(12, 16, 3), 128, GEMM_SMEM>>>(
            h, Wq + wofs, Wk + wofs, Wv + wofs,
            bq + l * 768, bk + l * 768, bv + l * 768, q, k, vt);

        // scores = q @ k^T (batched per head)
        gemm_g<0><<<dim3(16, 16, 12), 128, GEMM_SMEM>>>(
            q, k, nullptr, scores, 64, 1024, 65536LL, 65536LL, 1048576LL, 1.0f);

        // scores += q @ relsum^T; + mask; softmax  (fused, fp16 rel stream)
        rel_softmax_kernel<<<1024, 256, RS_SMEM>>>(relsum, q, scores, mask);

        // ctx = probs @ v
        gemm_g<0><<<dim3(1, 16, 12), 128, GEMM_SMEM>>>(
            scores, vt, nullptr, ctx, 1024, 768, 1048576LL, 65536LL, 64LL, 1.0f);

        // output projection + residual LN
        gemm_g<0><<<dim3(12, 16, 1), 128, GEMM_SMEM>>>(
            ctx, Wo + wofs, bo + l * 768, proj, 768, 768, 0, 0, 0, 1.0f);
        ln_kernel<<<1024, 256>>>(proj, h, g1 + l * 768, b1 + l * 768, attn);

        // FFN
        gemm_g<1><<<dim3(48, 16, 1), 128, GEMM_SMEM>>>(
            attn, Wi + wiofs, bi + l * 3072, inter, 768, 3072, 0, 0, 0, 1.0f);
        gemm_g<0><<<dim3(12, 16, 1), 128, GEMM_SMEM>>>(
            inter, W2 + wiofs, b2 + l * 768, ffn, 3072, 768, 0, 0, 0, 1.0f);

        float* outp = (l == NLAYERS - 1) ? (float*)d_out : hbuf;
        ln_kernel<<<1024, 256>>>(ffn, attn, g2 + l * 768, b2g + l * 768, outp);
        h = hbuf;
    }
}

// round 5
// speedup vs baseline: 3.3305x; 1.1705x over previous
#include <cuda_runtime.h>
#include <cuda_fp16.h>
#include <math.h>
#include <stdint.h>

#define SEQ 1024
#define DM  768
#define NHEAD 12
#define HDIM 64
#define NLAYERS 4
#define DFF 3072
#define STAGES 4

// ---------------- scratch (static device memory; no runtime allocs) ----------------
__device__ __half g_relsum[(size_t)SEQ * SEQ * HDIM];         // 128 MB (fp16)
__device__ float g_q[NHEAD * SEQ * HDIM];
__device__ float g_k[NHEAD * SEQ * HDIM];
__device__ float g_vt[NHEAD * HDIM * SEQ];                    // V transposed per head
__device__ float g_scores[(size_t)NHEAD * SEQ * SEQ];         // 48 MB
__device__ float g_ctx[SEQ * DM];
__device__ float g_proj[SEQ * DM];
__device__ float g_attn[SEQ * DM];
__device__ float g_inter[SEQ * DFF];                          // also PV split-K partials
__device__ float g_ffn[SEQ * DM];
__device__ float g_h[SEQ * DM];

// ---------------- helpers ----------------
__device__ __forceinline__ float warpRedMax(float v) {
#pragma unroll
    for (int o = 16; o > 0; o >>= 1) v = fmaxf(v, __shfl_xor_sync(0xffffffffu, v, o));
    return v;
}
__device__ __forceinline__ float warpRedSum(float v) {
#pragma unroll
    for (int o = 16; o > 0; o >>= 1) v += __shfl_xor_sync(0xffffffffu, v, o);
    return v;
}
__device__ __forceinline__ uint32_t f2tf(float x) {
    uint32_t r;
    asm("cvt.rna.tf32.f32 %0, %1;" : "=r"(r) : "f"(x));
    return r;
}
__device__ __forceinline__ void cp16(uint32_t dst, const void* src) {
    asm volatile("cp.async.cg.shared.global [%0], [%1], 16;" :: "r"(dst), "l"(src));
}
__device__ __forceinline__ void mma_tf32(float* c, const uint32_t* a, const uint32_t* b) {
    asm volatile(
        "mma.sync.aligned.m16n8k8.row.col.f32.tf32.tf32.f32 "
        "{%0,%1,%2,%3}, {%4,%5,%6,%7}, {%8,%9}, {%0,%1,%2,%3};"
        : "+f"(c[0]), "+f"(c[1]), "+f"(c[2]), "+f"(c[3])
        : "r"(a[0]), "r"(a[1]), "r"(a[2]), "r"(a[3]), "r"(b[0]), "r"(b[1]));
}
__device__ __forceinline__ void mma_f16(float* c, const uint32_t* a, const uint32_t* b) {
    asm volatile(
        "mma.sync.aligned.m16n8k16.row.col.f32.f16.f16.f32 "
        "{%0,%1,%2,%3}, {%4,%5,%6,%7}, {%8,%9}, {%0,%1,%2,%3};"
        : "+f"(c[0]), "+f"(c[1]), "+f"(c[2]), "+f"(c[3])
        : "r"(a[0]), "r"(a[1]), "r"(a[2]), "r"(a[3]), "r"(b[0]), "r"(b[1]));
}

// ---------------- relsum = rel_pos + rel_2d_pos + rel_2d_angle (fp16 out) ----------------
__global__ void __launch_bounds__(256) relsum_kernel(
    const float4* __restrict__ a, const float4* __restrict__ b,
    const float4* __restrict__ c, uint2* __restrict__ out, int n4)
{
    int i = blockIdx.x * blockDim.x + threadIdx.x;
    int stride = gridDim.x * blockDim.x;
    for (; i < n4; i += stride) {
        float4 x = a[i], y = b[i], z = c[i];
        x.x += y.x + z.x; x.y += y.y + z.y; x.z += y.z + z.z; x.w += y.w + z.w;
        __half2 h0 = __floats2half2_rn(x.x, x.y);
        __half2 h1 = __floats2half2_rn(x.z, x.w);
        uint2 o;
        o.x = *(uint32_t*)&h0;
        o.y = *(uint32_t*)&h1;
        out[i] = o;
    }
}

// ---------------- 64x64x32 tf32 GEMM mainloop (128 threads, 4-stage cp.async) ----------------
// Kloop = K elements to process; lda/ldw = row strides of A / W.
__device__ __forceinline__ void gemm64_mainloop(
    const float* __restrict__ Ag, const float* __restrict__ Wg,
    float* __restrict__ sm, int Kloop, int lda, int ldw, float acc[2][4][4])
{
    const int tid = threadIdx.x;
    const int row = tid >> 3;            // 0..15
    const int cg  = (tid & 7) << 2;      // 0,4,...,28

    float* As = sm;
    float* Ws = sm + STAGES * 2304;

    const uint32_t sa0 = (uint32_t)__cvta_generic_to_shared(As) + (uint32_t)(row * 36 + cg) * 4u;
    const uint32_t sw0 = (uint32_t)__cvta_generic_to_shared(Ws) + (uint32_t)(row * 36 + cg) * 4u;

    const float* Agp = Ag + (long long)row * lda + cg;
    const float* Wgp = Wg + (long long)row * ldw + cg;

    const int KT = Kloop >> 5;

#pragma unroll
    for (int st = 0; st < STAGES - 1; st++) {
        if (st < KT) {
#pragma unroll
            for (int p = 0; p < 4; p++) {
                cp16(sa0 + (uint32_t)(st * 2304 + p * 16 * 36) * 4u, Agp + (long long)(p * 16) * lda + st * 32);
                cp16(sw0 + (uint32_t)(st * 2304 + p * 16 * 36) * 4u, Wgp + (long long)(p * 16) * ldw + st * 32);
            }
        }
        asm volatile("cp.async.commit_group;");
    }

    const int wid = tid >> 5, lane = tid & 31;
    const int wm = wid & 1, wn = wid >> 1;
    const int g = lane >> 2, t = lane & 3;

    for (int kt = 0; kt < KT; kt++) {
        asm volatile("cp.async.wait_group 2;");
        __syncthreads();

        const int pf = kt + STAGES - 1;
        if (pf < KT) {
            const int st = pf & 3;
#pragma unroll
            for (int p = 0; p < 4; p++) {
                cp16(sa0 + (uint32_t)(st * 2304 + p * 16 * 36) * 4u, Agp + (long long)(p * 16) * lda + pf * 32);
                cp16(sw0 + (uint32_t)(st * 2304 + p * 16 * 36) * 4u, Wgp + (long long)(p * 16) * ldw + pf * 32);
            }
        }
        asm volatile("cp.async.commit_group;");

        const float* Asb = As + (kt & 3) * 2304;
        const float* Wsb = Ws + (kt & 3) * 2304;

#pragma unroll
        for (int ks = 0; ks < 32; ks += 8) {
            uint32_t a[2][4], b[4][2];
#pragma unroll
            for (int mt = 0; mt < 2; mt++) {
                const int r = wm * 32 + mt * 16 + g;
                a[mt][0] = f2tf(Asb[r * 36 + ks + t]);
                a[mt][1] = f2tf(Asb[(r + 8) * 36 + ks + t]);
                a[mt][2] = f2tf(Asb[r * 36 + ks + t + 4]);
                a[mt][3] = f2tf(Asb[(r + 8) * 36 + ks + t + 4]);
            }
#pragma unroll
            for (int nt = 0; nt < 4; nt++) {
                const int c = wn * 32 + nt * 8 + g;
                b[nt][0] = f2tf(Wsb[c * 36 + ks + t]);
                b[nt][1] = f2tf(Wsb[c * 36 + ks + t + 4]);
            }
#pragma unroll
            for (int mt = 0; mt < 2; mt++)
#pragma unroll
                for (int nt = 0; nt < 4; nt++)
                    mma_tf32(acc[mt][nt], a[mt], b[nt]);
        }
    }
}

// ---------------- generic GEMM kernel (z-batched) ----------------
template<int EPI>
__global__ void __launch_bounds__(128) gemm_g(
    const float* __restrict__ A, const float* __restrict__ W,
    const float* __restrict__ bias, float* __restrict__ C,
    int K, int ldC, long long sA, long long sW, long long sC, float scale)
{
    extern __shared__ float sm[];
    const int bz = blockIdx.z;
    const int m0 = blockIdx.y << 6, n0 = blockIdx.x << 6;

    float acc[2][4][4];
#pragma unroll
    for (int i = 0; i < 2; i++)
#pragma unroll
        for (int j = 0; j < 4; j++)
#pragma unroll
            for (int l = 0; l < 4; l++) acc[i][j][l] = 0.f;

    gemm64_mainloop(A + sA * bz + (long long)m0 * K,
                    W + sW * bz + (long long)n0 * K, sm, K, K, K, acc);
    C += sC * bz;

    const int tid = threadIdx.x, wid = tid >> 5, lane = tid & 31;
    const int wm = wid & 1, wn = wid >> 1, g = lane >> 2, t = lane & 3;

#pragma unroll
    for (int mt = 0; mt < 2; mt++) {
        const int rb = m0 + wm * 32 + mt * 16 + g;
#pragma unroll
        for (int nt = 0; nt < 4; nt++) {
            const int cb = n0 + wn * 32 + nt * 8 + 2 * t;
#pragma unroll
            for (int hf = 0; hf < 2; hf++) {
                const int m = rb + hf * 8;
                float v0 = acc[mt][nt][hf * 2 + 0];
                float v1 = acc[mt][nt][hf * 2 + 1];
                if (bias) { v0 += bias[cb]; v1 += bias[cb + 1]; }
                if (EPI == 1) {
                    v0 = 0.5f * v0 * (1.0f + erff(v0 * 0.70710678118654752f));
                    v1 = 0.5f * v1 * (1.0f + erff(v1 * 0.70710678118654752f));
                }
                v0 *= scale; v1 *= scale;
                *(float2*)&C[(long long)m * ldC + cb] = make_float2(v0, v1);
            }
        }
    }
}

// ---------------- PV split-K GEMM: part[ks] = probs[:, ks*256:(ks+1)*256] @ Vt^T ----------------
__global__ void __launch_bounds__(128) gemm_pv(
    const float* __restrict__ scores, const float* __restrict__ vt, float* __restrict__ part)
{
    extern __shared__ float sm[];
    const int ks = blockIdx.x;           // 0..3
    const int m0 = blockIdx.y << 6;
    const int hd = blockIdx.z;           // head

    float acc[2][4][4];
#pragma unroll
    for (int i = 0; i < 2; i++)
#pragma unroll
        for (int j = 0; j < 4; j++)
#pragma unroll
            for (int l = 0; l < 4; l++) acc[i][j][l] = 0.f;

    gemm64_mainloop(scores + (long long)hd * 1048576 + (long long)m0 * 1024 + ks * 256,
                    vt + (long long)hd * 65536 + ks * 256,
                    sm, 256, 1024, 1024, acc);

    float* C = part + (long long)ks * 786432 + hd * 64;

    const int tid = threadIdx.x, wid = tid >> 5, lane = tid & 31;
    const int wm = wid & 1, wn = wid >> 1, g = lane >> 2, t = lane & 3;

#pragma unroll
    for (int mt = 0; mt < 2; mt++) {
        const int rb = m0 + wm * 32 + mt * 16 + g;
#pragma unroll
        for (int nt = 0; nt < 4; nt++) {
            const int cb = wn * 32 + nt * 8 + 2 * t;
#pragma unroll
            for (int hf = 0; hf < 2; hf++) {
                const int m = rb + hf * 8;
                *(float2*)&C[(long long)m * 768 + cb] =
                    make_float2(acc[mt][nt][hf * 2 + 0], acc[mt][nt][hf * 2 + 1]);
            }
        }
    }
}

// ---------------- PV reduce: ctx = sum of 4 partials (deterministic order) ----------------
__global__ void __launch_bounds__(256) pv_reduce(
    const float4* __restrict__ part, float4* __restrict__ ctx)
{
    const int i = blockIdx.x * 256 + threadIdx.x;   // n4 = 196608
    float4 a = part[i];
    float4 b = part[i + 196608];
    float4 c = part[i + 393216];
    float4 d = part[i + 589824];
    a.x += b.x + c.x + d.x; a.y += b.y + c.y + d.y;
    a.z += b.z + c.z + d.z; a.w += b.w + c.w + d.w;
    ctx[i] = a;
}

// ---------------- fused rel-score + mask + softmax kernel ----------------
// One block per s. scores[n,s,:] += q[n,s,:] @ relsum[s,:,:]^T ; then mask + safe softmax.
// scores rows + mask prefetched into smem via cp.async group 0 (overlaps rel stream);
// softmax epilogue fully warp-parallel (no block syncs).
#define ACC_PITCH 1032
#define RS_QPITCH 72
#define RS_RPITCH 72                 // halves per relb row
#define RS_CHUNK_H (128 * RS_RPITCH) // halves per staging buffer
#define RS_NBUF 4

// smem layout (bytes):
//   accsc  fp32 [12][ACC_PITCH]           @ 0       (49536)
//   qs     fp16 [16][RS_QPITCH]           @ 49536   (2304)
//   relb   fp16 [RS_NBUF][128][RS_RPITCH] @ 51840   (73728)
//   sscore fp32 [12][1024]                @ 125568  (49152)
//   smask  fp32 [1024]                    @ 174720  (4096)
#define RS_SMEM 178816

__global__ void __launch_bounds__(256) rel_softmax_kernel(
    const __half* __restrict__ rel, const float* __restrict__ qb,
    float* __restrict__ scores, const float* __restrict__ mask)
{
    extern __shared__ char smc[];
    float*  accsc   = (float*)smc;
    __half* qs      = (__half*)(smc + 49536);
    __half* relb    = (__half*)(smc + 51840);
    float*  sscores = (float*)(smc + 125568);
    float*  smask   = (float*)(smc + 174720);

    const int s = blockIdx.x;
    const int tid = threadIdx.x;
    const int wid = tid >> 5, lane = tid & 31;
    const int g = lane >> 2, t = lane & 3;

    // ---- commit group 0: prefetch 12 score rows + mask into smem ----
    {
        const uint32_t ss_s = (uint32_t)__cvta_generic_to_shared(sscores);
#pragma unroll
        for (int p = 0; p < 12; p++) {
            const int idx = tid + 256 * p;          // 0..3071
            const int n = idx >> 8, c4 = (idx & 255) << 2;
            cp16(ss_s + (uint32_t)(n * 1024 + c4) * 4u,
                 scores + (((long long)n << 10) + s) * 1024 + c4);
        }
        cp16((uint32_t)__cvta_generic_to_shared(smask) + (uint32_t)(tid << 4),
             mask + (tid << 2));
        asm volatile("cp.async.commit_group;");
    }

    // load q for this s into padded fp16 16x64 tile (rows 12..15 zero)
    for (int i = tid; i < 16 * 64; i += 256) {
        const int r = i >> 6, c = i & 63;
        qs[r * RS_QPITCH + c] = __float2half((r < 12) ? qb[((long long)r << 16) + (s << 6) + c] : 0.f);
    }

    const __half* relS = rel + ((long long)s << 16);
    const uint32_t relb_s = (uint32_t)__cvta_generic_to_shared(relb);

    // prologue: chunks 0..2 -> bufs 0..2 (groups 1..3)
#pragma unroll
    for (int ch = 0; ch < RS_NBUF - 1; ch++) {
        const uint32_t dstb = relb_s + (uint32_t)(ch * RS_CHUNK_H) * 2u;
        const __half* src = relS + (long long)ch * 128 * 64;
#pragma unroll
        for (int p = 0; p < 4; p++) {
            const int idx = tid + 256 * p;
            const int r = idx >> 3, c8 = (idx & 7) << 3;
            cp16(dstb + (uint32_t)(r * RS_RPITCH + c8) * 2u, src + (long long)r * 64 + c8);
        }
        asm volatile("cp.async.commit_group;");
    }

    __syncthreads();   // qs visible

    // hoist q fragments: K=64 -> 4 k16-steps
    uint32_t afrag[4][4];
#pragma unroll
    for (int ks = 0; ks < 4; ks++) {
        afrag[ks][0] = *(const uint32_t*)&qs[g * RS_QPITCH + ks * 16 + 2 * t];
        afrag[ks][1] = *(const uint32_t*)&qs[(g + 8) * RS_QPITCH + ks * 16 + 2 * t];
        afrag[ks][2] = *(const uint32_t*)&qs[g * RS_QPITCH + ks * 16 + 2 * t + 8];
        afrag[ks][3] = *(const uint32_t*)&qs[(g + 8) * RS_QPITCH + ks * 16 + 2 * t + 8];
    }

    for (int ch = 0; ch < 8; ch++) {
        // groups committed so far: 4 + ch; allow last 2 pending -> scores + chunks 0..ch done
        asm volatile("cp.async.wait_group 2;");
        __syncthreads();

        const int pf = ch + RS_NBUF - 1;
        if (pf < 8) {
            const uint32_t dstb = relb_s + (uint32_t)((pf & (RS_NBUF - 1)) * RS_CHUNK_H) * 2u;
            const __half* src = relS + (long long)pf * 128 * 64;
#pragma unroll
            for (int p = 0; p < 4; p++) {
                const int idx = tid + 256 * p;
                const int r = idx >> 3, c8 = (idx & 7) << 3;
                cp16(dstb + (uint32_t)(r * RS_RPITCH + c8) * 2u, src + (long long)r * 64 + c8);
            }
        }
        asm volatile("cp.async.commit_group;");

        const __half* rb = relb + (ch & (RS_NBUF - 1)) * RS_CHUNK_H;
#pragma unroll
        for (int nt2 = 0; nt2 < 2; nt2++) {
            const int lrb = (wid * 2 + nt2) * 8;
            const int lr = lrb + g;
            float c[4] = {0.f, 0.f, 0.f, 0.f};
#pragma unroll
            for (int ks = 0; ks < 4; ks++) {
                uint32_t bb[2];
                bb[0] = *(const uint32_t*)&rb[lr * RS_RPITCH + ks * 16 + 2 * t];
                bb[1] = *(const uint32_t*)&rb[lr * RS_RPITCH + ks * 16 + 2 * t + 8];
                mma_f16(c, afrag[ks], bb);
            }
            const int kc = ch * 128 + lrb + 2 * t;
            *(float2*)&accsc[g * ACC_PITCH + kc] = make_float2(c[0], c[1]);
            if (g < 4)
                *(float2*)&accsc[(g + 8) * ACC_PITCH + kc] = make_float2(c[2], c[3]);
        }
    }
    __syncthreads();

    // ---- warp-parallel softmax: warp w handles head w (and 8+w for w<4) ----
#pragma unroll
    for (int hh = 0; hh < 2; hh++) {
        if (hh == 1 && wid >= 4) break;
        const int n = hh ? (8 + wid) : wid;

        float4 v[8];
        float m = -1e30f;
#pragma unroll
        for (int j = 0; j < 8; j++) {
            const int c4 = (lane + 32 * j) << 2;
            float4 a = *(const float4*)&sscores[n * 1024 + c4];
            const float4 b = *(const float4*)&accsc[n * ACC_PITCH + c4];
            const float4 mk = *(const float4*)&smask[c4];
            a.x += b.x + mk.x; a.y += b.y + mk.y; a.z += b.z + mk.z; a.w += b.w + mk.w;
            v[j] = a;
            m = fmaxf(m, fmaxf(fmaxf(a.x, a.y), fmaxf(a.z, a.w)));
        }
        m = warpRedMax(m);

        float sum = 0.f;
#pragma unroll
        for (int j = 0; j < 8; j++) {
            v[j].x = __expf(v[j].x - m); v[j].y = __expf(v[j].y - m);
            v[j].z = __expf(v[j].z - m); v[j].w = __expf(v[j].w - m);
            sum += v[j].x + v[j].y + v[j].z + v[j].w;
        }
        sum = warpRedSum(sum);
        const float inv = 1.0f / sum;

        float* srow = scores + (((long long)n << 10) + s) * 1024;
#pragma unroll
        for (int j = 0; j < 8; j++) {
            const int c4 = (lane + 32 * j) << 2;
            *(float4*)&srow[c4] = make_float4(v[j].x * inv, v[j].y * inv, v[j].z * inv, v[j].w * inv);
        }
    }
}

// ---------------- fused QKV projection kernel ----------------
__global__ void __launch_bounds__(128) qkv_kernel(
    const float* __restrict__ h,
    const float* __restrict__ Wq, const float* __restrict__ Wk, const float* __restrict__ Wv,
    const float* __restrict__ bq, const float* __restrict__ bk, const float* __restrict__ bv,
    float* __restrict__ qo, float* __restrict__ ko, float* __restrict__ vto)
{
    extern __shared__ float sm[];
    const int z = blockIdx.z;
    const float* W    = (z == 0) ? Wq : (z == 1) ? Wk : Wv;
    const float* bias = (z == 0) ? bq : (z == 1) ? bk : bv;
    float* out        = (z == 0) ? qo : (z == 1) ? ko : vto;
    const float scale = (z == 0) ? 0.125f : 1.0f;
    const int m0 = blockIdx.y << 6, n0 = blockIdx.x << 6;

    float acc[2][4][4];
#pragma unroll
    for (int i = 0; i < 2; i++)
#pragma unroll
        for (int j = 0; j < 4; j++)
#pragma unroll
            for (int l = 0; l < 4; l++) acc[i][j][l] = 0.f;

    gemm64_mainloop(h + (long long)m0 * DM, W + (long long)n0 * DM, sm, DM, DM, DM, acc);

    const int tid = threadIdx.x, wid = tid >> 5, lane = tid & 31;
    const int wm = wid & 1, wn = wid >> 1, g = lane >> 2, t = lane & 3;

#pragma unroll
    for (int mt = 0; mt < 2; mt++) {
        const int rb = m0 + wm * 32 + mt * 16 + g;
#pragma unroll
        for (int nt = 0; nt < 4; nt++) {
            const int cb = n0 + wn * 32 + nt * 8 + 2 * t;
#pragma unroll
            for (int hf = 0; hf < 2; hf++) {
                const int m = rb + hf * 8;
                float v0 = (acc[mt][nt][hf * 2 + 0] + bias[cb]) * scale;
                float v1 = (acc[mt][nt][hf * 2 + 1] + bias[cb + 1]) * scale;
                if (z < 2) {
                    const long long idx = ((long long)(cb >> 6) << 16) + (long long)m * 64 + (cb & 63);
                    *(float2*)&out[idx] = make_float2(v0, v1);
                } else {
                    out[(long long)cb * 1024 + m]       = v0;
                    out[(long long)(cb + 1) * 1024 + m] = v1;
                }
            }
        }
    }
}

// ---------------- residual + LayerNorm ----------------
__global__ void __launch_bounds__(256) ln_kernel(
    const float* __restrict__ x, const float* __restrict__ res,
    const float* __restrict__ g, const float* __restrict__ b, float* __restrict__ out)
{
    const int s = blockIdx.x;
    const int tid = threadIdx.x;
    const int lane = tid & 31, wid = tid >> 5;
    __shared__ float red[8];

    float v[3];
    float lsum = 0.f;
#pragma unroll
    for (int i = 0; i < 3; i++) {
        const int idx = tid + i * 256;
        v[i] = x[s * 768 + idx] + res[s * 768 + idx];
        lsum += v[i];
    }
    lsum = warpRedSum(lsum);
    if (lane == 0) red[wid] = lsum;
    __syncthreads();
    float tot = 0.f;
#pragma unroll
    for (int i = 0; i < 8; i++) tot += red[i];
    const float mu = tot * (1.0f / 768.0f);
    __syncthreads();

    float ls2 = 0.f;
#pragma unroll
    for (int i = 0; i < 3; i++) { const float d = v[i] - mu; ls2 += d * d; }
    ls2 = warpRedSum(ls2);
    if (lane == 0) red[wid] = ls2;
    __syncthreads();
    float tot2 = 0.f;
#pragma unroll
    for (int i = 0; i < 8; i++) tot2 += red[i];
    const float rs = rsqrtf(tot2 * (1.0f / 768.0f) + 1e-12f);

#pragma unroll
    for (int i = 0; i < 3; i++) {
        const int idx = tid + i * 256;
        out[s * 768 + idx] = (v[i] - mu) * rs * g[idx] + b[idx];
    }
}

// ---------------- launcher ----------------
#define GEMM_SMEM  (STAGES * 2304 * 2 * 4)            // 73728 B

extern "C" void kernel_launch(void* const* d_in, const int* in_sizes, int n_in,
                              void* d_out, int out_size)
{
    const float* hid  = (const float*)d_in[0];
    const float* mask = (const float*)d_in[1];
    const float* rel  = (const float*)d_in[2];
    const float* rel2 = (const float*)d_in[3];
    const float* rela = (const float*)d_in[4];
    const float* Wq = (const float*)d_in[5];   const float* bq = (const float*)d_in[6];
    const float* Wk = (const float*)d_in[7];   const float* bk = (const float*)d_in[8];
    const float* Wv = (const float*)d_in[9];   const float* bv = (const float*)d_in[10];
    const float* Wo = (const float*)d_in[11];  const float* bo = (const float*)d_in[12];
    const float* g1 = (const float*)d_in[13];  const float* b1 = (const float*)d_in[14];
    const float* Wi = (const float*)d_in[15];  const float* bi = (const float*)d_in[16];
    const float* W2 = (const float*)d_in[17];  const float* b2 = (const float*)d_in[18];
    const float* g2 = (const float*)d_in[19];  const float* b2g = (const float*)d_in[20];

    __half* relsum;
    float *q, *k, *vt, *scores, *ctx, *proj, *attn, *inter, *ffn, *hbuf;
    cudaGetSymbolAddress((void**)&relsum, g_relsum);
    cudaGetSymbolAddress((void**)&q, g_q);
    cudaGetSymbolAddress((void**)&k, g_k);
    cudaGetSymbolAddress((void**)&vt, g_vt);
    cudaGetSymbolAddress((void**)&scores, g_scores);
    cudaGetSymbolAddress((void**)&ctx, g_ctx);
    cudaGetSymbolAddress((void**)&proj, g_proj);
    cudaGetSymbolAddress((void**)&attn, g_attn);
    cudaGetSymbolAddress((void**)&inter, g_inter);
    cudaGetSymbolAddress((void**)&ffn, g_ffn);
    cudaGetSymbolAddress((void**)&hbuf, g_h);

    cudaFuncSetAttribute(gemm_g<0>, cudaFuncAttributeMaxDynamicSharedMemorySize, GEMM_SMEM);
    cudaFuncSetAttribute(gemm_g<1>, cudaFuncAttributeMaxDynamicSharedMemorySize, GEMM_SMEM);
    cudaFuncSetAttribute(qkv_kernel, cudaFuncAttributeMaxDynamicSharedMemorySize, GEMM_SMEM);
    cudaFuncSetAttribute(gemm_pv, cudaFuncAttributeMaxDynamicSharedMemorySize, GEMM_SMEM);
    cudaFuncSetAttribute(rel_softmax_kernel, cudaFuncAttributeMaxDynamicSharedMemorySize, RS_SMEM);

    relsum_kernel<<<4096, 256>>>((const float4*)rel, (const float4*)rel2,
                                 (const float4*)rela, (uint2*)relsum,
                                 (int)((size_t)SEQ * SEQ * HDIM / 4));

    const float* h = hid;
    for (int l = 0; l < NLAYERS; l++) {
        const size_t wofs  = (size_t)l * 768 * 768;
        const size_t wiofs = (size_t)l * 3072 * 768;

        // fused Q/K/V projections
        qkv_kernel<<<dim3(12, 16, 3), 128, GEMM_SMEM>>>(
            h, Wq + wofs, Wk + wofs, Wv + wofs,
            bq + l * 768, bk + l * 768, bv + l * 768, q, k, vt);

        // scores = q @ k^T (batched per head)
        gemm_g<0><<<dim3(16, 16, 12), 128, GEMM_SMEM>>>(
            q, k, nullptr, scores, 64, 1024, 65536LL, 65536LL, 1048576LL, 1.0f);

        // scores += q @ relsum^T; + mask; softmax  (fused, warp-parallel epilogue)
        rel_softmax_kernel<<<1024, 256, RS_SMEM>>>(relsum, q, scores, mask);

        // ctx = probs @ v  (split-K=4, partials in g_inter, deterministic reduce)
        gemm_pv<<<dim3(4, 16, 12), 128, GEMM_SMEM>>>(scores, vt, inter);
        pv_reduce<<<768, 256>>>((const float4*)inter, (float4*)ctx);

        // output projection + residual LN
        gemm_g<0><<<dim3(12, 16, 1), 128, GEMM_SMEM>>>(
            ctx, Wo + wofs, bo + l * 768, proj, 768, 768, 0, 0, 0, 1.0f);
        ln_kernel<<<1024, 256>>>(proj, h, g1 + l * 768, b1 + l * 768, attn);

        // FFN
        gemm_g<1><<<dim3(48, 16, 1), 128, GEMM_SMEM>>>(
            attn, Wi + wiofs, bi + l * 3072, inter, 768, 3072, 0, 0, 0, 1.0f);
        gemm_g<0><<<dim3(12, 16, 1), 128, GEMM_SMEM>>>(
            inter, W2 + wiofs, b2 + l * 768, ffn, 3072, 768, 0, 0, 0, 1.0f);

        float* outp = (l == NLAYERS - 1) ? (float*)d_out : hbuf;
        ln_kernel<<<1024, 256>>>(ffn, attn, g2 + l * 768, b2g + l * 768, outp);
        h = hbuf;
    }
}

// round 6
// speedup vs baseline: 4.8492x; 1.4560x over previous
#include <cuda_runtime.h>
#include <cuda_fp16.h>
#include <math.h>
#include <stdint.h>

#define SEQ 1024
#define DM  768
#define NHEAD 12
#define HDIM 64
#define NLAYERS 4
#define DFF 3072
#define STAGES 4

// ---------------- scratch (static device memory; no runtime allocs) ----------------
__device__ __half g_relsum[(size_t)SEQ * SEQ * HDIM];         // 128 MB (fp16)
__device__ float  g_scores[(size_t)NHEAD * SEQ * SEQ];        // 48 MB (fp32 logits)
__device__ __half g_probs[(size_t)NHEAD * SEQ * SEQ];         // 24 MB (fp16 probs)
__device__ float  g_part[4 * SEQ * DM];                       // PV split-K partials
__device__ __half g_h16[SEQ * DM];
__device__ __half g_hbuf[SEQ * DM];
__device__ __half g_q[NHEAD * SEQ * HDIM];
__device__ __half g_k[NHEAD * SEQ * HDIM];
__device__ __half g_vt[NHEAD * HDIM * SEQ];
__device__ __half g_ctx[SEQ * DM];
__device__ __half g_proj[SEQ * DM];
__device__ __half g_attn[SEQ * DM];
__device__ __half g_inter[SEQ * DFF];
__device__ __half g_ffn[SEQ * DM];
// fp16 weights (converted once per launch)
__device__ __half g_wq16[NLAYERS * DM * DM];
__device__ __half g_wk16[NLAYERS * DM * DM];
__device__ __half g_wv16[NLAYERS * DM * DM];
__device__ __half g_wo16[NLAYERS * DM * DM];
__device__ __half g_wi16[NLAYERS * DFF * DM];
__device__ __half g_w216[NLAYERS * DM * DFF];

// ---------------- helpers ----------------
__device__ __forceinline__ float warpRedMax(float v) {
#pragma unroll
    for (int o = 16; o > 0; o >>= 1) v = fmaxf(v, __shfl_xor_sync(0xffffffffu, v, o));
    return v;
}
__device__ __forceinline__ float warpRedSum(float v) {
#pragma unroll
    for (int o = 16; o > 0; o >>= 1) v += __shfl_xor_sync(0xffffffffu, v, o);
    return v;
}
__device__ __forceinline__ void cp16(uint32_t dst, const void* src) {
    asm volatile("cp.async.cg.shared.global [%0], [%1], 16;" :: "r"(dst), "l"(src));
}
__device__ __forceinline__ void mma_f16(float* c, const uint32_t* a, const uint32_t* b) {
    asm volatile(
        "mma.sync.aligned.m16n8k16.row.col.f32.f16.f16.f32 "
        "{%0,%1,%2,%3}, {%4,%5,%6,%7}, {%8,%9}, {%0,%1,%2,%3};"
        : "+f"(c[0]), "+f"(c[1]), "+f"(c[2]), "+f"(c[3])
        : "r"(a[0]), "r"(a[1]), "r"(a[2]), "r"(a[3]), "r"(b[0]), "r"(b[1]));
}

// ---------------- fp32 -> fp16 conversion (grid-stride) ----------------
__global__ void __launch_bounds__(256) f2h_kernel(
    const float4* __restrict__ src, uint2* __restrict__ dst, int n4)
{
    int i = blockIdx.x * blockDim.x + threadIdx.x;
    const int stride = gridDim.x * blockDim.x;
    for (; i < n4; i += stride) {
        float4 x = src[i];
        __half2 h0 = __floats2half2_rn(x.x, x.y);
        __half2 h1 = __floats2half2_rn(x.z, x.w);
        uint2 o; o.x = *(uint32_t*)&h0; o.y = *(uint32_t*)&h1;
        dst[i] = o;
    }
}

// ---------------- relsum = rel_pos + rel_2d_pos + rel_2d_angle (fp16 out) ----------------
__global__ void __launch_bounds__(256) relsum_kernel(
    const float4* __restrict__ a, const float4* __restrict__ b,
    const float4* __restrict__ c, uint2* __restrict__ out, int n4)
{
    int i = blockIdx.x * blockDim.x + threadIdx.x;
    const int stride = gridDim.x * blockDim.x;
    for (; i < n4; i += stride) {
        float4 x = a[i], y = b[i], z = c[i];
        x.x += y.x + z.x; x.y += y.y + z.y; x.z += y.z + z.z; x.w += y.w + z.w;
        __half2 h0 = __floats2half2_rn(x.x, x.y);
        __half2 h1 = __floats2half2_rn(x.z, x.w);
        uint2 o; o.x = *(uint32_t*)&h0; o.y = *(uint32_t*)&h1;
        out[i] = o;
    }
}

// ---------------- 64x64x64 fp16 GEMM mainloop (128 threads, 4-stage cp.async) ----------------
// smem: As[STAGES][64][72] halves, Ws[STAGES][64][72] halves
#define HSTG 4608   // halves per stage per matrix
__device__ __forceinline__ void hgemm64_mainloop(
    const __half* __restrict__ Ag, const __half* __restrict__ Wg,
    __half* __restrict__ sm, int Kloop, int lda, int ldw, float acc[2][4][4])
{
    const int tid = threadIdx.x;
    const int srow = tid >> 3;          // 0..15
    const int scol = (tid & 7) << 3;    // halves 0,8,...,56

    __half* As = sm;
    __half* Ws = sm + STAGES * HSTG;

    const uint32_t sa0 = (uint32_t)__cvta_generic_to_shared(As) + (uint32_t)(srow * 72 + scol) * 2u;
    const uint32_t sw0 = (uint32_t)__cvta_generic_to_shared(Ws) + (uint32_t)(srow * 72 + scol) * 2u;

    const __half* Agp = Ag + (long long)srow * lda + scol;
    const __half* Wgp = Wg + (long long)srow * ldw + scol;

    const int KT = Kloop >> 6;

#pragma unroll
    for (int st = 0; st < STAGES - 1; st++) {
        if (st < KT) {
#pragma unroll
            for (int p = 0; p < 4; p++) {
                cp16(sa0 + (uint32_t)(st * HSTG + p * 16 * 72) * 2u, Agp + (long long)(p * 16) * lda + st * 64);
                cp16(sw0 + (uint32_t)(st * HSTG + p * 16 * 72) * 2u, Wgp + (long long)(p * 16) * ldw + st * 64);
            }
        }
        asm volatile("cp.async.commit_group;");
    }

    const int wid = tid >> 5, lane = tid & 31;
    const int wm = wid & 1, wn = wid >> 1;
    const int g = lane >> 2, t = lane & 3;

    for (int kt = 0; kt < KT; kt++) {
        asm volatile("cp.async.wait_group 2;");
        __syncthreads();

        const int pf = kt + STAGES - 1;
        if (pf < KT) {
            const int st = pf & 3;
#pragma unroll
            for (int p = 0; p < 4; p++) {
                cp16(sa0 + (uint32_t)(st * HSTG + p * 16 * 72) * 2u, Agp + (long long)(p * 16) * lda + pf * 64);
                cp16(sw0 + (uint32_t)(st * HSTG + p * 16 * 72) * 2u, Wgp + (long long)(p * 16) * ldw + pf * 64);
            }
        }
        asm volatile("cp.async.commit_group;");

        const __half* Asb = As + (kt & 3) * HSTG;
        const __half* Wsb = Ws + (kt & 3) * HSTG;

#pragma unroll
        for (int ks = 0; ks < 4; ks++) {
            uint32_t a[2][4], b[4][2];
#pragma unroll
            for (int mt = 0; mt < 2; mt++) {
                const int r = wm * 32 + mt * 16 + g;
                a[mt][0] = *(const uint32_t*)&Asb[r * 72 + ks * 16 + 2 * t];
                a[mt][1] = *(const uint32_t*)&Asb[(r + 8) * 72 + ks * 16 + 2 * t];
                a[mt][2] = *(const uint32_t*)&Asb[r * 72 + ks * 16 + 2 * t + 8];
                a[mt][3] = *(const uint32_t*)&Asb[(r + 8) * 72 + ks * 16 + 2 * t + 8];
            }
#pragma unroll
            for (int nt = 0; nt < 4; nt++) {
                const int c = wn * 32 + nt * 8 + g;
                b[nt][0] = *(const uint32_t*)&Wsb[c * 72 + ks * 16 + 2 * t];
                b[nt][1] = *(const uint32_t*)&Wsb[c * 72 + ks * 16 + 2 * t + 8];
            }
#pragma unroll
            for (int mt = 0; mt < 2; mt++)
#pragma unroll
                for (int nt = 0; nt < 4; nt++)
                    mma_f16(acc[mt][nt], a[mt], b[nt]);
        }
    }
}

// ---------------- generic fp16 GEMM (z-batched): C = A @ W^T (+bias, GELU, scale) ----------------
// EPI: 0 none, 1 exact GELU. F32OUT: 0 -> fp16 C, 1 -> fp32 C.
template<int EPI, int F32OUT>
__global__ void __launch_bounds__(128) hgemm_g(
    const __half* __restrict__ A, const __half* __restrict__ W,
    const float* __restrict__ bias, void* __restrict__ Cv,
    int K, int ldC, long long sA, long long sW, long long sC, float scale)
{
    extern __shared__ __half smh[];
    const int bz = blockIdx.z;
    const int m0 = blockIdx.y << 6, n0 = blockIdx.x << 6;

    float acc[2][4][4];
#pragma unroll
    for (int i = 0; i < 2; i++)
#pragma unroll
        for (int j = 0; j < 4; j++)
#pragma unroll
            for (int l = 0; l < 4; l++) acc[i][j][l] = 0.f;

    hgemm64_mainloop(A + sA * bz + (long long)m0 * K,
                     W + sW * bz + (long long)n0 * K, smh, K, K, K, acc);

    const int tid = threadIdx.x, wid = tid >> 5, lane = tid & 31;
    const int wm = wid & 1, wn = wid >> 1, g = lane >> 2, t = lane & 3;

#pragma unroll
    for (int mt = 0; mt < 2; mt++) {
        const int rb = m0 + wm * 32 + mt * 16 + g;
#pragma unroll
        for (int nt = 0; nt < 4; nt++) {
            const int cb = n0 + wn * 32 + nt * 8 + 2 * t;
#pragma unroll
            for (int hf = 0; hf < 2; hf++) {
                const int m = rb + hf * 8;
                float v0 = acc[mt][nt][hf * 2 + 0];
                float v1 = acc[mt][nt][hf * 2 + 1];
                if (bias) { v0 += bias[cb]; v1 += bias[cb + 1]; }
                if (EPI == 1) {
                    v0 = 0.5f * v0 * (1.0f + erff(v0 * 0.70710678118654752f));
                    v1 = 0.5f * v1 * (1.0f + erff(v1 * 0.70710678118654752f));
                }
                v0 *= scale; v1 *= scale;
                if (F32OUT) {
                    float* C = (float*)Cv + sC * bz;
                    *(float2*)&C[(long long)m * ldC + cb] = make_float2(v0, v1);
                } else {
                    __half* C = (__half*)Cv + sC * bz;
                    __half2 h2 = __floats2half2_rn(v0, v1);
                    *(__half2*)&C[(long long)m * ldC + cb] = h2;
                }
            }
        }
    }
}

// ---------------- fused QKV projection (fp16) ----------------
__global__ void __launch_bounds__(128) hqkv_kernel(
    const __half* __restrict__ h,
    const __half* __restrict__ Wq, const __half* __restrict__ Wk, const __half* __restrict__ Wv,
    const float* __restrict__ bq, const float* __restrict__ bk, const float* __restrict__ bv,
    __half* __restrict__ qo, __half* __restrict__ ko, __half* __restrict__ vto)
{
    extern __shared__ __half smh[];
    const int z = blockIdx.z;
    const __half* W   = (z == 0) ? Wq : (z == 1) ? Wk : Wv;
    const float* bias = (z == 0) ? bq : (z == 1) ? bk : bv;
    __half* out       = (z == 0) ? qo : (z == 1) ? ko : vto;
    const float scale = (z == 0) ? 0.125f : 1.0f;
    const int m0 = blockIdx.y << 6, n0 = blockIdx.x << 6;

    float acc[2][4][4];
#pragma unroll
    for (int i = 0; i < 2; i++)
#pragma unroll
        for (int j = 0; j < 4; j++)
#pragma unroll
            for (int l = 0; l < 4; l++) acc[i][j][l] = 0.f;

    hgemm64_mainloop(h + (long long)m0 * DM, W + (long long)n0 * DM, smh, DM, DM, DM, acc);

    const int tid = threadIdx.x, wid = tid >> 5, lane = tid & 31;
    const int wm = wid & 1, wn = wid >> 1, g = lane >> 2, t = lane & 3;

#pragma unroll
    for (int mt = 0; mt < 2; mt++) {
        const int rb = m0 + wm * 32 + mt * 16 + g;
#pragma unroll
        for (int nt = 0; nt < 4; nt++) {
            const int cb = n0 + wn * 32 + nt * 8 + 2 * t;
#pragma unroll
            for (int hf = 0; hf < 2; hf++) {
                const int m = rb + hf * 8;
                float v0 = (acc[mt][nt][hf * 2 + 0] + bias[cb]) * scale;
                float v1 = (acc[mt][nt][hf * 2 + 1] + bias[cb + 1]) * scale;
                if (z < 2) {
                    const long long idx = ((long long)(cb >> 6) << 16) + (long long)m * 64 + (cb & 63);
                    __half2 h2 = __floats2half2_rn(v0, v1);
                    *(__half2*)&out[idx] = h2;
                } else {
                    out[(long long)cb * 1024 + m]       = __float2half(v0);
                    out[(long long)(cb + 1) * 1024 + m] = __float2half(v1);
                }
            }
        }
    }
}

// ---------------- PV split-K GEMM (fp16 probs x fp16 vt -> fp32 partials) ----------------
__global__ void __launch_bounds__(128) hgemm_pv(
    const __half* __restrict__ probs, const __half* __restrict__ vt, float* __restrict__ part)
{
    extern __shared__ __half smh[];
    const int ks = blockIdx.x;           // 0..3
    const int m0 = blockIdx.y << 6;
    const int hd = blockIdx.z;

    float acc[2][4][4];
#pragma unroll
    for (int i = 0; i < 2; i++)
#pragma unroll
        for (int j = 0; j < 4; j++)
#pragma unroll
            for (int l = 0; l < 4; l++) acc[i][j][l] = 0.f;

    hgemm64_mainloop(probs + (long long)hd * 1048576 + (long long)m0 * 1024 + ks * 256,
                     vt + (long long)hd * 65536 + ks * 256,
                     smh, 256, 1024, 1024, acc);

    float* C = part + (long long)ks * 786432 + hd * 64;

    const int tid = threadIdx.x, wid = tid >> 5, lane = tid & 31;
    const int wm = wid & 1, wn = wid >> 1, g = lane >> 2, t = lane & 3;

#pragma unroll
    for (int mt = 0; mt < 2; mt++) {
        const int rb = m0 + wm * 32 + mt * 16 + g;
#pragma unroll
        for (int nt = 0; nt < 4; nt++) {
            const int cb = wn * 32 + nt * 8 + 2 * t;
#pragma unroll
            for (int hf = 0; hf < 2; hf++) {
                const int m = rb + hf * 8;
                *(float2*)&C[(long long)m * 768 + cb] =
                    make_float2(acc[mt][nt][hf * 2 + 0], acc[mt][nt][hf * 2 + 1]);
            }
        }
    }
}

// ---------------- PV reduce: ctx(fp16) = sum of 4 fp32 partials ----------------
__global__ void __launch_bounds__(256) pv_reduce(
    const float4* __restrict__ part, uint2* __restrict__ ctx)
{
    const int i = blockIdx.x * 256 + threadIdx.x;   // n4 = 196608
    float4 a = part[i];
    const float4 b = part[i + 196608];
    const float4 c = part[i + 393216];
    const float4 d = part[i + 589824];
    a.x += b.x + c.x + d.x; a.y += b.y + c.y + d.y;
    a.z += b.z + c.z + d.z; a.w += b.w + c.w + d.w;
    __half2 h0 = __floats2half2_rn(a.x, a.y);
    __half2 h1 = __floats2half2_rn(a.z, a.w);
    uint2 o; o.x = *(uint32_t*)&h0; o.y = *(uint32_t*)&h1;
    ctx[i] = o;
}

// ---------------- fused rel-score + mask + softmax (fp16 rel/q, fp32 logits, fp16 probs) ----------------
#define ACC_PITCH 1032
#define RS_QPITCH 72
#define RS_RPITCH 72
#define RS_CHUNK_H (128 * RS_RPITCH)
#define RS_NBUF 4
// smem layout (bytes):
//   accsc  fp32 [12][ACC_PITCH]           @ 0       (49536)
//   qs     fp16 [16][RS_QPITCH]           @ 49536   (2304)
//   relb   fp16 [RS_NBUF][128][RS_RPITCH] @ 51840   (73728)
//   sscore fp32 [12][1024]                @ 125568  (49152)
//   smask  fp32 [1024]                    @ 174720  (4096)
#define RS_SMEM 178816

__global__ void __launch_bounds__(256) rel_softmax_kernel(
    const __half* __restrict__ rel, const __half* __restrict__ qb,
    const float* __restrict__ scores, __half* __restrict__ probs,
    const float* __restrict__ mask)
{
    extern __shared__ char smc[];
    float*  accsc   = (float*)smc;
    __half* qs      = (__half*)(smc + 49536);
    __half* relb    = (__half*)(smc + 51840);
    float*  sscores = (float*)(smc + 125568);
    float*  smask   = (float*)(smc + 174720);

    const int s = blockIdx.x;
    const int tid = threadIdx.x;
    const int wid = tid >> 5, lane = tid & 31;
    const int g = lane >> 2, t = lane & 3;

    // ---- group 0: prefetch 12 fp32 score rows + mask ----
    {
        const uint32_t ss_s = (uint32_t)__cvta_generic_to_shared(sscores);
#pragma unroll
        for (int p = 0; p < 12; p++) {
            const int idx = tid + 256 * p;
            const int n = idx >> 8, c4 = (idx & 255) << 2;
            cp16(ss_s + (uint32_t)(n * 1024 + c4) * 4u,
                 scores + (((long long)n << 10) + s) * 1024 + c4);
        }
        cp16((uint32_t)__cvta_generic_to_shared(smask) + (uint32_t)(tid << 4),
             mask + (tid << 2));
        asm volatile("cp.async.commit_group;");
    }

    // q for this s: fp16 head layout, rows 12..15 zero
    for (int i = tid; i < 16 * 64; i += 256) {
        const int r = i >> 6, c = i & 63;
        qs[r * RS_QPITCH + c] = (r < 12) ? qb[((long long)r << 16) + (s << 6) + c] : __float2half(0.f);
    }

    const __half* relS = rel + ((long long)s << 16);
    const uint32_t relb_s = (uint32_t)__cvta_generic_to_shared(relb);

#pragma unroll
    for (int ch = 0; ch < RS_NBUF - 1; ch++) {
        const uint32_t dstb = relb_s + (uint32_t)(ch * RS_CHUNK_H) * 2u;
        const __half* src = relS + (long long)ch * 128 * 64;
#pragma unroll
        for (int p = 0; p < 4; p++) {
            const int idx = tid + 256 * p;
            const int r = idx >> 3, c8 = (idx & 7) << 3;
            cp16(dstb + (uint32_t)(r * RS_RPITCH + c8) * 2u, src + (long long)r * 64 + c8);
        }
        asm volatile("cp.async.commit_group;");
    }

    __syncthreads();

    uint32_t afrag[4][4];
#pragma unroll
    for (int ks = 0; ks < 4; ks++) {
        afrag[ks][0] = *(const uint32_t*)&qs[g * RS_QPITCH + ks * 16 + 2 * t];
        afrag[ks][1] = *(const uint32_t*)&qs[(g + 8) * RS_QPITCH + ks * 16 + 2 * t];
        afrag[ks][2] = *(const uint32_t*)&qs[g * RS_QPITCH + ks * 16 + 2 * t + 8];
        afrag[ks][3] = *(const uint32_t*)&qs[(g + 8) * RS_QPITCH + ks * 16 + 2 * t + 8];
    }

    for (int ch = 0; ch < 8; ch++) {
        asm volatile("cp.async.wait_group 2;");
        __syncthreads();

        const int pf = ch + RS_NBUF - 1;
        if (pf < 8) {
            const uint32_t dstb = relb_s + (uint32_t)((pf & (RS_NBUF - 1)) * RS_CHUNK_H) * 2u;
            const __half* src = relS + (long long)pf * 128 * 64;
#pragma unroll
            for (int p = 0; p < 4; p++) {
                const int idx = tid + 256 * p;
                const int r = idx >> 3, c8 = (idx & 7) << 3;
                cp16(dstb + (uint32_t)(r * RS_RPITCH + c8) * 2u, src + (long long)r * 64 + c8);
            }
        }
        asm volatile("cp.async.commit_group;");

        const __half* rb = relb + (ch & (RS_NBUF - 1)) * RS_CHUNK_H;
#pragma unroll
        for (int nt2 = 0; nt2 < 2; nt2++) {
            const int lrb = (wid * 2 + nt2) * 8;
            const int lr = lrb + g;
            float c[4] = {0.f, 0.f, 0.f, 0.f};
#pragma unroll
            for (int ks = 0; ks < 4; ks++) {
                uint32_t bb[2];
                bb[0] = *(const uint32_t*)&rb[lr * RS_RPITCH + ks * 16 + 2 * t];
                bb[1] = *(const uint32_t*)&rb[lr * RS_RPITCH + ks * 16 + 2 * t + 8];
                mma_f16(c, afrag[ks], bb);
            }
            const int kc = ch * 128 + lrb + 2 * t;
            *(float2*)&accsc[g * ACC_PITCH + kc] = make_float2(c[0], c[1]);
            if (g < 4)
                *(float2*)&accsc[(g + 8) * ACC_PITCH + kc] = make_float2(c[2], c[3]);
        }
    }
    __syncthreads();

    // ---- warp-parallel softmax; write fp16 probs ----
#pragma unroll
    for (int hh = 0; hh < 2; hh++) {
        if (hh == 1 && wid >= 4) break;
        const int n = hh ? (8 + wid) : wid;

        float4 v[8];
        float m = -1e30f;
#pragma unroll
        for (int j = 0; j < 8; j++) {
            const int c4 = (lane + 32 * j) << 2;
            float4 a = *(const float4*)&sscores[n * 1024 + c4];
            const float4 b = *(const float4*)&accsc[n * ACC_PITCH + c4];
            const float4 mk = *(const float4*)&smask[c4];
            a.x += b.x + mk.x; a.y += b.y + mk.y; a.z += b.z + mk.z; a.w += b.w + mk.w;
            v[j] = a;
            m = fmaxf(m, fmaxf(fmaxf(a.x, a.y), fmaxf(a.z, a.w)));
        }
        m = warpRedMax(m);

        float sum = 0.f;
#pragma unroll
        for (int j = 0; j < 8; j++) {
            v[j].x = __expf(v[j].x - m); v[j].y = __expf(v[j].y - m);
            v[j].z = __expf(v[j].z - m); v[j].w = __expf(v[j].w - m);
            sum += v[j].x + v[j].y + v[j].z + v[j].w;
        }
        sum = warpRedSum(sum);
        const float inv = 1.0f / sum;

        __half* prow = probs + (((long long)n << 10) + s) * 1024;
#pragma unroll
        for (int j = 0; j < 8; j++) {
            const int c4 = (lane + 32 * j) << 2;
            __half2 p0 = __floats2half2_rn(v[j].x * inv, v[j].y * inv);
            __half2 p1 = __floats2half2_rn(v[j].z * inv, v[j].w * inv);
            uint2 o; o.x = *(uint32_t*)&p0; o.y = *(uint32_t*)&p1;
            *(uint2*)&prow[c4] = o;
        }
    }
}

// ---------------- residual + LayerNorm (fp16 in, fp16 or fp32 out) ----------------
template<int F32OUT>
__global__ void __launch_bounds__(256) ln_kernel(
    const __half* __restrict__ x, const __half* __restrict__ res,
    const float* __restrict__ g, const float* __restrict__ b, void* __restrict__ outv)
{
    const int s = blockIdx.x;
    const int tid = threadIdx.x;
    const int lane = tid & 31, wid = tid >> 5;
    __shared__ float red[8];

    float v[3];
    float lsum = 0.f;
#pragma unroll
    for (int i = 0; i < 3; i++) {
        const int idx = tid + i * 256;
        v[i] = __half2float(x[s * 768 + idx]) + __half2float(res[s * 768 + idx]);
        lsum += v[i];
    }
    lsum = warpRedSum(lsum);
    if (lane == 0) red[wid] = lsum;
    __syncthreads();
    float tot = 0.f;
#pragma unroll
    for (int i = 0; i < 8; i++) tot += red[i];
    const float mu = tot * (1.0f / 768.0f);
    __syncthreads();

    float ls2 = 0.f;
#pragma unroll
    for (int i = 0; i < 3; i++) { const float d = v[i] - mu; ls2 += d * d; }
    ls2 = warpRedSum(ls2);
    if (lane == 0) red[wid] = ls2;
    __syncthreads();
    float tot2 = 0.f;
#pragma unroll
    for (int i = 0; i < 8; i++) tot2 += red[i];
    const float rs = rsqrtf(tot2 * (1.0f / 768.0f) + 1e-12f);

#pragma unroll
    for (int i = 0; i < 3; i++) {
        const int idx = tid + i * 256;
        const float o = (v[i] - mu) * rs * g[idx] + b[idx];
        if (F32OUT) ((float*)outv)[s * 768 + idx] = o;
        else        ((__half*)outv)[s * 768 + idx] = __float2half(o);
    }
}

// ---------------- launcher ----------------
#define GEMM_SMEM  (STAGES * HSTG * 2 * 2)   // 73728 B

extern "C" void kernel_launch(void* const* d_in, const int* in_sizes, int n_in,
                              void* d_out, int out_size)
{
    const float* hid  = (const float*)d_in[0];
    const float* mask = (const float*)d_in[1];
    const float* rel  = (const float*)d_in[2];
    const float* rel2 = (const float*)d_in[3];
    const float* rela = (const float*)d_in[4];
    const float* Wq = (const float*)d_in[5];   const float* bq = (const float*)d_in[6];
    const float* Wk = (const float*)d_in[7];   const float* bk = (const float*)d_in[8];
    const float* Wv = (const float*)d_in[9];   const float* bv = (const float*)d_in[10];
    const float* Wo = (const float*)d_in[11];  const float* bo = (const float*)d_in[12];
    const float* g1 = (const float*)d_in[13];  const float* b1 = (const float*)d_in[14];
    const float* Wi = (const float*)d_in[15];  const float* bi = (const float*)d_in[16];
    const float* W2 = (const float*)d_in[17];  const float* b2 = (const float*)d_in[18];
    const float* g2 = (const float*)d_in[19];  const float* b2g = (const float*)d_in[20];

    __half *relsum, *probs, *h16, *hbuf, *q, *k, *vt, *ctx, *proj, *attn, *inter, *ffn;
    __half *wq16, *wk16, *wv16, *wo16, *wi16, *w216;
    float *scores, *part;
    cudaGetSymbolAddress((void**)&relsum, g_relsum);
    cudaGetSymbolAddress((void**)&scores, g_scores);
    cudaGetSymbolAddress((void**)&probs, g_probs);
    cudaGetSymbolAddress((void**)&part, g_part);
    cudaGetSymbolAddress((void**)&h16, g_h16);
    cudaGetSymbolAddress((void**)&hbuf, g_hbuf);
    cudaGetSymbolAddress((void**)&q, g_q);
    cudaGetSymbolAddress((void**)&k, g_k);
    cudaGetSymbolAddress((void**)&vt, g_vt);
    cudaGetSymbolAddress((void**)&ctx, g_ctx);
    cudaGetSymbolAddress((void**)&proj, g_proj);
    cudaGetSymbolAddress((void**)&attn, g_attn);
    cudaGetSymbolAddress((void**)&inter, g_inter);
    cudaGetSymbolAddress((void**)&ffn, g_ffn);
    cudaGetSymbolAddress((void**)&wq16, g_wq16);
    cudaGetSymbolAddress((void**)&wk16, g_wk16);
    cudaGetSymbolAddress((void**)&wv16, g_wv16);
    cudaGetSymbolAddress((void**)&wo16, g_wo16);
    cudaGetSymbolAddress((void**)&wi16, g_wi16);
    cudaGetSymbolAddress((void**)&w216, g_w216);

    cudaFuncSetAttribute(hgemm_g<0, 0>, cudaFuncAttributeMaxDynamicSharedMemorySize, GEMM_SMEM);
    cudaFuncSetAttribute(hgemm_g<0, 1>, cudaFuncAttributeMaxDynamicSharedMemorySize, GEMM_SMEM);
    cudaFuncSetAttribute(hgemm_g<1, 0>, cudaFuncAttributeMaxDynamicSharedMemorySize, GEMM_SMEM);
    cudaFuncSetAttribute(hqkv_kernel, cudaFuncAttributeMaxDynamicSharedMemorySize, GEMM_SMEM);
    cudaFuncSetAttribute(hgemm_pv, cudaFuncAttributeMaxDynamicSharedMemorySize, GEMM_SMEM);
    cudaFuncSetAttribute(rel_softmax_kernel, cudaFuncAttributeMaxDynamicSharedMemorySize, RS_SMEM);

    // one-time fp32 -> fp16 conversions
    f2h_kernel<<<1024, 256>>>((const float4*)hid, (uint2*)h16, SEQ * DM / 4);
    f2h_kernel<<<2048, 256>>>((const float4*)Wq, (uint2*)wq16, NLAYERS * DM * DM / 4);
    f2h_kernel<<<2048, 256>>>((const float4*)Wk, (uint2*)wk16, NLAYERS * DM * DM / 4);
    f2h_kernel<<<2048, 256>>>((const float4*)Wv, (uint2*)wv16, NLAYERS * DM * DM / 4);
    f2h_kernel<<<2048, 256>>>((const float4*)Wo, (uint2*)wo16, NLAYERS * DM * DM / 4);
    f2h_kernel<<<4096, 256>>>((const float4*)Wi, (uint2*)wi16, NLAYERS * DFF * DM / 4);
    f2h_kernel<<<4096, 256>>>((const float4*)W2, (uint2*)w216, NLAYERS * DM * DFF / 4);

    relsum_kernel<<<4096, 256>>>((const float4*)rel, (const float4*)rel2,
                                 (const float4*)rela, (uint2*)relsum,
                                 (int)((size_t)SEQ * SEQ * HDIM / 4));

    const __half* h = h16;
    for (int l = 0; l < NLAYERS; l++) {
        const size_t wofs  = (size_t)l * DM * DM;
        const size_t wiofs = (size_t)l * DFF * DM;

        // fused Q/K/V projections
        hqkv_kernel<<<dim3(12, 16, 3), 128, GEMM_SMEM>>>(
            h, wq16 + wofs, wk16 + wofs, wv16 + wofs,
            bq + l * 768, bk + l * 768, bv + l * 768, q, k, vt);

        // logits = q @ k^T (fp32 out)
        hgemm_g<0, 1><<<dim3(16, 16, 12), 128, GEMM_SMEM>>>(
            q, k, nullptr, scores, 64, 1024, 65536LL, 65536LL, 1048576LL, 1.0f);

        // + rel term + mask + softmax -> fp16 probs
        rel_softmax_kernel<<<1024, 256, RS_SMEM>>>(relsum, q, scores, probs, mask);

        // ctx = probs @ v  (split-K=4)
        hgemm_pv<<<dim3(4, 16, 12), 128, GEMM_SMEM>>>(probs, vt, part);
        pv_reduce<<<768, 256>>>((const float4*)part, (uint2*)ctx);

        // output projection + residual LN
        hgemm_g<0, 0><<<dim3(12, 16, 1), 128, GEMM_SMEM>>>(
            ctx, wo16 + wofs, bo + l * 768, proj, 768, 768, 0, 0, 0, 1.0f);
        ln_kernel<0><<<1024, 256>>>(proj, h, g1 + l * 768, b1 + l * 768, attn);

        // FFN
        hgemm_g<1, 0><<<dim3(48, 16, 1), 128, GEMM_SMEM>>>(
            attn, wi16 + wiofs, bi + l * 3072, inter, 768, 3072, 0, 0, 0, 1.0f);
        hgemm_g<0, 0><<<dim3(12, 16, 1), 128, GEMM_SMEM>>>(
            inter, w216 + wiofs, b2 + l * 768, ffn, 3072, 768, 0, 0, 0, 1.0f);

        if (l == NLAYERS - 1) {
            ln_kernel<1><<<1024, 256>>>(ffn, attn, g2 + l * 768, b2g + l * 768, d_out);
        } else {
            ln_kernel<0><<<1024, 256>>>(ffn, attn, g2 + l * 768, b2g + l * 768, hbuf);
        }
        h = hbuf;
    }
}

// round 7
// speedup vs baseline: 4.8621x; 1.0027x over previous
#include <cuda_runtime.h>
#include <cuda_fp16.h>
#include <math.h>
#include <stdint.h>

#define SEQ 1024
#define DM  768
#define NHEAD 12
#define HDIM 64
#define NLAYERS 4
#define DFF 3072
#define STAGES 4

// ---------------- scratch (static device memory; no runtime allocs) ----------------
__device__ __half g_relsum[(size_t)SEQ * SEQ * HDIM];         // 128 MB (fp16)
__device__ float  g_scores[(size_t)NHEAD * SEQ * SEQ];        // 48 MB (fp32 logits)
__device__ __half g_probs[(size_t)NHEAD * SEQ * SEQ];         // 24 MB (fp16 probs)
__device__ float  g_part[4 * SEQ * DM];                       // PV split-K partials
__device__ __half g_h16[SEQ * DM];
__device__ __half g_hbuf[SEQ * DM];
__device__ __half g_q[NHEAD * SEQ * HDIM];
__device__ __half g_k[NHEAD * SEQ * HDIM];
__device__ __half g_vt[NHEAD * HDIM * SEQ];
__device__ __half g_ctx[SEQ * DM];
__device__ __half g_proj[SEQ * DM];
__device__ __half g_attn[SEQ * DM];
__device__ __half g_inter[SEQ * DFF];
__device__ __half g_ffn[SEQ * DM];
// fp16 weights (converted once per launch)
__device__ __half g_wq16[NLAYERS * DM * DM];
__device__ __half g_wk16[NLAYERS * DM * DM];
__device__ __half g_wv16[NLAYERS * DM * DM];
__device__ __half g_wo16[NLAYERS * DM * DM];
__device__ __half g_wi16[NLAYERS * DFF * DM];
__device__ __half g_w216[NLAYERS * DM * DFF];

// ---------------- helpers ----------------
__device__ __forceinline__ float warpRedMax(float v) {
#pragma unroll
    for (int o = 16; o > 0; o >>= 1) v = fmaxf(v, __shfl_xor_sync(0xffffffffu, v, o));
    return v;
}
__device__ __forceinline__ float warpRedSum(float v) {
#pragma unroll
    for (int o = 16; o > 0; o >>= 1) v += __shfl_xor_sync(0xffffffffu, v, o);
    return v;
}
__device__ __forceinline__ void cp16(uint32_t dst, const void* src) {
    asm volatile("cp.async.cg.shared.global [%0], [%1], 16;" :: "r"(dst), "l"(src));
}
__device__ __forceinline__ void mma_f16(float* c, const uint32_t* a, const uint32_t* b) {
    asm volatile(
        "mma.sync.aligned.m16n8k16.row.col.f32.f16.f16.f32 "
        "{%0,%1,%2,%3}, {%4,%5,%6,%7}, {%8,%9}, {%0,%1,%2,%3};"
        : "+f"(c[0]), "+f"(c[1]), "+f"(c[2]), "+f"(c[3])
        : "r"(a[0]), "r"(a[1]), "r"(a[2]), "r"(a[3]), "r"(b[0]), "r"(b[1]));
}

// ---------------- fp32 -> fp16 conversion (grid-stride) ----------------
__global__ void __launch_bounds__(256) f2h_kernel(
    const float4* __restrict__ src, uint2* __restrict__ dst, int n4)
{
    int i = blockIdx.x * blockDim.x + threadIdx.x;
    const int stride = gridDim.x * blockDim.x;
    for (; i < n4; i += stride) {
        float4 x = src[i];
        __half2 h0 = __floats2half2_rn(x.x, x.y);
        __half2 h1 = __floats2half2_rn(x.z, x.w);
        uint2 o; o.x = *(uint32_t*)&h0; o.y = *(uint32_t*)&h1;
        dst[i] = o;
    }
}

// ---------------- relsum = rel_pos + rel_2d_pos + rel_2d_angle (fp16 out) ----------------
__global__ void __launch_bounds__(256) relsum_kernel(
    const float4* __restrict__ a, const float4* __restrict__ b,
    const float4* __restrict__ c, uint2* __restrict__ out, int n4)
{
    int i = blockIdx.x * blockDim.x + threadIdx.x;
    const int stride = gridDim.x * blockDim.x;
    for (; i < n4; i += stride) {
        float4 x = a[i], y = b[i], z = c[i];
        x.x += y.x + z.x; x.y += y.y + z.y; x.z += y.z + z.z; x.w += y.w + z.w;
        __half2 h0 = __floats2half2_rn(x.x, x.y);
        __half2 h1 = __floats2half2_rn(x.z, x.w);
        uint2 o; o.x = *(uint32_t*)&h0; o.y = *(uint32_t*)&h1;
        out[i] = o;
    }
}

// ---------------- 64x64x64 fp16 GEMM mainloop (256 threads, 8 warps, 4-stage cp.async) ----------------
// smem: As[STAGES][64][72] halves, Ws[STAGES][64][72] halves
// warp layout: wm = wid&1 (2 x 32 M), wn = wid>>1 (4 x 16 N); warp tile 32x16
#define HSTG 4608   // halves per stage per matrix
__device__ __forceinline__ void hgemm64_mainloop(
    const __half* __restrict__ Ag, const __half* __restrict__ Wg,
    __half* __restrict__ sm, int Kloop, int lda, int ldw, float acc[2][2][4])
{
    const int tid = threadIdx.x;
    const int srow = tid >> 3;          // 0..31
    const int scol = (tid & 7) << 3;    // halves 0,8,...,56

    __half* As = sm;
    __half* Ws = sm + STAGES * HSTG;

    const uint32_t sa0 = (uint32_t)__cvta_generic_to_shared(As) + (uint32_t)(srow * 72 + scol) * 2u;
    const uint32_t sw0 = (uint32_t)__cvta_generic_to_shared(Ws) + (uint32_t)(srow * 72 + scol) * 2u;

    const __half* Agp = Ag + (long long)srow * lda + scol;
    const __half* Wgp = Wg + (long long)srow * ldw + scol;

    const int KT = Kloop >> 6;
    const uint32_t ROW32 = 32u * 72u * 2u;

#pragma unroll
    for (int st = 0; st < STAGES - 1; st++) {
        if (st < KT) {
            cp16(sa0 + (uint32_t)(st * HSTG) * 2u,         Agp + st * 64);
            cp16(sa0 + (uint32_t)(st * HSTG) * 2u + ROW32, Agp + 32LL * lda + st * 64);
            cp16(sw0 + (uint32_t)(st * HSTG) * 2u,         Wgp + st * 64);
            cp16(sw0 + (uint32_t)(st * HSTG) * 2u + ROW32, Wgp + 32LL * ldw + st * 64);
        }
        asm volatile("cp.async.commit_group;");
    }

    const int wid = tid >> 5, lane = tid & 31;
    const int wm = wid & 1, wn = wid >> 1;
    const int g = lane >> 2, t = lane & 3;

    for (int kt = 0; kt < KT; kt++) {
        asm volatile("cp.async.wait_group 2;");
        __syncthreads();

        const int pf = kt + STAGES - 1;
        if (pf < KT) {
            const int st = pf & 3;
            cp16(sa0 + (uint32_t)(st * HSTG) * 2u,         Agp + pf * 64);
            cp16(sa0 + (uint32_t)(st * HSTG) * 2u + ROW32, Agp + 32LL * lda + pf * 64);
            cp16(sw0 + (uint32_t)(st * HSTG) * 2u,         Wgp + pf * 64);
            cp16(sw0 + (uint32_t)(st * HSTG) * 2u + ROW32, Wgp + 32LL * ldw + pf * 64);
        }
        asm volatile("cp.async.commit_group;");

        const __half* Asb = As + (kt & 3) * HSTG;
        const __half* Wsb = Ws + (kt & 3) * HSTG;

#pragma unroll
        for (int ks = 0; ks < 4; ks++) {
            uint32_t a[2][4], b[2][2];
#pragma unroll
            for (int mt = 0; mt < 2; mt++) {
                const int r = wm * 32 + mt * 16 + g;
                a[mt][0] = *(const uint32_t*)&Asb[r * 72 + ks * 16 + 2 * t];
                a[mt][1] = *(const uint32_t*)&Asb[(r + 8) * 72 + ks * 16 + 2 * t];
                a[mt][2] = *(const uint32_t*)&Asb[r * 72 + ks * 16 + 2 * t + 8];
                a[mt][3] = *(const uint32_t*)&Asb[(r + 8) * 72 + ks * 16 + 2 * t + 8];
            }
#pragma unroll
            for (int nt = 0; nt < 2; nt++) {
                const int c = wn * 16 + nt * 8 + g;
                b[nt][0] = *(const uint32_t*)&Wsb[c * 72 + ks * 16 + 2 * t];
                b[nt][1] = *(const uint32_t*)&Wsb[c * 72 + ks * 16 + 2 * t + 8];
            }
#pragma unroll
            for (int mt = 0; mt < 2; mt++)
#pragma unroll
                for (int nt = 0; nt < 2; nt++)
                    mma_f16(acc[mt][nt], a[mt], b[nt]);
        }
    }
}

// ---------------- generic fp16 GEMM (z-batched): C = A @ W^T (+bias, GELU, scale) ----------------
template<int EPI, int F32OUT>
__global__ void __launch_bounds__(256) hgemm_g(
    const __half* __restrict__ A, const __half* __restrict__ W,
    const float* __restrict__ bias, void* __restrict__ Cv,
    int K, int ldC, long long sA, long long sW, long long sC, float scale)
{
    extern __shared__ __half smh[];
    const int bz = blockIdx.z;
    const int m0 = blockIdx.y << 6, n0 = blockIdx.x << 6;

    float acc[2][2][4];
#pragma unroll
    for (int i = 0; i < 2; i++)
#pragma unroll
        for (int j = 0; j < 2; j++)
#pragma unroll
            for (int l = 0; l < 4; l++) acc[i][j][l] = 0.f;

    hgemm64_mainloop(A + sA * bz + (long long)m0 * K,
                     W + sW * bz + (long long)n0 * K, smh, K, K, K, acc);

    const int tid = threadIdx.x, wid = tid >> 5, lane = tid & 31;
    const int wm = wid & 1, wn = wid >> 1, g = lane >> 2, t = lane & 3;

#pragma unroll
    for (int mt = 0; mt < 2; mt++) {
        const int rb = m0 + wm * 32 + mt * 16 + g;
#pragma unroll
        for (int nt = 0; nt < 2; nt++) {
            const int cb = n0 + wn * 16 + nt * 8 + 2 * t;
#pragma unroll
            for (int hf = 0; hf < 2; hf++) {
                const int m = rb + hf * 8;
                float v0 = acc[mt][nt][hf * 2 + 0];
                float v1 = acc[mt][nt][hf * 2 + 1];
                if (bias) { v0 += bias[cb]; v1 += bias[cb + 1]; }
                if (EPI == 1) {
                    v0 = 0.5f * v0 * (1.0f + erff(v0 * 0.70710678118654752f));
                    v1 = 0.5f * v1 * (1.0f + erff(v1 * 0.70710678118654752f));
                }
                v0 *= scale; v1 *= scale;
                if (F32OUT) {
                    float* C = (float*)Cv + sC * bz;
                    *(float2*)&C[(long long)m * ldC + cb] = make_float2(v0, v1);
                } else {
                    __half* C = (__half*)Cv + sC * bz;
                    __half2 h2 = __floats2half2_rn(v0, v1);
                    *(__half2*)&C[(long long)m * ldC + cb] = h2;
                }
            }
        }
    }
}

// ---------------- fused QKV projection (fp16) ----------------
__global__ void __launch_bounds__(256) hqkv_kernel(
    const __half* __restrict__ h,
    const __half* __restrict__ Wq, const __half* __restrict__ Wk, const __half* __restrict__ Wv,
    const float* __restrict__ bq, const float* __restrict__ bk, const float* __restrict__ bv,
    __half* __restrict__ qo, __half* __restrict__ ko, __half* __restrict__ vto)
{
    extern __shared__ __half smh[];
    const int z = blockIdx.z;
    const __half* W   = (z == 0) ? Wq : (z == 1) ? Wk : Wv;
    const float* bias = (z == 0) ? bq : (z == 1) ? bk : bv;
    __half* out       = (z == 0) ? qo : (z == 1) ? ko : vto;
    const float scale = (z == 0) ? 0.125f : 1.0f;
    const int m0 = blockIdx.y << 6, n0 = blockIdx.x << 6;

    float acc[2][2][4];
#pragma unroll
    for (int i = 0; i < 2; i++)
#pragma unroll
        for (int j = 0; j < 2; j++)
#pragma unroll
            for (int l = 0; l < 4; l++) acc[i][j][l] = 0.f;

    hgemm64_mainloop(h + (long long)m0 * DM, W + (long long)n0 * DM, smh, DM, DM, DM, acc);

    const int tid = threadIdx.x, wid = tid >> 5, lane = tid & 31;
    const int wm = wid & 1, wn = wid >> 1, g = lane >> 2, t = lane & 3;

#pragma unroll
    for (int mt = 0; mt < 2; mt++) {
        const int rb = m0 + wm * 32 + mt * 16 + g;
#pragma unroll
        for (int nt = 0; nt < 2; nt++) {
            const int cb = n0 + wn * 16 + nt * 8 + 2 * t;
#pragma unroll
            for (int hf = 0; hf < 2; hf++) {
                const int m = rb + hf * 8;
                float v0 = (acc[mt][nt][hf * 2 + 0] + bias[cb]) * scale;
                float v1 = (acc[mt][nt][hf * 2 + 1] + bias[cb + 1]) * scale;
                if (z < 2) {
                    const long long idx = ((long long)(cb >> 6) << 16) + (long long)m * 64 + (cb & 63);
                    __half2 h2 = __floats2half2_rn(v0, v1);
                    *(__half2*)&out[idx] = h2;
                } else {
                    out[(long long)cb * 1024 + m]       = __float2half(v0);
                    out[(long long)(cb + 1) * 1024 + m] = __float2half(v1);
                }
            }
        }
    }
}

// ---------------- PV split-K GEMM (fp16 probs x fp16 vt -> fp32 partials) ----------------
__global__ void __launch_bounds__(256) hgemm_pv(
    const __half* __restrict__ probs, const __half* __restrict__ vt, float* __restrict__ part)
{
    extern __shared__ __half smh[];
    const int ks = blockIdx.x;           // 0..3
    const int m0 = blockIdx.y << 6;
    const int hd = blockIdx.z;

    float acc[2][2][4];
#pragma unroll
    for (int i = 0; i < 2; i++)
#pragma unroll
        for (int j = 0; j < 2; j++)
#pragma unroll
            for (int l = 0; l < 4; l++) acc[i][j][l] = 0.f;

    hgemm64_mainloop(probs + (long long)hd * 1048576 + (long long)m0 * 1024 + ks * 256,
                     vt + (long long)hd * 65536 + ks * 256,
                     smh, 256, 1024, 1024, acc);

    float* C = part + (long long)ks * 786432 + hd * 64;

    const int tid = threadIdx.x, wid = tid >> 5, lane = tid & 31;
    const int wm = wid & 1, wn = wid >> 1, g = lane >> 2, t = lane & 3;

#pragma unroll
    for (int mt = 0; mt < 2; mt++) {
        const int rb = m0 + wm * 32 + mt * 16 + g;
#pragma unroll
        for (int nt = 0; nt < 2; nt++) {
            const int cb = wn * 16 + nt * 8 + 2 * t;
#pragma unroll
            for (int hf = 0; hf < 2; hf++) {
                const int m = rb + hf * 8;
                *(float2*)&C[(long long)m * 768 + cb] =
                    make_float2(acc[mt][nt][hf * 2 + 0], acc[mt][nt][hf * 2 + 1]);
            }
        }
    }
}

// ---------------- PV reduce: ctx(fp16) = sum of 4 fp32 partials ----------------
__global__ void __launch_bounds__(256) pv_reduce(
    const float4* __restrict__ part, uint2* __restrict__ ctx)
{
    const int i = blockIdx.x * 256 + threadIdx.x;   // n4 = 196608
    float4 a = part[i];
    const float4 b = part[i + 196608];
    const float4 c = part[i + 393216];
    const float4 d = part[i + 589824];
    a.x += b.x + c.x + d.x; a.y += b.y + c.y + d.y;
    a.z += b.z + c.z + d.z; a.w += b.w + c.w + d.w;
    __half2 h0 = __floats2half2_rn(a.x, a.y);
    __half2 h1 = __floats2half2_rn(a.z, a.w);
    uint2 o; o.x = *(uint32_t*)&h0; o.y = *(uint32_t*)&h1;
    ctx[i] = o;
}

// ---------------- fused rel-score + mask + softmax ----------------
// One block per s. Prefetches 12 fp32 logit rows into padded smem, accumulates the
// rel MMA output directly into them, then warp-parallel softmax -> fp16 probs.
// smem 111232 B -> 2 CTAs/SM.
#define SC_PITCH 1032
#define RS_QPITCH 72
#define RS_RPITCH 72
#define RS_CHUNK_H (128 * RS_RPITCH)
#define RS_NBUF 3
// layout (bytes):
//   qs     fp16 [16][72]          @ 0      (2304)
//   sscore fp32 [12][1032]        @ 2304   (49536)
//   smask  fp32 [1024]            @ 51840  (4096)
//   relb   fp16 [3][128][72]      @ 55936  (55296)
#define RS_SMEM 111232

__global__ void __launch_bounds__(256) rel_softmax_kernel(
    const __half* __restrict__ rel, const __half* __restrict__ qb,
    const float* __restrict__ scores, __half* __restrict__ probs,
    const float* __restrict__ mask)
{
    extern __shared__ char smc[];
    __half* qs      = (__half*)smc;
    float*  sscores = (float*)(smc + 2304);
    float*  smask   = (float*)(smc + 51840);
    __half* relb    = (__half*)(smc + 55936);

    const int s = blockIdx.x;
    const int tid = threadIdx.x;
    const int wid = tid >> 5, lane = tid & 31;
    const int g = lane >> 2, t = lane & 3;

    // ---- group 0: prefetch 12 fp32 score rows (padded pitch) + mask ----
    {
        const uint32_t ss_s = (uint32_t)__cvta_generic_to_shared(sscores);
#pragma unroll
        for (int p = 0; p < 12; p++) {
            const int idx = tid + 256 * p;
            const int n = idx >> 8, c4 = (idx & 255) << 2;
            cp16(ss_s + (uint32_t)(n * SC_PITCH + c4) * 4u,
                 scores + (((long long)n << 10) + s) * 1024 + c4);
        }
        cp16((uint32_t)__cvta_generic_to_shared(smask) + (uint32_t)(tid << 4),
             mask + (tid << 2));
        asm volatile("cp.async.commit_group;");
    }

    // q for this s: fp16 head layout, rows 12..15 zero
    for (int i = tid; i < 16 * 64; i += 256) {
        const int r = i >> 6, c = i & 63;
        qs[r * RS_QPITCH + c] = (r < 12) ? qb[((long long)r << 16) + (s << 6) + c] : __float2half(0.f);
    }

    const __half* relS = rel + ((long long)s << 16);
    const uint32_t relb_s = (uint32_t)__cvta_generic_to_shared(relb);

#pragma unroll
    for (int ch = 0; ch < RS_NBUF - 1; ch++) {
        const uint32_t dstb = relb_s + (uint32_t)(ch * RS_CHUNK_H) * 2u;
        const __half* src = relS + (long long)ch * 128 * 64;
#pragma unroll
        for (int p = 0; p < 4; p++) {
            const int idx = tid + 256 * p;
            const int r = idx >> 3, c8 = (idx & 7) << 3;
            cp16(dstb + (uint32_t)(r * RS_RPITCH + c8) * 2u, src + (long long)r * 64 + c8);
        }
        asm volatile("cp.async.commit_group;");
    }

    __syncthreads();

    uint32_t afrag[4][4];
#pragma unroll
    for (int ks = 0; ks < 4; ks++) {
        afrag[ks][0] = *(const uint32_t*)&qs[g * RS_QPITCH + ks * 16 + 2 * t];
        afrag[ks][1] = *(const uint32_t*)&qs[(g + 8) * RS_QPITCH + ks * 16 + 2 * t];
        afrag[ks][2] = *(const uint32_t*)&qs[g * RS_QPITCH + ks * 16 + 2 * t + 8];
        afrag[ks][3] = *(const uint32_t*)&qs[(g + 8) * RS_QPITCH + ks * 16 + 2 * t + 8];
    }

    for (int ch = 0; ch < 8; ch++) {
        // groups: [scores][c0][c1] + one per loop iter; allow 1 pending
        asm volatile("cp.async.wait_group 1;");
        __syncthreads();

        const int pf = ch + RS_NBUF - 1;
        if (pf < 8) {
            const uint32_t dstb = relb_s + (uint32_t)((pf % RS_NBUF) * RS_CHUNK_H) * 2u;
            const __half* src = relS + (long long)pf * 128 * 64;
#pragma unroll
            for (int p = 0; p < 4; p++) {
                const int idx = tid + 256 * p;
                const int r = idx >> 3, c8 = (idx & 7) << 3;
                cp16(dstb + (uint32_t)(r * RS_RPITCH + c8) * 2u, src + (long long)r * 64 + c8);
            }
        }
        asm volatile("cp.async.commit_group;");

        const __half* rb = relb + (ch % RS_NBUF) * RS_CHUNK_H;
#pragma unroll
        for (int nt2 = 0; nt2 < 2; nt2++) {
            const int lrb = (wid * 2 + nt2) * 8;
            const int lr = lrb + g;
            float c[4] = {0.f, 0.f, 0.f, 0.f};
#pragma unroll
            for (int ks = 0; ks < 4; ks++) {
                uint32_t bb[2];
                bb[0] = *(const uint32_t*)&rb[lr * RS_RPITCH + ks * 16 + 2 * t];
                bb[1] = *(const uint32_t*)&rb[lr * RS_RPITCH + ks * 16 + 2 * t + 8];
                mma_f16(c, afrag[ks], bb);
            }
            const int kc = ch * 128 + lrb + 2 * t;
            float2 o0 = *(float2*)&sscores[g * SC_PITCH + kc];
            o0.x += c[0]; o0.y += c[1];
            *(float2*)&sscores[g * SC_PITCH + kc] = o0;
            if (g < 4) {
                float2 o1 = *(float2*)&sscores[(g + 8) * SC_PITCH + kc];
                o1.x += c[2]; o1.y += c[3];
                *(float2*)&sscores[(g + 8) * SC_PITCH + kc] = o1;
            }
        }
    }
    __syncthreads();

    // ---- warp-parallel softmax; write fp16 probs ----
#pragma unroll
    for (int hh = 0; hh < 2; hh++) {
        if (hh == 1 && wid >= 4) break;
        const int n = hh ? (8 + wid) : wid;

        float4 v[8];
        float m = -1e30f;
#pragma unroll
        for (int j = 0; j < 8; j++) {
            const int c4 = (lane + 32 * j) << 2;
            float4 a = *(const float4*)&sscores[n * SC_PITCH + c4];
            const float4 mk = *(const float4*)&smask[c4];
            a.x += mk.x; a.y += mk.y; a.z += mk.z; a.w += mk.w;
            v[j] = a;
            m = fmaxf(m, fmaxf(fmaxf(a.x, a.y), fmaxf(a.z, a.w)));
        }
        m = warpRedMax(m);

        float sum = 0.f;
#pragma unroll
        for (int j = 0; j < 8; j++) {
            v[j].x = __expf(v[j].x - m); v[j].y = __expf(v[j].y - m);
            v[j].z = __expf(v[j].z - m); v[j].w = __expf(v[j].w - m);
            sum += v[j].x + v[j].y + v[j].z + v[j].w;
        }
        sum = warpRedSum(sum);
        const float inv = 1.0f / sum;

        __half* prow = probs + (((long long)n << 10) + s) * 1024;
#pragma unroll
        for (int j = 0; j < 8; j++) {
            const int c4 = (lane + 32 * j) << 2;
            __half2 p0 = __floats2half2_rn(v[j].x * inv, v[j].y * inv);
            __half2 p1 = __floats2half2_rn(v[j].z * inv, v[j].w * inv);
            uint2 o; o.x = *(uint32_t*)&p0; o.y = *(uint32_t*)&p1;
            *(uint2*)&prow[c4] = o;
        }
    }
}

// ---------------- residual + LayerNorm (fp16 in, fp16 or fp32 out) ----------------
template<int F32OUT>
__global__ void __launch_bounds__(256) ln_kernel(
    const __half* __restrict__ x, const __half* __restrict__ res,
    const float* __restrict__ g, const float* __restrict__ b, void* __restrict__ outv)
{
    const int s = blockIdx.x;
    const int tid = threadIdx.x;
    const int lane = tid & 31, wid = tid >> 5;
    __shared__ float red[8];

    float v[3];
    float lsum = 0.f;
#pragma unroll
    for (int i = 0; i < 3; i++) {
        const int idx = tid + i * 256;
        v[i] = __half2float(x[s * 768 + idx]) + __half2float(res[s * 768 + idx]);
        lsum += v[i];
    }
    lsum = warpRedSum(lsum);
    if (lane == 0) red[wid] = lsum;
    __syncthreads();
    float tot = 0.f;
#pragma unroll
    for (int i = 0; i < 8; i++) tot += red[i];
    const float mu = tot * (1.0f / 768.0f);
    __syncthreads();

    float ls2 = 0.f;
#pragma unroll
    for (int i = 0; i < 3; i++) { const float d = v[i] - mu; ls2 += d * d; }
    ls2 = warpRedSum(ls2);
    if (lane == 0) red[wid] = ls2;
    __syncthreads();
    float tot2 = 0.f;
#pragma unroll
    for (int i = 0; i < 8; i++) tot2 += red[i];
    const float rs = rsqrtf(tot2 * (1.0f / 768.0f) + 1e-12f);

#pragma unroll
    for (int i = 0; i < 3; i++) {
        const int idx = tid + i * 256;
        const float o = (v[i] - mu) * rs * g[idx] + b[idx];
        if (F32OUT) ((float*)outv)[s * 768 + idx] = o;
        else        ((__half*)outv)[s * 768 + idx] = __float2half(o);
    }
}

// ---------------- launcher ----------------
#define GEMM_SMEM  (STAGES * HSTG * 2 * 2)   // 73728 B

extern "C" void kernel_launch(void* const* d_in, const int* in_sizes, int n_in,
                              void* d_out, int out_size)
{
    const float* hid  = (const float*)d_in[0];
    const float* mask = (const float*)d_in[1];
    const float* rel  = (const float*)d_in[2];
    const float* rel2 = (const float*)d_in[3];
    const float* rela = (const float*)d_in[4];
    const float* Wq = (const float*)d_in[5];   const float* bq = (const float*)d_in[6];
    const float* Wk = (const float*)d_in[7];   const float* bk = (const float*)d_in[8];
    const float* Wv = (const float*)d_in[9];   const float* bv = (const float*)d_in[10];
    const float* Wo = (const float*)d_in[11];  const float* bo = (const float*)d_in[12];
    const float* g1 = (const float*)d_in[13];  const float* b1 = (const float*)d_in[14];
    const float* Wi = (const float*)d_in[15];  const float* bi = (const float*)d_in[16];
    const float* W2 = (const float*)d_in[17];  const float* b2 = (const float*)d_in[18];
    const float* g2 = (const float*)d_in[19];  const float* b2g = (const float*)d_in[20];

    __half *relsum, *probs, *h16, *hbuf, *q, *k, *vt, *ctx, *proj, *attn, *inter, *ffn;
    __half *wq16, *wk16, *wv16, *wo16, *wi16, *w216;
    float *scores, *part;
    cudaGetSymbolAddress((void**)&relsum, g_relsum);
    cudaGetSymbolAddress((void**)&scores, g_scores);
    cudaGetSymbolAddress((void**)&probs, g_probs);
    cudaGetSymbolAddress((void**)&part, g_part);
    cudaGetSymbolAddress((void**)&h16, g_h16);
    cudaGetSymbolAddress((void**)&hbuf, g_hbuf);
    cudaGetSymbolAddress((void**)&q, g_q);
    cudaGetSymbolAddress((void**)&k, g_k);
    cudaGetSymbolAddress((void**)&vt, g_vt);
    cudaGetSymbolAddress((void**)&ctx, g_ctx);
    cudaGetSymbolAddress((void**)&proj, g_proj);
    cudaGetSymbolAddress((void**)&attn, g_attn);
    cudaGetSymbolAddress((void**)&inter, g_inter);
    cudaGetSymbolAddress((void**)&ffn, g_ffn);
    cudaGetSymbolAddress((void**)&wq16, g_wq16);
    cudaGetSymbolAddress((void**)&wk16, g_wk16);
    cudaGetSymbolAddress((void**)&wv16, g_wv16);
    cudaGetSymbolAddress((void**)&wo16, g_wo16);
    cudaGetSymbolAddress((void**)&wi16, g_wi16);
    cudaGetSymbolAddress((void**)&w216, g_w216);

    cudaFuncSetAttribute(hgemm_g<0, 0>, cudaFuncAttributeMaxDynamicSharedMemorySize, GEMM_SMEM);
    cudaFuncSetAttribute(hgemm_g<0, 1>, cudaFuncAttributeMaxDynamicSharedMemorySize, GEMM_SMEM);
    cudaFuncSetAttribute(hgemm_g<1, 0>, cudaFuncAttributeMaxDynamicSharedMemorySize, GEMM_SMEM);
    cudaFuncSetAttribute(hqkv_kernel, cudaFuncAttributeMaxDynamicSharedMemorySize, GEMM_SMEM);
    cudaFuncSetAttribute(hgemm_pv, cudaFuncAttributeMaxDynamicSharedMemorySize, GEMM_SMEM);
    cudaFuncSetAttribute(rel_softmax_kernel, cudaFuncAttributeMaxDynamicSharedMemorySize, RS_SMEM);

    // one-time fp32 -> fp16 conversions
    f2h_kernel<<<1024, 256>>>((const float4*)hid, (uint2*)h16, SEQ * DM / 4);
    f2h_kernel<<<2048, 256>>>((const float4*)Wq, (uint2*)wq16, NLAYERS * DM * DM / 4);
    f2h_kernel<<<2048, 256>>>((const float4*)Wk, (uint2*)wk16, NLAYERS * DM * DM / 4);
    f2h_kernel<<<2048, 256>>>((const float4*)Wv, (uint2*)wv16, NLAYERS * DM * DM / 4);
    f2h_kernel<<<2048, 256>>>((const float4*)Wo, (uint2*)wo16, NLAYERS * DM * DM / 4);
    f2h_kernel<<<4096, 256>>>((const float4*)Wi, (uint2*)wi16, NLAYERS * DFF * DM / 4);
    f2h_kernel<<<4096, 256>>>((const float4*)W2, (uint2*)w216, NLAYERS * DM * DFF / 4);

    relsum_kernel<<<4096, 256>>>((const float4*)rel, (const float4*)rel2,
                                 (const float4*)rela, (uint2*)relsum,
                                 (int)((size_t)SEQ * SEQ * HDIM / 4));

    const __half* h = h16;
    for (int l = 0; l < NLAYERS; l++) {
        const size_t wofs  = (size_t)l * DM * DM;
        const size_t wiofs = (size_t)l * DFF * DM;

        // fused Q/K/V projections
        hqkv_kernel<<<dim3(12, 16, 3), 256, GEMM_SMEM>>>(
            h, wq16 + wofs, wk16 + wofs, wv16 + wofs,
            bq + l * 768, bk + l * 768, bv + l * 768, q, k, vt);

        // logits = q @ k^T (fp32 out)
        hgemm_g<0, 1><<<dim3(16, 16, 12), 256, GEMM_SMEM>>>(
            q, k, nullptr, scores, 64, 1024, 65536LL, 65536LL, 1048576LL, 1.0f);

        // + rel term + mask + softmax -> fp16 probs
        rel_softmax_kernel<<<1024, 256, RS_SMEM>>>(relsum, q, scores, probs, mask);

        // ctx = probs @ v  (split-K=4)
        hgemm_pv<<<dim3(4, 16, 12), 256, GEMM_SMEM>>>(probs, vt, part);
        pv_reduce<<<768, 256>>>((const float4*)part, (uint2*)ctx);

        // output projection + residual LN
        hgemm_g<0, 0><<<dim3(12, 16, 1), 256, GEMM_SMEM>>>(
            ctx, wo16 + wofs, bo + l * 768, proj, 768, 768, 0, 0, 0, 1.0f);
        ln_kernel<0><<<1024, 256>>>(proj, h, g1 + l * 768, b1 + l * 768, attn);

        // FFN
        hgemm_g<1, 0><<<dim3(48, 16, 1), 256, GEMM_SMEM>>>(
            attn, wi16 + wiofs, bi + l * 3072, inter, 768, 3072, 0, 0, 0, 1.0f);
        hgemm_g<0, 0><<<dim3(12, 16, 1), 256, GEMM_SMEM>>>(
            inter, w216 + wiofs, b2 + l * 768, ffn, 3072, 768, 0, 0, 0, 1.0f);

        if (l == NLAYERS - 1) {
            ln_kernel<1><<<1024, 256>>>(ffn, attn, g2 + l * 768, b2g + l * 768, d_out);
        } else {
            ln_kernel<0><<<1024, 256>>>(ffn, attn, g2 + l * 768, b2g + l * 768, hbuf);
        }
        h = hbuf;
    }
}

// round 8
// speedup vs baseline: 5.4628x; 1.1235x over previous
#include <cuda_runtime.h>
#include <cuda_fp16.h>
#include <math.h>
#include <stdint.h>

#define SEQ 1024
#define DM  768
#define NHEAD 12
#define HDIM 64
#define NLAYERS 4
#define DFF 3072

// ---------------- scratch (static device memory; no runtime allocs) ----------------
__device__ __half g_relsum[(size_t)SEQ * SEQ * HDIM];         // 128 MB (fp16)
__device__ float  g_scores[(size_t)NHEAD * SEQ * SEQ];        // 48 MB (fp32 logits)
__device__ __half g_probs[(size_t)NHEAD * SEQ * SEQ];         // 24 MB (fp16 probs)
__device__ float  g_part[4 * SEQ * DM];                       // PV split-K partials
__device__ __half g_h16[SEQ * DM];
__device__ __half g_hbuf[SEQ * DM];
__device__ __half g_q[NHEAD * SEQ * HDIM];
__device__ __half g_k[NHEAD * SEQ * HDIM];
__device__ __half g_vt[NHEAD * HDIM * SEQ];
__device__ __half g_ctx[SEQ * DM];
__device__ __half g_proj[SEQ * DM];
__device__ __half g_attn[SEQ * DM];
__device__ __half g_inter[SEQ * DFF];
__device__ __half g_ffn[SEQ * DM];
// fp16 weights (converted once per launch)
__device__ __half g_wq16[NLAYERS * DM * DM];
__device__ __half g_wk16[NLAYERS * DM * DM];
__device__ __half g_wv16[NLAYERS * DM * DM];
__device__ __half g_wo16[NLAYERS * DM * DM];
__device__ __half g_wi16[NLAYERS * DFF * DM];
__device__ __half g_w216[NLAYERS * DM * DFF];

// ---------------- helpers ----------------
__device__ __forceinline__ float warpRedMax(float v) {
#pragma unroll
    for (int o = 16; o > 0; o >>= 1) v = fmaxf(v, __shfl_xor_sync(0xffffffffu, v, o));
    return v;
}
__device__ __forceinline__ float warpRedSum(float v) {
#pragma unroll
    for (int o = 16; o > 0; o >>= 1) v += __shfl_xor_sync(0xffffffffu, v, o);
    return v;
}
__device__ __forceinline__ void cp16(uint32_t dst, const void* src) {
    asm volatile("cp.async.cg.shared.global [%0], [%1], 16;" :: "r"(dst), "l"(src));
}
__device__ __forceinline__ void mma_f16(float* c, const uint32_t* a, const uint32_t* b) {
    asm volatile(
        "mma.sync.aligned.m16n8k16.row.col.f32.f16.f16.f32 "
        "{%0,%1,%2,%3}, {%4,%5,%6,%7}, {%8,%9}, {%0,%1,%2,%3};"
        : "+f"(c[0]), "+f"(c[1]), "+f"(c[2]), "+f"(c[3])
        : "r"(a[0]), "r"(a[1]), "r"(a[2]), "r"(a[3]), "r"(b[0]), "r"(b[1]));
}
__device__ __forceinline__ void ldsm_x4(uint32_t& r0, uint32_t& r1, uint32_t& r2, uint32_t& r3,
                                        uint32_t addr) {
    asm volatile("ldmatrix.sync.aligned.m8n8.x4.shared.b16 {%0,%1,%2,%3}, [%4];"
                 : "=r"(r0), "=r"(r1), "=r"(r2), "=r"(r3) : "r"(addr));
}
__device__ __forceinline__ uint2 f4_to_h4(float4 x) {
    __half2 h0 = __floats2half2_rn(x.x, x.y);
    __half2 h1 = __floats2half2_rn(x.z, x.w);
    uint2 o; o.x = *(uint32_t*)&h0; o.y = *(uint32_t*)&h1;
    return o;
}

// ---------------- one-shot fp32 -> fp16 conversions ----------------
__global__ void __launch_bounds__(256) f2h1_kernel(
    const float4* __restrict__ s, uint2* __restrict__ d)
{
    const int i = blockIdx.x * 256 + threadIdx.x;
    d[i] = f4_to_h4(s[i]);
}
__global__ void __launch_bounds__(256) f2h4_kernel(
    const float4* __restrict__ s0, const float4* __restrict__ s1,
    const float4* __restrict__ s2, const float4* __restrict__ s3,
    uint2* __restrict__ d0, uint2* __restrict__ d1,
    uint2* __restrict__ d2, uint2* __restrict__ d3)
{
    const int i = blockIdx.x * 256 + threadIdx.x;
    const int z = blockIdx.z;
    const float4* s = (z == 0) ? s0 : (z == 1) ? s1 : (z == 2) ? s2 : s3;
    uint2* d        = (z == 0) ? d0 : (z == 1) ? d1 : (z == 2) ? d2 : d3;
    d[i] = f4_to_h4(s[i]);
}
__global__ void __launch_bounds__(256) f2h2_kernel(
    const float4* __restrict__ s0, const float4* __restrict__ s1,
    uint2* __restrict__ d0, uint2* __restrict__ d1)
{
    const int i = blockIdx.x * 256 + threadIdx.x;
    const float4* s = blockIdx.z ? s1 : s0;
    uint2* d        = blockIdx.z ? d1 : d0;
    d[i] = f4_to_h4(s[i]);
}

// ---------------- relsum = rel_pos + rel_2d_pos + rel_2d_angle (fp16 out, one-shot) ----------------
// grid 32768 x 256; each thread handles 2 independent float4 triplets (6 loads in flight)
#define RELSUM_HALF 8388608
__global__ void __launch_bounds__(256) relsum_kernel(
    const float4* __restrict__ a, const float4* __restrict__ b,
    const float4* __restrict__ c, uint2* __restrict__ out)
{
    const int i = blockIdx.x * 256 + threadIdx.x;
    float4 x0 = a[i], y0 = b[i], z0 = c[i];
    float4 x1 = a[i + RELSUM_HALF], y1 = b[i + RELSUM_HALF], z1 = c[i + RELSUM_HALF];
    x0.x += y0.x + z0.x; x0.y += y0.y + z0.y; x0.z += y0.z + z0.z; x0.w += y0.w + z0.w;
    x1.x += y1.x + z1.x; x1.y += y1.y + z1.y; x1.z += y1.z + z1.z; x1.w += y1.w + z1.w;
    out[i] = f4_to_h4(x0);
    out[i + RELSUM_HALF] = f4_to_h4(x1);
}

// ---------------- 128x64x64 fp16 GEMM mainloop (256 threads, ldmatrix, 3-stage) ----------------
// smem: As[3][128][72] halves, Ws[3][64][72] halves.  warps: 4 (M) x 2 (N), warp tile 32x32.
#define A_ST 9216    // halves per A stage
#define W_ST 4608    // halves per W stage
#define GEMM_SMEM ((3 * A_ST + 3 * W_ST) * 2)   // 82944 B

__device__ __forceinline__ void hgemm_mainloop(
    const __half* __restrict__ Ag, const __half* __restrict__ Wg,
    __half* __restrict__ sm, int Kloop, int lda, int ldw, float acc[2][4][4])
{
    const int tid = threadIdx.x;
    const int srow = tid >> 3;          // 0..31
    const int scol = (tid & 7) << 3;    // halves

    __half* As = sm;
    __half* Ws = sm + 3 * A_ST;

    const uint32_t asB = (uint32_t)__cvta_generic_to_shared(As);
    const uint32_t wsB = (uint32_t)__cvta_generic_to_shared(Ws);
    const uint32_t sa0 = asB + (uint32_t)(srow * 72 + scol) * 2u;
    const uint32_t sw0 = wsB + (uint32_t)(srow * 72 + scol) * 2u;

    const __half* Agp = Ag + (long long)srow * lda + scol;
    const __half* Wgp = Wg + (long long)srow * ldw + scol;

    const int KT = Kloop >> 6;

#pragma unroll
    for (int st = 0; st < 2; st++) {
        if (st < KT) {
#pragma unroll
            for (int p = 0; p < 4; p++)
                cp16(sa0 + (uint32_t)(st * A_ST + p * 32 * 72) * 2u, Agp + (long long)(p * 32) * lda + st * 64);
#pragma unroll
            for (int p = 0; p < 2; p++)
                cp16(sw0 + (uint32_t)(st * W_ST + p * 32 * 72) * 2u, Wgp + (long long)(p * 32) * ldw + st * 64);
        }
        asm volatile("cp.async.commit_group;");
    }

    const int wid = tid >> 5, lane = tid & 31;
    const int wm = wid & 3, wn = wid >> 2;
    // ldmatrix address components
    const int a_row = wm * 32 + (lane & 15);
    const int a_ko  = (lane >> 4) << 3;
    const int b_row = wn * 32 + (lane & 7) + ((lane >> 4) << 3);
    const int b_ko  = ((lane >> 3) & 1) << 3;

    const uint32_t aF = asB + (uint32_t)(a_row * 72 + a_ko) * 2u;
    const uint32_t wF = wsB + (uint32_t)(b_row * 72 + b_ko) * 2u;

    for (int kt = 0; kt < KT; kt++) {
        asm volatile("cp.async.wait_group 1;");
        __syncthreads();

        const int pf = kt + 2;
        if (pf < KT) {
            const int st = pf % 3;
#pragma unroll
            for (int p = 0; p < 4; p++)
                cp16(sa0 + (uint32_t)(st * A_ST + p * 32 * 72) * 2u, Agp + (long long)(p * 32) * lda + pf * 64);
#pragma unroll
            for (int p = 0; p < 2; p++)
                cp16(sw0 + (uint32_t)(st * W_ST + p * 32 * 72) * 2u, Wgp + (long long)(p * 32) * ldw + pf * 64);
        }
        asm volatile("cp.async.commit_group;");

        const uint32_t aS = aF + (uint32_t)((kt % 3) * A_ST) * 2u;
        const uint32_t wS = wF + (uint32_t)((kt % 3) * W_ST) * 2u;

#pragma unroll
        for (int ks = 0; ks < 4; ks++) {
            uint32_t a[2][4], b[2][4];
#pragma unroll
            for (int mt = 0; mt < 2; mt++)
                ldsm_x4(a[mt][0], a[mt][1], a[mt][2], a[mt][3],
                        aS + (uint32_t)(mt * 16 * 72 + ks * 16) * 2u);
#pragma unroll
            for (int nt2 = 0; nt2 < 2; nt2++)
                ldsm_x4(b[nt2][0], b[nt2][1], b[nt2][2], b[nt2][3],
                        wS + (uint32_t)(nt2 * 16 * 72 + ks * 16) * 2u);
#pragma unroll
            for (int mt = 0; mt < 2; mt++)
#pragma unroll
                for (int nt = 0; nt < 4; nt++) {
                    uint32_t bb[2] = { b[nt >> 1][(nt & 1) * 2], b[nt >> 1][(nt & 1) * 2 + 1] };
                    mma_f16(acc[mt][nt], a[mt], bb);
                }
        }
        // ensure compute done before stage reuse next iteration
    }
}

// ---------------- generic fp16 GEMM (z-batched): C = A @ W^T (+bias, GELU, scale) ----------------
template<int EPI, int F32OUT>
__global__ void __launch_bounds__(256, 2) hgemm_g(
    const __half* __restrict__ A, const __half* __restrict__ W,
    const float* __restrict__ bias, void* __restrict__ Cv,
    int K, int ldC, long long sA, long long sW, long long sC, float scale)
{
    extern __shared__ __half smh[];
    const int bz = blockIdx.z;
    const int m0 = blockIdx.y << 7, n0 = blockIdx.x << 6;

    float acc[2][4][4];
#pragma unroll
    for (int i = 0; i < 2; i++)
#pragma unroll
        for (int j = 0; j < 4; j++)
#pragma unroll
            for (int l = 0; l < 4; l++) acc[i][j][l] = 0.f;

    hgemm_mainloop(A + sA * bz + (long long)m0 * K,
                   W + sW * bz + (long long)n0 * K, smh, K, K, K, acc);

    const int tid = threadIdx.x, wid = tid >> 5, lane = tid & 31;
    const int wm = wid & 3, wn = wid >> 2, g = lane >> 2, t = lane & 3;

#pragma unroll
    for (int mt = 0; mt < 2; mt++) {
        const int rb = m0 + wm * 32 + mt * 16 + g;
#pragma unroll
        for (int nt = 0; nt < 4; nt++) {
            const int cb = n0 + wn * 32 + nt * 8 + 2 * t;
#pragma unroll
            for (int hf = 0; hf < 2; hf++) {
                const int m = rb + hf * 8;
                float v0 = acc[mt][nt][hf * 2 + 0];
                float v1 = acc[mt][nt][hf * 2 + 1];
                if (bias) { v0 += bias[cb]; v1 += bias[cb + 1]; }
                if (EPI == 1) {
                    v0 = 0.5f * v0 * (1.0f + erff(v0 * 0.70710678118654752f));
                    v1 = 0.5f * v1 * (1.0f + erff(v1 * 0.70710678118654752f));
                }
                v0 *= scale; v1 *= scale;
                if (F32OUT) {
                    float* C = (float*)Cv + sC * bz;
                    *(float2*)&C[(long long)m * ldC + cb] = make_float2(v0, v1);
                } else {
                    __half* C = (__half*)Cv + sC * bz;
                    __half2 h2 = __floats2half2_rn(v0, v1);
                    *(__half2*)&C[(long long)m * ldC + cb] = h2;
                }
            }
        }
    }
}

// ---------------- fused QKV projection (fp16) ----------------
__global__ void __launch_bounds__(256, 2) hqkv_kernel(
    const __half* __restrict__ h,
    const __half* __restrict__ Wq, const __half* __restrict__ Wk, const __half* __restrict__ Wv,
    const float* __restrict__ bq, const float* __restrict__ bk, const float* __restrict__ bv,
    __half* __restrict__ qo, __half* __restrict__ ko, __half* __restrict__ vto)
{
    extern __shared__ __half smh[];
    const int z = blockIdx.z;
    const __half* W   = (z == 0) ? Wq : (z == 1) ? Wk : Wv;
    const float* bias = (z == 0) ? bq : (z == 1) ? bk : bv;
    __half* out       = (z == 0) ? qo : (z == 1) ? ko : vto;
    const float scale = (z == 0) ? 0.125f : 1.0f;
    const int m0 = blockIdx.y << 7, n0 = blockIdx.x << 6;

    float acc[2][4][4];
#pragma unroll
    for (int i = 0; i < 2; i++)
#pragma unroll
        for (int j = 0; j < 4; j++)
#pragma unroll
            for (int l = 0; l < 4; l++) acc[i][j][l] = 0.f;

    hgemm_mainloop(h + (long long)m0 * DM, W + (long long)n0 * DM, smh, DM, DM, DM, acc);

    const int tid = threadIdx.x, wid = tid >> 5, lane = tid & 31;
    const int wm = wid & 3, wn = wid >> 2, g = lane >> 2, t = lane & 3;

#pragma unroll
    for (int mt = 0; mt < 2; mt++) {
        const int rb = m0 + wm * 32 + mt * 16 + g;
#pragma unroll
        for (int nt = 0; nt < 4; nt++) {
            const int cb = n0 + wn * 32 + nt * 8 + 2 * t;
#pragma unroll
            for (int hf = 0; hf < 2; hf++) {
                const int m = rb + hf * 8;
                float v0 = (acc[mt][nt][hf * 2 + 0] + bias[cb]) * scale;
                float v1 = (acc[mt][nt][hf * 2 + 1] + bias[cb + 1]) * scale;
                if (z < 2) {
                    const long long idx = ((long long)(cb >> 6) << 16) + (long long)m * 64 + (cb & 63);
                    __half2 h2 = __floats2half2_rn(v0, v1);
                    *(__half2*)&out[idx] = h2;
                } else {
                    out[(long long)cb * 1024 + m]       = __float2half(v0);
                    out[(long long)(cb + 1) * 1024 + m] = __float2half(v1);
                }
            }
        }
    }
}

// ---------------- PV split-K GEMM (fp16 probs x fp16 vt -> fp32 partials) ----------------
__global__ void __launch_bounds__(256, 2) hgemm_pv(
    const __half* __restrict__ probs, const __half* __restrict__ vt, float* __restrict__ part)
{
    extern __shared__ __half smh[];
    const int ks = blockIdx.x;           // 0..3
    const int m0 = blockIdx.y << 7;
    const int hd = blockIdx.z;

    float acc[2][4][4];
#pragma unroll
    for (int i = 0; i < 2; i++)
#pragma unroll
        for (int j = 0; j < 4; j++)
#pragma unroll
            for (int l = 0; l < 4; l++) acc[i][j][l] = 0.f;

    hgemm_mainloop(probs + (long long)hd * 1048576 + (long long)m0 * 1024 + ks * 256,
                   vt + (long long)hd * 65536 + ks * 256,
                   smh, 256, 1024, 1024, acc);

    float* C = part + (long long)ks * 786432 + hd * 64;

    const int tid = threadIdx.x, wid = tid >> 5, lane = tid & 31;
    const int wm = wid & 3, wn = wid >> 2, g = lane >> 2, t = lane & 3;

#pragma unroll
    for (int mt = 0; mt < 2; mt++) {
        const int rb = m0 + wm * 32 + mt * 16 + g;
#pragma unroll
        for (int nt = 0; nt < 4; nt++) {
            const int cb = wn * 32 + nt * 8 + 2 * t;
#pragma unroll
            for (int hf = 0; hf < 2; hf++) {
                const int m = rb + hf * 8;
                *(float2*)&C[(long long)m * 768 + cb] =
                    make_float2(acc[mt][nt][hf * 2 + 0], acc[mt][nt][hf * 2 + 1]);
            }
        }
    }
}

// ---------------- PV reduce: ctx(fp16) = sum of 4 fp32 partials ----------------
__global__ void __launch_bounds__(256) pv_reduce(
    const float4* __restrict__ part, uint2* __restrict__ ctx)
{
    const int i = blockIdx.x * 256 + threadIdx.x;   // n4 = 196608
    float4 a = part[i];
    const float4 b = part[i + 196608];
    const float4 c = part[i + 393216];
    const float4 d = part[i + 589824];
    a.x += b.x + c.x + d.x; a.y += b.y + c.y + d.y;
    a.z += b.z + c.z + d.z; a.w += b.w + c.w + d.w;
    ctx[i] = f4_to_h4(a);
}

// ---------------- fused rel-score + mask + softmax ----------------
#define SC_PITCH 1032
#define RS_QPITCH 72
#define RS_RPITCH 72
#define RS_CHUNK_H (128 * RS_RPITCH)
#define RS_NBUF 3
#define RS_SMEM 111232

__global__ void __launch_bounds__(256) rel_softmax_kernel(
    const __half* __restrict__ rel, const __half* __restrict__ qb,
    const float* __restrict__ scores, __half* __restrict__ probs,
    const float* __restrict__ mask)
{
    extern __shared__ char smc[];
    __half* qs      = (__half*)smc;
    float*  sscores = (float*)(smc + 2304);
    float*  smask   = (float*)(smc + 51840);
    __half* relb    = (__half*)(smc + 55936);

    const int s = blockIdx.x;
    const int tid = threadIdx.x;
    const int wid = tid >> 5, lane = tid & 31;
    const int g = lane >> 2, t = lane & 3;

    // ---- group 0: prefetch 12 fp32 score rows (padded pitch) + mask ----
    {
        const uint32_t ss_s = (uint32_t)__cvta_generic_to_shared(sscores);
#pragma unroll
        for (int p = 0; p < 12; p++) {
            const int idx = tid + 256 * p;
            const int n = idx >> 8, c4 = (idx & 255) << 2;
            cp16(ss_s + (uint32_t)(n * SC_PITCH + c4) * 4u,
                 scores + (((long long)n << 10) + s) * 1024 + c4);
        }
        cp16((uint32_t)__cvta_generic_to_shared(smask) + (uint32_t)(tid << 4),
             mask + (tid << 2));
        asm volatile("cp.async.commit_group;");
    }

    for (int i = tid; i < 16 * 64; i += 256) {
        const int r = i >> 6, c = i & 63;
        qs[r * RS_QPITCH + c] = (r < 12) ? qb[((long long)r << 16) + (s << 6) + c] : __float2half(0.f);
    }

    const __half* relS = rel + ((long long)s << 16);
    const uint32_t relb_s = (uint32_t)__cvta_generic_to_shared(relb);

#pragma unroll
    for (int ch = 0; ch < RS_NBUF - 1; ch++) {
        const uint32_t dstb = relb_s + (uint32_t)(ch * RS_CHUNK_H) * 2u;
        const __half* src = relS + (long long)ch * 128 * 64;
#pragma unroll
        for (int p = 0; p < 4; p++) {
            const int idx = tid + 256 * p;
            const int r = idx >> 3, c8 = (idx & 7) << 3;
            cp16(dstb + (uint32_t)(r * RS_RPITCH + c8) * 2u, src + (long long)r * 64 + c8);
        }
        asm volatile("cp.async.commit_group;");
    }

    __syncthreads();

    uint32_t afrag[4][4];
#pragma unroll
    for (int ks = 0; ks < 4; ks++) {
        afrag[ks][0] = *(const uint32_t*)&qs[g * RS_QPITCH + ks * 16 + 2 * t];
        afrag[ks][1] = *(const uint32_t*)&qs[(g + 8) * RS_QPITCH + ks * 16 + 2 * t];
        afrag[ks][2] = *(const uint32_t*)&qs[g * RS_QPITCH + ks * 16 + 2 * t + 8];
        afrag[ks][3] = *(const uint32_t*)&qs[(g + 8) * RS_QPITCH + ks * 16 + 2 * t + 8];
    }

    for (int ch = 0; ch < 8; ch++) {
        asm volatile("cp.async.wait_group 1;");
        __syncthreads();

        const int pf = ch + RS_NBUF - 1;
        if (pf < 8) {
            const uint32_t dstb = relb_s + (uint32_t)((pf % RS_NBUF) * RS_CHUNK_H) * 2u;
            const __half* src = relS + (long long)pf * 128 * 64;
#pragma unroll
            for (int p = 0; p < 4; p++) {
                const int idx = tid + 256 * p;
                const int r = idx >> 3, c8 = (idx & 7) << 3;
                cp16(dstb + (uint32_t)(r * RS_RPITCH + c8) * 2u, src + (long long)r * 64 + c8);
            }
        }
        asm volatile("cp.async.commit_group;");

        const __half* rb = relb + (ch % RS_NBUF) * RS_CHUNK_H;
#pragma unroll
        for (int nt2 = 0; nt2 < 2; nt2++) {
            const int lrb = (wid * 2 + nt2) * 8;
            const int lr = lrb + g;
            float c[4] = {0.f, 0.f, 0.f, 0.f};
#pragma unroll
            for (int ks = 0; ks < 4; ks++) {
                uint32_t bb[2];
                bb[0] = *(const uint32_t*)&rb[lr * RS_RPITCH + ks * 16 + 2 * t];
                bb[1] = *(const uint32_t*)&rb[lr * RS_RPITCH + ks * 16 + 2 * t + 8];
                mma_f16(c, afrag[ks], bb);
            }
            const int kc = ch * 128 + lrb + 2 * t;
            float2 o0 = *(float2*)&sscores[g * SC_PITCH + kc];
            o0.x += c[0]; o0.y += c[1];
            *(float2*)&sscores[g * SC_PITCH + kc] = o0;
            if (g < 4) {
                float2 o1 = *(float2*)&sscores[(g + 8) * SC_PITCH + kc];
                o1.x += c[2]; o1.y += c[3];
                *(float2*)&sscores[(g + 8) * SC_PITCH + kc] = o1;
            }
        }
    }
    __syncthreads();

    // ---- warp-parallel softmax; write fp16 probs ----
#pragma unroll
    for (int hh = 0; hh < 2; hh++) {
        if (hh == 1 && wid >= 4) break;
        const int n = hh ? (8 + wid) : wid;

        float4 v[8];
        float m = -1e30f;
#pragma unroll
        for (int j = 0; j < 8; j++) {
            const int c4 = (lane + 32 * j) << 2;
            float4 a = *(const float4*)&sscores[n * SC_PITCH + c4];
            const float4 mk = *(const float4*)&smask[c4];
            a.x += mk.x; a.y += mk.y; a.z += mk.z; a.w += mk.w;
            v[j] = a;
            m = fmaxf(m, fmaxf(fmaxf(a.x, a.y), fmaxf(a.z, a.w)));
        }
        m = warpRedMax(m);

        float sum = 0.f;
#pragma unroll
        for (int j = 0; j < 8; j++) {
            v[j].x = __expf(v[j].x - m); v[j].y = __expf(v[j].y - m);
            v[j].z = __expf(v[j].z - m); v[j].w = __expf(v[j].w - m);
            sum += v[j].x + v[j].y + v[j].z + v[j].w;
        }
        sum = warpRedSum(sum);
        const float inv = 1.0f / sum;

        __half* prow = probs + (((long long)n << 10) + s) * 1024;
#pragma unroll
        for (int j = 0; j < 8; j++) {
            const int c4 = (lane + 32 * j) << 2;
            __half2 p0 = __floats2half2_rn(v[j].x * inv, v[j].y * inv);
            __half2 p1 = __floats2half2_rn(v[j].z * inv, v[j].w * inv);
            uint2 o; o.x = *(uint32_t*)&p0; o.y = *(uint32_t*)&p1;
            *(uint2*)&prow[c4] = o;
        }
    }
}

// ---------------- residual + LayerNorm (fp16 in, fp16 or fp32 out) ----------------
template<int F32OUT>
__global__ void __launch_bounds__(256) ln_kernel(
    const __half* __restrict__ x, const __half* __restrict__ res,
    const float* __restrict__ g, const float* __restrict__ b, void* __restrict__ outv)
{
    const int s = blockIdx.x;
    const int tid = threadIdx.x;
    const int lane = tid & 31, wid = tid >> 5;
    __shared__ float red[8];

    float v[3];
    float lsum = 0.f;
#pragma unroll
    for (int i = 0; i < 3; i++) {
        const int idx = tid + i * 256;
        v[i] = __half2float(x[s * 768 + idx]) + __half2float(res[s * 768 + idx]);
        lsum += v[i];
    }
    lsum = warpRedSum(lsum);
    if (lane == 0) red[wid] = lsum;
    __syncthreads();
    float tot = 0.f;
#pragma unroll
    for (int i = 0; i < 8; i++) tot += red[i];
    const float mu = tot * (1.0f / 768.0f);
    __syncthreads();

    float ls2 = 0.f;
#pragma unroll
    for (int i = 0; i < 3; i++) { const float d = v[i] - mu; ls2 += d * d; }
    ls2 = warpRedSum(ls2);
    if (lane == 0) red[wid] = ls2;
    __syncthreads();
    float tot2 = 0.f;
#pragma unroll
    for (int i = 0; i < 8; i++) tot2 += red[i];
    const float rs = rsqrtf(tot2 * (1.0f / 768.0f) + 1e-12f);

#pragma unroll
    for (int i = 0; i < 3; i++) {
        const int idx = tid + i * 256;
        const float o = (v[i] - mu) * rs * g[idx] + b[idx];
        if (F32OUT) ((float*)outv)[s * 768 + idx] = o;
        else        ((__half*)outv)[s * 768 + idx] = __float2half(o);
    }
}

// ---------------- launcher ----------------
extern "C" void kernel_launch(void* const* d_in, const int* in_sizes, int n_in,
                              void* d_out, int out_size)
{
    const float* hid  = (const float*)d_in[0];
    const float* mask = (const float*)d_in[1];
    const float* rel  = (const float*)d_in[2];
    const float* rel2 = (const float*)d_in[3];
    const float* rela = (const float*)d_in[4];
    const float* Wq = (const float*)d_in[5];   const float* bq = (const float*)d_in[6];
    const float* Wk = (const float*)d_in[7];   const float* bk = (const float*)d_in[8];
    const float* Wv = (const float*)d_in[9];   const float* bv = (const float*)d_in[10];
    const float* Wo = (const float*)d_in[11];  const float* bo = (const float*)d_in[12];
    const float* g1 = (const float*)d_in[13];  const float* b1 = (const float*)d_in[14];
    const float* Wi = (const float*)d_in[15];  const float* bi = (const float*)d_in[16];
    const float* W2 = (const float*)d_in[17];  const float* b2 = (const float*)d_in[18];
    const float* g2 = (const float*)d_in[19];  const float* b2g = (const float*)d_in[20];

    __half *relsum, *probs, *h16, *hbuf, *q, *k, *vt, *ctx, *proj, *attn, *inter, *ffn;
    __half *wq16, *wk16, *wv16, *wo16, *wi16, *w216;
    float *scores, *part;
    cudaGetSymbolAddress((void**)&relsum, g_relsum);
    cudaGetSymbolAddress((void**)&scores, g_scores);
    cudaGetSymbolAddress((void**)&probs, g_probs);
    cudaGetSymbolAddress((void**)&part, g_part);
    cudaGetSymbolAddress((void**)&h16, g_h16);
    cudaGetSymbolAddress((void**)&hbuf, g_hbuf);
    cudaGetSymbolAddress((void**)&q, g_q);
    cudaGetSymbolAddress((void**)&k, g_k);
    cudaGetSymbolAddress((void**)&vt, g_vt);
    cudaGetSymbolAddress((void**)&ctx, g_ctx);
    cudaGetSymbolAddress((void**)&proj, g_proj);
    cudaGetSymbolAddress((void**)&attn, g_attn);
    cudaGetSymbolAddress((void**)&inter, g_inter);
    cudaGetSymbolAddress((void**)&ffn, g_ffn);
    cudaGetSymbolAddress((void**)&wq16, g_wq16);
    cudaGetSymbolAddress((void**)&wk16, g_wk16);
    cudaGetSymbolAddress((void**)&wv16, g_wv16);
    cudaGetSymbolAddress((void**)&wo16, g_wo16);
    cudaGetSymbolAddress((void**)&wi16, g_wi16);
    cudaGetSymbolAddress((void**)&w216, g_w216);

    cudaFuncSetAttribute(hgemm_g<0, 0>, cudaFuncAttributeMaxDynamicSharedMemorySize, GEMM_SMEM);
    cudaFuncSetAttribute(hgemm_g<0, 1>, cudaFuncAttributeMaxDynamicSharedMemorySize, GEMM_SMEM);
    cudaFuncSetAttribute(hgemm_g<1, 0>, cudaFuncAttributeMaxDynamicSharedMemorySize, GEMM_SMEM);
    cudaFuncSetAttribute(hqkv_kernel, cudaFuncAttributeMaxDynamicSharedMemorySize, GEMM_SMEM);
    cudaFuncSetAttribute(hgemm_pv, cudaFuncAttributeMaxDynamicSharedMemorySize, GEMM_SMEM);
    cudaFuncSetAttribute(rel_softmax_kernel, cudaFuncAttributeMaxDynamicSharedMemorySize, RS_SMEM);

    // one-shot fp32 -> fp16 conversions (3 launches)
    f2h1_kernel<<<SEQ * DM / 4 / 256, 256>>>((const float4*)hid, (uint2*)h16);
    f2h4_kernel<<<dim3(NLAYERS * DM * DM / 4 / 256, 1, 4), 256>>>(
        (const float4*)Wq, (const float4*)Wk, (const float4*)Wv, (const float4*)Wo,
        (uint2*)wq16, (uint2*)wk16, (uint2*)wv16, (uint2*)wo16);
    f2h2_kernel<<<dim3(NLAYERS * DFF * DM / 4 / 256, 1, 2), 256>>>(
        (const float4*)Wi, (const float4*)W2, (uint2*)wi16, (uint2*)w216);

    relsum_kernel<<<32768, 256>>>((const float4*)rel, (const float4*)rel2,
                                  (const float4*)rela, (uint2*)relsum);

    const __half* h = h16;
    for (int l = 0; l < NLAYERS; l++) {
        const size_t wofs  = (size_t)l * DM * DM;
        const size_t wiofs = (size_t)l * DFF * DM;

        // fused Q/K/V projections
        hqkv_kernel<<<dim3(12, 8, 3), 256, GEMM_SMEM>>>(
            h, wq16 + wofs, wk16 + wofs, wv16 + wofs,
            bq + l * 768, bk + l * 768, bv + l * 768, q, k, vt);

        // logits = q @ k^T (fp32 out)
        hgemm_g<0, 1><<<dim3(16, 8, 12), 256, GEMM_SMEM>>>(
            q, k, nullptr, scores, 64, 1024, 65536LL, 65536LL, 1048576LL, 1.0f);

        // + rel term + mask + softmax -> fp16 probs
        rel_softmax_kernel<<<1024, 256, RS_SMEM>>>(relsum, q, scores, probs, mask);

        // ctx = probs @ v  (split-K=4)
        hgemm_pv<<<dim3(4, 8, 12), 256, GEMM_SMEM>>>(probs, vt, part);
        pv_reduce<<<768, 256>>>((const float4*)part, (uint2*)ctx);

        // output projection + residual LN
        hgemm_g<0, 0><<<dim3(12, 8, 1), 256, GEMM_SMEM>>>(
            ctx, wo16 + wofs, bo + l * 768, proj, 768, 768, 0, 0, 0, 1.0f);
        ln_kernel<0><<<1024, 256>>>(proj, h, g1 + l * 768, b1 + l * 768, attn);

        // FFN
        hgemm_g<1, 0><<<dim3(48, 8, 1), 256, GEMM_SMEM>>>(
            attn, wi16 + wiofs, bi + l * 3072, inter, 768, 3072, 0, 0, 0, 1.0f);
        hgemm_g<0, 0><<<dim3(12, 8, 1), 256, GEMM_SMEM>>>(
            inter, w216 + wiofs, b2 + l * 768, ffn, 3072, 768, 0, 0, 0, 1.0f);

        if (l == NLAYERS - 1) {
            ln_kernel<1><<<1024, 256>>>(ffn, attn, g2 + l * 768, b2g + l * 768, d_out);
        } else {
            ln_kernel<0><<<1024, 256>>>(ffn, attn, g2 + l * 768, b2g + l * 768, hbuf);
        }
        h = hbuf;
    }
}

// round 9
// speedup vs baseline: 5.7479x; 1.0522x over previous
#include <cuda_runtime.h>
#include <cuda_fp16.h>
#include <math.h>
#include <stdint.h>

#define SEQ 1024
#define DM  768
#define NHEAD 12
#define HDIM 64
#define NLAYERS 4
#define DFF 3072

// ---------------- scratch (static device memory; no runtime allocs) ----------------
__device__ __half g_relsum[(size_t)SEQ * SEQ * HDIM];         // 128 MB (fp16)
__device__ float  g_scores[(size_t)NHEAD * SEQ * SEQ];        // 48 MB (fp32 logits)
__device__ __half g_probs[(size_t)NHEAD * SEQ * SEQ];         // 24 MB (fp16 probs)
__device__ float  g_part[4 * SEQ * DM];                       // split-K partials
__device__ __half g_h16[SEQ * DM];
__device__ __half g_hbuf[SEQ * DM];
__device__ __half g_q[NHEAD * SEQ * HDIM];
__device__ __half g_k[NHEAD * SEQ * HDIM];
__device__ __half g_vt[NHEAD * HDIM * SEQ];
__device__ __half g_ctx[SEQ * DM];
__device__ __half g_attn[SEQ * DM];
__device__ __half g_inter[SEQ * DFF];
// fp16 weights (converted once per launch)
__device__ __half g_wq16[NLAYERS * DM * DM];
__device__ __half g_wk16[NLAYERS * DM * DM];
__device__ __half g_wv16[NLAYERS * DM * DM];
__device__ __half g_wo16[NLAYERS * DM * DM];
__device__ __half g_wi16[NLAYERS * DFF * DM];
__device__ __half g_w216[NLAYERS * DM * DFF];

// ---------------- helpers ----------------
__device__ __forceinline__ float warpRedMax(float v) {
#pragma unroll
    for (int o = 16; o > 0; o >>= 1) v = fmaxf(v, __shfl_xor_sync(0xffffffffu, v, o));
    return v;
}
__device__ __forceinline__ float warpRedSum(float v) {
#pragma unroll
    for (int o = 16; o > 0; o >>= 1) v += __shfl_xor_sync(0xffffffffu, v, o);
    return v;
}
__device__ __forceinline__ void cp16(uint32_t dst, const void* src) {
    asm volatile("cp.async.cg.shared.global [%0], [%1], 16;" :: "r"(dst), "l"(src));
}
__device__ __forceinline__ void mma_f16(float* c, const uint32_t* a, const uint32_t* b) {
    asm volatile(
        "mma.sync.aligned.m16n8k16.row.col.f32.f16.f16.f32 "
        "{%0,%1,%2,%3}, {%4,%5,%6,%7}, {%8,%9}, {%0,%1,%2,%3};"
        : "+f"(c[0]), "+f"(c[1]), "+f"(c[2]), "+f"(c[3])
        : "r"(a[0]), "r"(a[1]), "r"(a[2]), "r"(a[3]), "r"(b[0]), "r"(b[1]));
}
__device__ __forceinline__ void ldsm_x4(uint32_t& r0, uint32_t& r1, uint32_t& r2, uint32_t& r3,
                                        uint32_t addr) {
    asm volatile("ldmatrix.sync.aligned.m8n8.x4.shared.b16 {%0,%1,%2,%3}, [%4];"
                 : "=r"(r0), "=r"(r1), "=r"(r2), "=r"(r3) : "r"(addr));
}
__device__ __forceinline__ uint2 f4_to_h4(float4 x) {
    __half2 h0 = __floats2half2_rn(x.x, x.y);
    __half2 h1 = __floats2half2_rn(x.z, x.w);
    uint2 o; o.x = *(uint32_t*)&h0; o.y = *(uint32_t*)&h1;
    return o;
}

// ---------------- one-shot fp32 -> fp16 conversions ----------------
__global__ void __launch_bounds__(256) f2h1_kernel(
    const float4* __restrict__ s, uint2* __restrict__ d)
{
    const int i = blockIdx.x * 256 + threadIdx.x;
    d[i] = f4_to_h4(s[i]);
}
__global__ void __launch_bounds__(256) f2h4_kernel(
    const float4* __restrict__ s0, const float4* __restrict__ s1,
    const float4* __restrict__ s2, const float4* __restrict__ s3,
    uint2* __restrict__ d0, uint2* __restrict__ d1,
    uint2* __restrict__ d2, uint2* __restrict__ d3)
{
    const int i = blockIdx.x * 256 + threadIdx.x;
    const int z = blockIdx.z;
    const float4* s = (z == 0) ? s0 : (z == 1) ? s1 : (z == 2) ? s2 : s3;
    uint2* d        = (z == 0) ? d0 : (z == 1) ? d1 : (z == 2) ? d2 : d3;
    d[i] = f4_to_h4(s[i]);
}
__global__ void __launch_bounds__(256) f2h2_kernel(
    const float4* __restrict__ s0, const float4* __restrict__ s1,
    uint2* __restrict__ d0, uint2* __restrict__ d1)
{
    const int i = blockIdx.x * 256 + threadIdx.x;
    const float4* s = blockIdx.z ? s1 : s0;
    uint2* d        = blockIdx.z ? d1 : d0;
    d[i] = f4_to_h4(s[i]);
}

// ---------------- relsum = rel_pos + rel_2d_pos + rel_2d_angle (fp16 out, one-shot) ----------------
#define RELSUM_HALF 8388608
__global__ void __launch_bounds__(256) relsum_kernel(
    const float4* __restrict__ a, const float4* __restrict__ b,
    const float4* __restrict__ c, uint2* __restrict__ out)
{
    const int i = blockIdx.x * 256 + threadIdx.x;
    float4 x0 = a[i], y0 = b[i], z0 = c[i];
    float4 x1 = a[i + RELSUM_HALF], y1 = b[i + RELSUM_HALF], z1 = c[i + RELSUM_HALF];
    x0.x += y0.x + z0.x; x0.y += y0.y + z0.y; x0.z += y0.z + z0.z; x0.w += y0.w + z0.w;
    x1.x += y1.x + z1.x; x1.y += y1.y + z1.y; x1.z += y1.z + z1.z; x1.w += y1.w + z1.w;
    out[i] = f4_to_h4(x0);
    out[i + RELSUM_HALF] = f4_to_h4(x1);
}

// ---------------- 128x64 fp16 GEMM mainloop (256 threads, ldmatrix, 3-stage) ----------------
#define A_ST 9216    // halves per A stage
#define W_ST 4608    // halves per W stage
#define GEMM_SMEM ((3 * A_ST + 3 * W_ST) * 2)   // 82944 B

__device__ __forceinline__ void hgemm_mainloop(
    const __half* __restrict__ Ag, const __half* __restrict__ Wg,
    __half* __restrict__ sm, int Kloop, int lda, int ldw, float acc[2][4][4])
{
    const int tid = threadIdx.x;
    const int srow = tid >> 3;
    const int scol = (tid & 7) << 3;

    __half* As = sm;
    __half* Ws = sm + 3 * A_ST;

    const uint32_t asB = (uint32_t)__cvta_generic_to_shared(As);
    const uint32_t wsB = (uint32_t)__cvta_generic_to_shared(Ws);
    const uint32_t sa0 = asB + (uint32_t)(srow * 72 + scol) * 2u;
    const uint32_t sw0 = wsB + (uint32_t)(srow * 72 + scol) * 2u;

    const __half* Agp = Ag + (long long)srow * lda + scol;
    const __half* Wgp = Wg + (long long)srow * ldw + scol;

    const int KT = Kloop >> 6;

#pragma unroll
    for (int st = 0; st < 2; st++) {
        if (st < KT) {
#pragma unroll
            for (int p = 0; p < 4; p++)
                cp16(sa0 + (uint32_t)(st * A_ST + p * 32 * 72) * 2u, Agp + (long long)(p * 32) * lda + st * 64);
#pragma unroll
            for (int p = 0; p < 2; p++)
                cp16(sw0 + (uint32_t)(st * W_ST + p * 32 * 72) * 2u, Wgp + (long long)(p * 32) * ldw + st * 64);
        }
        asm volatile("cp.async.commit_group;");
    }

    const int wid = tid >> 5, lane = tid & 31;
    const int wm = wid & 3, wn = wid >> 2;
    const int a_row = wm * 32 + (lane & 15);
    const int a_ko  = (lane >> 4) << 3;
    const int b_row = wn * 32 + (lane & 7) + ((lane >> 4) << 3);
    const int b_ko  = ((lane >> 3) & 1) << 3;

    const uint32_t aF = asB + (uint32_t)(a_row * 72 + a_ko) * 2u;
    const uint32_t wF = wsB + (uint32_t)(b_row * 72 + b_ko) * 2u;

    for (int kt = 0; kt < KT; kt++) {
        asm volatile("cp.async.wait_group 1;");
        __syncthreads();

        const int pf = kt + 2;
        if (pf < KT) {
            const int st = pf % 3;
#pragma unroll
            for (int p = 0; p < 4; p++)
                cp16(sa0 + (uint32_t)(st * A_ST + p * 32 * 72) * 2u, Agp + (long long)(p * 32) * lda + pf * 64);
#pragma unroll
            for (int p = 0; p < 2; p++)
                cp16(sw0 + (uint32_t)(st * W_ST + p * 32 * 72) * 2u, Wgp + (long long)(p * 32) * ldw + pf * 64);
        }
        asm volatile("cp.async.commit_group;");

        const uint32_t aS = aF + (uint32_t)((kt % 3) * A_ST) * 2u;
        const uint32_t wS = wF + (uint32_t)((kt % 3) * W_ST) * 2u;

#pragma unroll
        for (int ks = 0; ks < 4; ks++) {
            uint32_t a[2][4], b[2][4];
#pragma unroll
            for (int mt = 0; mt < 2; mt++)
                ldsm_x4(a[mt][0], a[mt][1], a[mt][2], a[mt][3],
                        aS + (uint32_t)(mt * 16 * 72 + ks * 16) * 2u);
#pragma unroll
            for (int nt2 = 0; nt2 < 2; nt2++)
                ldsm_x4(b[nt2][0], b[nt2][1], b[nt2][2], b[nt2][3],
                        wS + (uint32_t)(nt2 * 16 * 72 + ks * 16) * 2u);
#pragma unroll
            for (int mt = 0; mt < 2; mt++)
#pragma unroll
                for (int nt = 0; nt < 4; nt++) {
                    uint32_t bb[2] = { b[nt >> 1][(nt & 1) * 2], b[nt >> 1][(nt & 1) * 2 + 1] };
                    mma_f16(acc[mt][nt], a[mt], bb);
                }
        }
    }
}

// ---------------- generic fp16 GEMM (z-batched): C = A @ W^T (+bias, GELU, scale) ----------------
template<int EPI, int F32OUT>
__global__ void __launch_bounds__(256, 2) hgemm_g(
    const __half* __restrict__ A, const __half* __restrict__ W,
    const float* __restrict__ bias, void* __restrict__ Cv,
    int K, int ldC, long long sA, long long sW, long long sC, float scale)
{
    extern __shared__ __half smh[];
    const int bz = blockIdx.z;
    const int m0 = blockIdx.y << 7, n0 = blockIdx.x << 6;

    float acc[2][4][4];
#pragma unroll
    for (int i = 0; i < 2; i++)
#pragma unroll
        for (int j = 0; j < 4; j++)
#pragma unroll
            for (int l = 0; l < 4; l++) acc[i][j][l] = 0.f;

    hgemm_mainloop(A + sA * bz + (long long)m0 * K,
                   W + sW * bz + (long long)n0 * K, smh, K, K, K, acc);

    const int tid = threadIdx.x, wid = tid >> 5, lane = tid & 31;
    const int wm = wid & 3, wn = wid >> 2, g = lane >> 2, t = lane & 3;

#pragma unroll
    for (int mt = 0; mt < 2; mt++) {
        const int rb = m0 + wm * 32 + mt * 16 + g;
#pragma unroll
        for (int nt = 0; nt < 4; nt++) {
            const int cb = n0 + wn * 32 + nt * 8 + 2 * t;
#pragma unroll
            for (int hf = 0; hf < 2; hf++) {
                const int m = rb + hf * 8;
                float v0 = acc[mt][nt][hf * 2 + 0];
                float v1 = acc[mt][nt][hf * 2 + 1];
                if (bias) { v0 += bias[cb]; v1 += bias[cb + 1]; }
                if (EPI == 1) {
                    v0 = 0.5f * v0 * (1.0f + erff(v0 * 0.70710678118654752f));
                    v1 = 0.5f * v1 * (1.0f + erff(v1 * 0.70710678118654752f));
                }
                v0 *= scale; v1 *= scale;
                if (F32OUT) {
                    float* C = (float*)Cv + sC * bz;
                    *(float2*)&C[(long long)m * ldC + cb] = make_float2(v0, v1);
                } else {
                    __half* C = (__half*)Cv + sC * bz;
                    __half2 h2 = __floats2half2_rn(v0, v1);
                    *(__half2*)&C[(long long)m * ldC + cb] = h2;
                }
            }
        }
    }
}

// ---------------- split-K GEMM: part[ks] = A[:, ks*Ksplit:+Ksplit] @ W[:, same]^T ----------------
__global__ void __launch_bounds__(256, 2) hgemm_sk(
    const __half* __restrict__ A, const __half* __restrict__ W,
    float* __restrict__ part, int Kfull, int Ksplit)
{
    extern __shared__ __half smh[];
    const int ks = blockIdx.z;
    const int m0 = blockIdx.y << 7, n0 = blockIdx.x << 6;

    float acc[2][4][4];
#pragma unroll
    for (int i = 0; i < 2; i++)
#pragma unroll
        for (int j = 0; j < 4; j++)
#pragma unroll
            for (int l = 0; l < 4; l++) acc[i][j][l] = 0.f;

    hgemm_mainloop(A + (long long)m0 * Kfull + (long long)ks * Ksplit,
                   W + (long long)n0 * Kfull + (long long)ks * Ksplit,
                   smh, Ksplit, Kfull, Kfull, acc);

    float* C = part + (long long)ks * (SEQ * DM);

    const int tid = threadIdx.x, wid = tid >> 5, lane = tid & 31;
    const int wm = wid & 3, wn = wid >> 2, g = lane >> 2, t = lane & 3;

#pragma unroll
    for (int mt = 0; mt < 2; mt++) {
        const int rb = m0 + wm * 32 + mt * 16 + g;
#pragma unroll
        for (int nt = 0; nt < 4; nt++) {
            const int cb = n0 + wn * 32 + nt * 8 + 2 * t;
#pragma unroll
            for (int hf = 0; hf < 2; hf++) {
                const int m = rb + hf * 8;
                *(float2*)&C[(long long)m * DM + cb] =
                    make_float2(acc[mt][nt][hf * 2 + 0], acc[mt][nt][hf * 2 + 1]);
            }
        }
    }
}

// ---------------- fused QKV projection (fp16) ----------------
__global__ void __launch_bounds__(256, 2) hqkv_kernel(
    const __half* __restrict__ h,
    const __half* __restrict__ Wq, const __half* __restrict__ Wk, const __half* __restrict__ Wv,
    const float* __restrict__ bq, const float* __restrict__ bk, const float* __restrict__ bv,
    __half* __restrict__ qo, __half* __restrict__ ko, __half* __restrict__ vto)
{
    extern __shared__ __half smh[];
    const int z = blockIdx.z;
    const __half* W   = (z == 0) ? Wq : (z == 1) ? Wk : Wv;
    const float* bias = (z == 0) ? bq : (z == 1) ? bk : bv;
    __half* out       = (z == 0) ? qo : (z == 1) ? ko : vto;
    const float scale = (z == 0) ? 0.125f : 1.0f;
    const int m0 = blockIdx.y << 7, n0 = blockIdx.x << 6;

    float acc[2][4][4];
#pragma unroll
    for (int i = 0; i < 2; i++)
#pragma unroll
        for (int j = 0; j < 4; j++)
#pragma unroll
            for (int l = 0; l < 4; l++) acc[i][j][l] = 0.f;

    hgemm_mainloop(h + (long long)m0 * DM, W + (long long)n0 * DM, smh, DM, DM, DM, acc);

    const int tid = threadIdx.x, wid = tid >> 5, lane = tid & 31;
    const int wm = wid & 3, wn = wid >> 2, g = lane >> 2, t = lane & 3;

#pragma unroll
    for (int mt = 0; mt < 2; mt++) {
        const int rb = m0 + wm * 32 + mt * 16 + g;
#pragma unroll
        for (int nt = 0; nt < 4; nt++) {
            const int cb = n0 + wn * 32 + nt * 8 + 2 * t;
#pragma unroll
            for (int hf = 0; hf < 2; hf++) {
                const int m = rb + hf * 8;
                float v0 = (acc[mt][nt][hf * 2 + 0] + bias[cb]) * scale;
                float v1 = (acc[mt][nt][hf * 2 + 1] + bias[cb + 1]) * scale;
                if (z < 2) {
                    const long long idx = ((long long)(cb >> 6) << 16) + (long long)m * 64 + (cb & 63);
                    __half2 h2 = __floats2half2_rn(v0, v1);
                    *(__half2*)&out[idx] = h2;
                } else {
                    out[(long long)cb * 1024 + m]       = __float2half(v0);
                    out[(long long)(cb + 1) * 1024 + m] = __float2half(v1);
                }
            }
        }
    }
}

// ---------------- PV split-K GEMM (fp16 probs x fp16 vt -> fp32 partials) ----------------
__global__ void __launch_bounds__(256, 2) hgemm_pv(
    const __half* __restrict__ probs, const __half* __restrict__ vt, float* __restrict__ part)
{
    extern __shared__ __half smh[];
    const int ks = blockIdx.x;
    const int m0 = blockIdx.y << 7;
    const int hd = blockIdx.z;

    float acc[2][4][4];
#pragma unroll
    for (int i = 0; i < 2; i++)
#pragma unroll
        for (int j = 0; j < 4; j++)
#pragma unroll
            for (int l = 0; l < 4; l++) acc[i][j][l] = 0.f;

    hgemm_mainloop(probs + (long long)hd * 1048576 + (long long)m0 * 1024 + ks * 256,
                   vt + (long long)hd * 65536 + ks * 256,
                   smh, 256, 1024, 1024, acc);

    float* C = part + (long long)ks * 786432 + hd * 64;

    const int tid = threadIdx.x, wid = tid >> 5, lane = tid & 31;
    const int wm = wid & 3, wn = wid >> 2, g = lane >> 2, t = lane & 3;

#pragma unroll
    for (int mt = 0; mt < 2; mt++) {
        const int rb = m0 + wm * 32 + mt * 16 + g;
#pragma unroll
        for (int nt = 0; nt < 4; nt++) {
            const int cb = wn * 32 + nt * 8 + 2 * t;
#pragma unroll
            for (int hf = 0; hf < 2; hf++) {
                const int m = rb + hf * 8;
                *(float2*)&C[(long long)m * 768 + cb] =
                    make_float2(acc[mt][nt][hf * 2 + 0], acc[mt][nt][hf * 2 + 1]);
            }
        }
    }
}

// ---------------- PV reduce: ctx(fp16) = sum of 4 fp32 partials ----------------
__global__ void __launch_bounds__(256) pv_reduce(
    const float4* __restrict__ part, uint2* __restrict__ ctx)
{
    const int i = blockIdx.x * 256 + threadIdx.x;
    float4 a = part[i];
    const float4 b = part[i + 196608];
    const float4 c = part[i + 393216];
    const float4 d = part[i + 589824];
    a.x += b.x + c.x + d.x; a.y += b.y + c.y + d.y;
    a.z += b.z + c.z + d.z; a.w += b.w + c.w + d.w;
    ctx[i] = f4_to_h4(a);
}

// ---------------- fused rel-score + mask + softmax (64-row chunks, 6-deep pipeline) ----------------
#define SC_PITCH 1032
#define RS_QPITCH 72
#define RS_RPITCH 72
#define RS_CROWS 64
#define RS_CHUNK_H (RS_CROWS * RS_RPITCH)   // 4608 halves
#define RS_NBUF 6
#define RS_NCHUNK 16
// layout (bytes):
//   qs     fp16 [16][72]       @ 0      (2304)
//   sscore fp32 [12][1032]     @ 2304   (49536)
//   smask  fp32 [1024]         @ 51840  (4096)
//   relb   fp16 [6][64][72]    @ 55936  (55296)
#define RS_SMEM 111232

__global__ void __launch_bounds__(256) rel_softmax_kernel(
    const __half* __restrict__ rel, const __half* __restrict__ qb,
    const float* __restrict__ scores, __half* __restrict__ probs,
    const float* __restrict__ mask)
{
    extern __shared__ char smc[];
    __half* qs      = (__half*)smc;
    float*  sscores = (float*)(smc + 2304);
    float*  smask   = (float*)(smc + 51840);
    __half* relb    = (__half*)(smc + 55936);

    const int s = blockIdx.x;
    const int tid = threadIdx.x;
    const int wid = tid >> 5, lane = tid & 31;
    const int g = lane >> 2, t = lane & 3;

    // ---- group 0: prefetch 12 fp32 score rows (padded pitch) + mask ----
    {
        const uint32_t ss_s = (uint32_t)__cvta_generic_to_shared(sscores);
#pragma unroll
        for (int p = 0; p < 12; p++) {
            const int idx = tid + 256 * p;
            const int n = idx >> 8, c4 = (idx & 255) << 2;
            cp16(ss_s + (uint32_t)(n * SC_PITCH + c4) * 4u,
                 scores + (((long long)n << 10) + s) * 1024 + c4);
        }
        cp16((uint32_t)__cvta_generic_to_shared(smask) + (uint32_t)(tid << 4),
             mask + (tid << 2));
        asm volatile("cp.async.commit_group;");
    }

    for (int i = tid; i < 16 * 64; i += 256) {
        const int r = i >> 6, c = i & 63;
        qs[r * RS_QPITCH + c] = (r < 12) ? qb[((long long)r << 16) + (s << 6) + c] : __float2half(0.f);
    }

    const __half* relS = rel + ((long long)s << 16);
    const uint32_t relb_s = (uint32_t)__cvta_generic_to_shared(relb);

    // prologue: chunks 0..4 -> buffers 0..4
#pragma unroll
    for (int ch = 0; ch < RS_NBUF - 1; ch++) {
        const uint32_t dstb = relb_s + (uint32_t)(ch * RS_CHUNK_H) * 2u;
        const __half* src = relS + (long long)ch * RS_CROWS * 64;
#pragma unroll
        for (int p = 0; p < 2; p++) {
            const int idx = tid + 256 * p;
            const int r = idx >> 3, c8 = (idx & 7) << 3;
            cp16(dstb + (uint32_t)(r * RS_RPITCH + c8) * 2u, src + (long long)r * 64 + c8);
        }
        asm volatile("cp.async.commit_group;");
    }

    __syncthreads();

    uint32_t afrag[4][4];
#pragma unroll
    for (int ks = 0; ks < 4; ks++) {
        afrag[ks][0] = *(const uint32_t*)&qs[g * RS_QPITCH + ks * 16 + 2 * t];
        afrag[ks][1] = *(const uint32_t*)&qs[(g + 8) * RS_QPITCH + ks * 16 + 2 * t];
        afrag[ks][2] = *(const uint32_t*)&qs[g * RS_QPITCH + ks * 16 + 2 * t + 8];
        afrag[ks][3] = *(const uint32_t*)&qs[(g + 8) * RS_QPITCH + ks * 16 + 2 * t + 8];
    }

    const int lrb = wid * 8;     // this warp's 8 k-cols within a chunk
    const int lr  = lrb + g;

    for (int ch = 0; ch < RS_NCHUNK; ch++) {
        asm volatile("cp.async.wait_group 4;");
        __syncthreads();

        const int pf = ch + RS_NBUF - 1;
        if (pf < RS_NCHUNK) {
            const uint32_t dstb = relb_s + (uint32_t)((pf % RS_NBUF) * RS_CHUNK_H) * 2u;
            const __half* src = relS + (long long)pf * RS_CROWS * 64;
#pragma unroll
            for (int p = 0; p < 2; p++) {
                const int idx = tid + 256 * p;
                const int r = idx >> 3, c8 = (idx & 7) << 3;
                cp16(dstb + (uint32_t)(r * RS_RPITCH + c8) * 2u, src + (long long)r * 64 + c8);
            }
        }
        asm volatile("cp.async.commit_group;");

        const __half* rb = relb + (ch % RS_NBUF) * RS_CHUNK_H;
        float c[4] = {0.f, 0.f, 0.f, 0.f};
#pragma unroll
        for (int ks = 0; ks < 4; ks++) {
            uint32_t bb[2];
            bb[0] = *(const uint32_t*)&rb[lr * RS_RPITCH + ks * 16 + 2 * t];
            bb[1] = *(const uint32_t*)&rb[lr * RS_RPITCH + ks * 16 + 2 * t + 8];
            mma_f16(c, afrag[ks], bb);
        }
        const int kc = ch * RS_CROWS + lrb + 2 * t;
        float2 o0 = *(float2*)&sscores[g * SC_PITCH + kc];
        o0.x += c[0]; o0.y += c[1];
        *(float2*)&sscores[g * SC_PITCH + kc] = o0;
        if (g < 4) {
            float2 o1 = *(float2*)&sscores[(g + 8) * SC_PITCH + kc];
            o1.x += c[2]; o1.y += c[3];
            *(float2*)&sscores[(g + 8) * SC_PITCH + kc] = o1;
        }
    }
    __syncthreads();

    // ---- warp-parallel softmax; write fp16 probs ----
#pragma unroll
    for (int hh = 0; hh < 2; hh++) {
        if (hh == 1 && wid >= 4) break;
        const int n = hh ? (8 + wid) : wid;

        float4 v[8];
        float m = -1e30f;
#pragma unroll
        for (int j = 0; j < 8; j++) {
            const int c4 = (lane + 32 * j) << 2;
            float4 a = *(const float4*)&sscores[n * SC_PITCH + c4];
            const float4 mk = *(const float4*)&smask[c4];
            a.x += mk.x; a.y += mk.y; a.z += mk.z; a.w += mk.w;
            v[j] = a;
            m = fmaxf(m, fmaxf(fmaxf(a.x, a.y), fmaxf(a.z, a.w)));
        }
        m = warpRedMax(m);

        float sum = 0.f;
#pragma unroll
        for (int j = 0; j < 8; j++) {
            v[j].x = __expf(v[j].x - m); v[j].y = __expf(v[j].y - m);
            v[j].z = __expf(v[j].z - m); v[j].w = __expf(v[j].w - m);
            sum += v[j].x + v[j].y + v[j].z + v[j].w;
        }
        sum = warpRedSum(sum);
        const float inv = 1.0f / sum;

        __half* prow = probs + (((long long)n << 10) + s) * 1024;
#pragma unroll
        for (int j = 0; j < 8; j++) {
            const int c4 = (lane + 32 * j) << 2;
            __half2 p0 = __floats2half2_rn(v[j].x * inv, v[j].y * inv);
            __half2 p1 = __floats2half2_rn(v[j].z * inv, v[j].w * inv);
            uint2 o; o.x = *(uint32_t*)&p0; o.y = *(uint32_t*)&p1;
            *(uint2*)&prow[c4] = o;
        }
    }
}

// ---------------- split-K reduce + bias + residual + LayerNorm ----------------
template<int NPART, int F32OUT>
__global__ void __launch_bounds__(256) ln_red_kernel(
    const float* __restrict__ part, const float* __restrict__ bias,
    const __half* __restrict__ res,
    const float* __restrict__ g, const float* __restrict__ b, void* __restrict__ outv)
{
    const int s = blockIdx.x;
    const int tid = threadIdx.x;
    const int lane = tid & 31, wid = tid >> 5;
    __shared__ float red[8];

    float v[3];
    float lsum = 0.f;
#pragma unroll
    for (int i = 0; i < 3; i++) {
        const int idx = tid + i * 256;
        float acc = bias[idx] + __half2float(res[s * 768 + idx]);
#pragma unroll
        for (int p = 0; p < NPART; p++)
            acc += part[(long long)p * (SEQ * DM) + s * 768 + idx];
        v[i] = acc;
        lsum += acc;
    }
    lsum = warpRedSum(lsum);
    if (lane == 0) red[wid] = lsum;
    __syncthreads();
    float tot = 0.f;
#pragma unroll
    for (int i = 0; i < 8; i++) tot += red[i];
    const float mu = tot * (1.0f / 768.0f);
    __syncthreads();

    float ls2 = 0.f;
#pragma unroll
    for (int i = 0; i < 3; i++) { const float d = v[i] - mu; ls2 += d * d; }
    ls2 = warpRedSum(ls2);
    if (lane == 0) red[wid] = ls2;
    __syncthreads();
    float tot2 = 0.f;
#pragma unroll
    for (int i = 0; i < 8; i++) tot2 += red[i];
    const float rs = rsqrtf(tot2 * (1.0f / 768.0f) + 1e-12f);

#pragma unroll
    for (int i = 0; i < 3; i++) {
        const int idx = tid + i * 256;
        const float o = (v[i] - mu) * rs * g[idx] + b[idx];
        if (F32OUT) ((float*)outv)[s * 768 + idx] = o;
        else        ((__half*)outv)[s * 768 + idx] = __float2half(o);
    }
}

// ---------------- launcher ----------------
extern "C" void kernel_launch(void* const* d_in, const int* in_sizes, int n_in,
                              void* d_out, int out_size)
{
    const float* hid  = (const float*)d_in[0];
    const float* mask = (const float*)d_in[1];
    const float* rel  = (const float*)d_in[2];
    const float* rel2 = (const float*)d_in[3];
    const float* rela = (const float*)d_in[4];
    const float* Wq = (const float*)d_in[5];   const float* bq = (const float*)d_in[6];
    const float* Wk = (const float*)d_in[7];   const float* bk = (const float*)d_in[8];
    const float* Wv = (const float*)d_in[9];   const float* bv = (const float*)d_in[10];
    const float* Wo = (const float*)d_in[11];  const float* bo = (const float*)d_in[12];
    const float* g1 = (const float*)d_in[13];  const float* b1 = (const float*)d_in[14];
    const float* Wi = (const float*)d_in[15];  const float* bi = (const float*)d_in[16];
    const float* W2 = (const float*)d_in[17];  const float* b2 = (const float*)d_in[18];
    const float* g2 = (const float*)d_in[19];  const float* b2g = (const float*)d_in[20];

    __half *relsum, *probs, *h16, *hbuf, *q, *k, *vt, *ctx, *attn, *inter;
    __half *wq16, *wk16, *wv16, *wo16, *wi16, *w216;
    float *scores, *part;
    cudaGetSymbolAddress((void**)&relsum, g_relsum);
    cudaGetSymbolAddress((void**)&scores, g_scores);
    cudaGetSymbolAddress((void**)&probs, g_probs);
    cudaGetSymbolAddress((void**)&part, g_part);
    cudaGetSymbolAddress((void**)&h16, g_h16);
    cudaGetSymbolAddress((void**)&hbuf, g_hbuf);
    cudaGetSymbolAddress((void**)&q, g_q);
    cudaGetSymbolAddress((void**)&k, g_k);
    cudaGetSymbolAddress((void**)&vt, g_vt);
    cudaGetSymbolAddress((void**)&ctx, g_ctx);
    cudaGetSymbolAddress((void**)&attn, g_attn);
    cudaGetSymbolAddress((void**)&inter, g_inter);
    cudaGetSymbolAddress((void**)&wq16, g_wq16);
    cudaGetSymbolAddress((void**)&wk16, g_wk16);
    cudaGetSymbolAddress((void**)&wv16, g_wv16);
    cudaGetSymbolAddress((void**)&wo16, g_wo16);
    cudaGetSymbolAddress((void**)&wi16, g_wi16);
    cudaGetSymbolAddress((void**)&w216, g_w216);

    cudaFuncSetAttribute(hgemm_g<0, 0>, cudaFuncAttributeMaxDynamicSharedMemorySize, GEMM_SMEM);
    cudaFuncSetAttribute(hgemm_g<0, 1>, cudaFuncAttributeMaxDynamicSharedMemorySize, GEMM_SMEM);
    cudaFuncSetAttribute(hgemm_g<1, 0>, cudaFuncAttributeMaxDynamicSharedMemorySize, GEMM_SMEM);
    cudaFuncSetAttribute(hgemm_sk, cudaFuncAttributeMaxDynamicSharedMemorySize, GEMM_SMEM);
    cudaFuncSetAttribute(hqkv_kernel, cudaFuncAttributeMaxDynamicSharedMemorySize, GEMM_SMEM);
    cudaFuncSetAttribute(hgemm_pv, cudaFuncAttributeMaxDynamicSharedMemorySize, GEMM_SMEM);
    cudaFuncSetAttribute(rel_softmax_kernel, cudaFuncAttributeMaxDynamicSharedMemorySize, RS_SMEM);

    // one-shot fp32 -> fp16 conversions
    f2h1_kernel<<<SEQ * DM / 4 / 256, 256>>>((const float4*)hid, (uint2*)h16);
    f2h4_kernel<<<dim3(NLAYERS * DM * DM / 4 / 256, 1, 4), 256>>>(
        (const float4*)Wq, (const float4*)Wk, (const float4*)Wv, (const float4*)Wo,
        (uint2*)wq16, (uint2*)wk16, (uint2*)wv16, (uint2*)wo16);
    f2h2_kernel<<<dim3(NLAYERS * DFF * DM / 4 / 256, 1, 2), 256>>>(
        (const float4*)Wi, (const float4*)W2, (uint2*)wi16, (uint2*)w216);

    relsum_kernel<<<32768, 256>>>((const float4*)rel, (const float4*)rel2,
                                  (const float4*)rela, (uint2*)relsum);

    const __half* h = h16;
    for (int l = 0; l < NLAYERS; l++) {
        const size_t wofs  = (size_t)l * DM * DM;
        const size_t wiofs = (size_t)l * DFF * DM;

        // fused Q/K/V projections
        hqkv_kernel<<<dim3(12, 8, 3), 256, GEMM_SMEM>>>(
            h, wq16 + wofs, wk16 + wofs, wv16 + wofs,
            bq + l * 768, bk + l * 768, bv + l * 768, q, k, vt);

        // logits = q @ k^T (fp32 out)
        hgemm_g<0, 1><<<dim3(16, 8, 12), 256, GEMM_SMEM>>>(
            q, k, nullptr, scores, 64, 1024, 65536LL, 65536LL, 1048576LL, 1.0f);

        // + rel term + mask + softmax -> fp16 probs
        rel_softmax_kernel<<<1024, 256, RS_SMEM>>>(relsum, q, scores, probs, mask);

        // ctx = probs @ v  (split-K=4)
        hgemm_pv<<<dim3(4, 8, 12), 256, GEMM_SMEM>>>(probs, vt, part);
        pv_reduce<<<768, 256>>>((const float4*)part, (uint2*)ctx);

        // output projection: split-K=2, reduce+bias+residual+LN fused
        hgemm_sk<<<dim3(12, 8, 2), 256, GEMM_SMEM>>>(ctx, wo16 + wofs, part, 768, 384);
        ln_red_kernel<2, 0><<<1024, 256>>>(part, bo + l * 768, h,
                                           g1 + l * 768, b1 + l * 768, attn);

        // FFN
        hgemm_g<1, 0><<<dim3(48, 8, 1), 256, GEMM_SMEM>>>(
            attn, wi16 + wiofs, bi + l * 3072, inter, 768, 3072, 0, 0, 0, 1.0f);

        // FFN2: split-K=4, reduce+bias+residual+LN fused
        hgemm_sk<<<dim3(12, 8, 4), 256, GEMM_SMEM>>>(inter, w216 + wiofs, part, 3072, 768);
        if (l == NLAYERS - 1) {
            ln_red_kernel<4, 1><<<1024, 256>>>(part, b2 + l * 768, attn,
                                               g2 + l * 768, b2g + l * 768, d_out);
        } else {
            ln_red_kernel<4, 0><<<1024, 256>>>(part, b2 + l * 768, attn,
                                               g2 + l * 768, b2g + l * 768, hbuf);
        }
        h = hbuf;
    }
}

// round 10
// speedup vs baseline: 5.7953x; 1.0082x over previous
#include <cuda_runtime.h>
#include <cuda_fp16.h>
#include <math.h>
#include <stdint.h>

#define SEQ 1024
#define DM  768
#define NHEAD 12
#define HDIM 64
#define NLAYERS 4
#define DFF 3072

// ---------------- scratch (static device memory; no runtime allocs) ----------------
__device__ __half g_relsum[(size_t)SEQ * SEQ * HDIM];         // 128 MB (fp16)
__device__ float  g_scores[(size_t)NHEAD * SEQ * SEQ];        // 48 MB (fp32 logits)
__device__ __half g_probs[(size_t)NHEAD * SEQ * SEQ];         // 24 MB (fp16 probs)
__device__ float  g_part[4 * SEQ * DM];                       // split-K partials
__device__ __half g_h16[SEQ * DM];
__device__ __half g_hbuf[SEQ * DM];
__device__ __half g_q[NHEAD * SEQ * HDIM];
__device__ __half g_k[NHEAD * SEQ * HDIM];
__device__ __half g_vt[NHEAD * HDIM * SEQ];
__device__ __half g_ctx[SEQ * DM];
__device__ __half g_attn[SEQ * DM];
__device__ __half g_inter[SEQ * DFF];
// fp16 weights (converted once per launch)
__device__ __half g_wq16[NLAYERS * DM * DM];
__device__ __half g_wk16[NLAYERS * DM * DM];
__device__ __half g_wv16[NLAYERS * DM * DM];
__device__ __half g_wo16[NLAYERS * DM * DM];
__device__ __half g_wi16[NLAYERS * DFF * DM];
__device__ __half g_w216[NLAYERS * DM * DFF];

// ---------------- helpers ----------------
__device__ __forceinline__ float warpRedMax(float v) {
#pragma unroll
    for (int o = 16; o > 0; o >>= 1) v = fmaxf(v, __shfl_xor_sync(0xffffffffu, v, o));
    return v;
}
__device__ __forceinline__ float warpRedSum(float v) {
#pragma unroll
    for (int o = 16; o > 0; o >>= 1) v += __shfl_xor_sync(0xffffffffu, v, o);
    return v;
}
__device__ __forceinline__ void cp16(uint32_t dst, const void* src) {
    asm volatile("cp.async.cg.shared.global [%0], [%1], 16;" :: "r"(dst), "l"(src));
}
__device__ __forceinline__ void mma_f16(float* c, const uint32_t* a, const uint32_t* b) {
    asm volatile(
        "mma.sync.aligned.m16n8k16.row.col.f32.f16.f16.f32 "
        "{%0,%1,%2,%3}, {%4,%5,%6,%7}, {%8,%9}, {%0,%1,%2,%3};"
        : "+f"(c[0]), "+f"(c[1]), "+f"(c[2]), "+f"(c[3])
        : "r"(a[0]), "r"(a[1]), "r"(a[2]), "r"(a[3]), "r"(b[0]), "r"(b[1]));
}
__device__ __forceinline__ void ldsm_x4(uint32_t& r0, uint32_t& r1, uint32_t& r2, uint32_t& r3,
                                        uint32_t addr) {
    asm volatile("ldmatrix.sync.aligned.m8n8.x4.shared.b16 {%0,%1,%2,%3}, [%4];"
                 : "=r"(r0), "=r"(r1), "=r"(r2), "=r"(r3) : "r"(addr));
}
__device__ __forceinline__ uint2 f4_to_h4(float4 x) {
    __half2 h0 = __floats2half2_rn(x.x, x.y);
    __half2 h1 = __floats2half2_rn(x.z, x.w);
    uint2 o; o.x = *(uint32_t*)&h0; o.y = *(uint32_t*)&h1;
    return o;
}

// ---------------- one-shot fp32 -> fp16 conversions ----------------
__global__ void __launch_bounds__(256) f2h1_kernel(
    const float4* __restrict__ s, uint2* __restrict__ d)
{
    const int i = blockIdx.x * 256 + threadIdx.x;
    d[i] = f4_to_h4(s[i]);
}
__global__ void __launch_bounds__(256) f2h4_kernel(
    const float4* __restrict__ s0, const float4* __restrict__ s1,
    const float4* __restrict__ s2, const float4* __restrict__ s3,
    uint2* __restrict__ d0, uint2* __restrict__ d1,
    uint2* __restrict__ d2, uint2* __restrict__ d3)
{
    const int i = blockIdx.x * 256 + threadIdx.x;
    const int z = blockIdx.z;
    const float4* s = (z == 0) ? s0 : (z == 1) ? s1 : (z == 2) ? s2 : s3;
    uint2* d        = (z == 0) ? d0 : (z == 1) ? d1 : (z == 2) ? d2 : d3;
    d[i] = f4_to_h4(s[i]);
}
__global__ void __launch_bounds__(256) f2h2_kernel(
    const float4* __restrict__ s0, const float4* __restrict__ s1,
    uint2* __restrict__ d0, uint2* __restrict__ d1)
{
    const int i = blockIdx.x * 256 + threadIdx.x;
    const float4* s = blockIdx.z ? s1 : s0;
    uint2* d        = blockIdx.z ? d1 : d0;
    d[i] = f4_to_h4(s[i]);
}

// ---------------- relsum = rel_pos + rel_2d_pos + rel_2d_angle (fp16 out, one-shot) ----------------
#define RELSUM_HALF 8388608
__global__ void __launch_bounds__(256) relsum_kernel(
    const float4* __restrict__ a, const float4* __restrict__ b,
    const float4* __restrict__ c, uint2* __restrict__ out)
{
    const int i = blockIdx.x * 256 + threadIdx.x;
    float4 x0 = a[i], y0 = b[i], z0 = c[i];
    float4 x1 = a[i + RELSUM_HALF], y1 = b[i + RELSUM_HALF], z1 = c[i + RELSUM_HALF];
    x0.x += y0.x + z0.x; x0.y += y0.y + z0.y; x0.z += y0.z + z0.z; x0.w += y0.w + z0.w;
    x1.x += y1.x + z1.x; x1.y += y1.y + z1.y; x1.z += y1.z + z1.z; x1.w += y1.w + z1.w;
    out[i] = f4_to_h4(x0);
    out[i + RELSUM_HALF] = f4_to_h4(x1);
}

// ---------------- 128x64 fp16 GEMM mainloop (256 threads, ldmatrix, 3-stage) ----------------
#define A_ST 9216    // halves per A stage
#define W_ST 4608    // halves per W stage
#define GEMM_SMEM ((3 * A_ST + 3 * W_ST) * 2)   // 82944 B

__device__ __forceinline__ void hgemm_mainloop(
    const __half* __restrict__ Ag, const __half* __restrict__ Wg,
    __half* __restrict__ sm, int Kloop, int lda, int ldw, float acc[2][4][4])
{
    const int tid = threadIdx.x;
    const int srow = tid >> 3;
    const int scol = (tid & 7) << 3;

    __half* As = sm;
    __half* Ws = sm + 3 * A_ST;

    const uint32_t asB = (uint32_t)__cvta_generic_to_shared(As);
    const uint32_t wsB = (uint32_t)__cvta_generic_to_shared(Ws);
    const uint32_t sa0 = asB + (uint32_t)(srow * 72 + scol) * 2u;
    const uint32_t sw0 = wsB + (uint32_t)(srow * 72 + scol) * 2u;

    const __half* Agp = Ag + (long long)srow * lda + scol;
    const __half* Wgp = Wg + (long long)srow * ldw + scol;

    const int KT = Kloop >> 6;

#pragma unroll
    for (int st = 0; st < 2; st++) {
        if (st < KT) {
#pragma unroll
            for (int p = 0; p < 4; p++)
                cp16(sa0 + (uint32_t)(st * A_ST + p * 32 * 72) * 2u, Agp + (long long)(p * 32) * lda + st * 64);
#pragma unroll
            for (int p = 0; p < 2; p++)
                cp16(sw0 + (uint32_t)(st * W_ST + p * 32 * 72) * 2u, Wgp + (long long)(p * 32) * ldw + st * 64);
        }
        asm volatile("cp.async.commit_group;");
    }

    const int wid = tid >> 5, lane = tid & 31;
    const int wm = wid & 3, wn = wid >> 2;
    const int a_row = wm * 32 + (lane & 15);
    const int a_ko  = (lane >> 4) << 3;
    const int b_row = wn * 32 + (lane & 7) + ((lane >> 4) << 3);
    const int b_ko  = ((lane >> 3) & 1) << 3;

    const uint32_t aF = asB + (uint32_t)(a_row * 72 + a_ko) * 2u;
    const uint32_t wF = wsB + (uint32_t)(b_row * 72 + b_ko) * 2u;

    for (int kt = 0; kt < KT; kt++) {
        asm volatile("cp.async.wait_group 1;");
        __syncthreads();

        const int pf = kt + 2;
        if (pf < KT) {
            const int st = pf % 3;
#pragma unroll
            for (int p = 0; p < 4; p++)
                cp16(sa0 + (uint32_t)(st * A_ST + p * 32 * 72) * 2u, Agp + (long long)(p * 32) * lda + pf * 64);
#pragma unroll
            for (int p = 0; p < 2; p++)
                cp16(sw0 + (uint32_t)(st * W_ST + p * 32 * 72) * 2u, Wgp + (long long)(p * 32) * ldw + pf * 64);
        }
        asm volatile("cp.async.commit_group;");

        const uint32_t aS = aF + (uint32_t)((kt % 3) * A_ST) * 2u;
        const uint32_t wS = wF + (uint32_t)((kt % 3) * W_ST) * 2u;

#pragma unroll
        for (int ks = 0; ks < 4; ks++) {
            uint32_t a[2][4], b[2][4];
#pragma unroll
            for (int mt = 0; mt < 2; mt++)
                ldsm_x4(a[mt][0], a[mt][1], a[mt][2], a[mt][3],
                        aS + (uint32_t)(mt * 16 * 72 + ks * 16) * 2u);
#pragma unroll
            for (int nt2 = 0; nt2 < 2; nt2++)
                ldsm_x4(b[nt2][0], b[nt2][1], b[nt2][2], b[nt2][3],
                        wS + (uint32_t)(nt2 * 16 * 72 + ks * 16) * 2u);
#pragma unroll
            for (int mt = 0; mt < 2; mt++)
#pragma unroll
                for (int nt = 0; nt < 4; nt++) {
                    uint32_t bb[2] = { b[nt >> 1][(nt & 1) * 2], b[nt >> 1][(nt & 1) * 2 + 1] };
                    mma_f16(acc[mt][nt], a[mt], bb);
                }
        }
    }
}

// ---------------- generic fp16 GEMM (z-batched): C = A @ W^T (+bias, GELU, scale) ----------------
template<int EPI, int F32OUT>
__global__ void __launch_bounds__(256, 2) hgemm_g(
    const __half* __restrict__ A, const __half* __restrict__ W,
    const float* __restrict__ bias, void* __restrict__ Cv,
    int K, int ldC, long long sA, long long sW, long long sC, float scale)
{
    extern __shared__ __half smh[];
    const int bz = blockIdx.z;
    const int m0 = blockIdx.y << 7, n0 = blockIdx.x << 6;

    float acc[2][4][4];
#pragma unroll
    for (int i = 0; i < 2; i++)
#pragma unroll
        for (int j = 0; j < 4; j++)
#pragma unroll
            for (int l = 0; l < 4; l++) acc[i][j][l] = 0.f;

    hgemm_mainloop(A + sA * bz + (long long)m0 * K,
                   W + sW * bz + (long long)n0 * K, smh, K, K, K, acc);

    const int tid = threadIdx.x, wid = tid >> 5, lane = tid & 31;
    const int wm = wid & 3, wn = wid >> 2, g = lane >> 2, t = lane & 3;

#pragma unroll
    for (int mt = 0; mt < 2; mt++) {
        const int rb = m0 + wm * 32 + mt * 16 + g;
#pragma unroll
        for (int nt = 0; nt < 4; nt++) {
            const int cb = n0 + wn * 32 + nt * 8 + 2 * t;
#pragma unroll
            for (int hf = 0; hf < 2; hf++) {
                const int m = rb + hf * 8;
                float v0 = acc[mt][nt][hf * 2 + 0];
                float v1 = acc[mt][nt][hf * 2 + 1];
                if (bias) { v0 += bias[cb]; v1 += bias[cb + 1]; }
                if (EPI == 1) {
                    v0 = 0.5f * v0 * (1.0f + erff(v0 * 0.70710678118654752f));
                    v1 = 0.5f * v1 * (1.0f + erff(v1 * 0.70710678118654752f));
                }
                v0 *= scale; v1 *= scale;
                if (F32OUT) {
                    float* C = (float*)Cv + sC * bz;
                    *(float2*)&C[(long long)m * ldC + cb] = make_float2(v0, v1);
                } else {
                    __half* C = (__half*)Cv + sC * bz;
                    __half2 h2 = __floats2half2_rn(v0, v1);
                    *(__half2*)&C[(long long)m * ldC + cb] = h2;
                }
            }
        }
    }
}

// ---------------- split-K GEMM: part[ks] = A[:, ks*Ksplit:+Ksplit] @ W[:, same]^T ----------------
__global__ void __launch_bounds__(256, 2) hgemm_sk(
    const __half* __restrict__ A, const __half* __restrict__ W,
    float* __restrict__ part, int Kfull, int Ksplit)
{
    extern __shared__ __half smh[];
    const int ks = blockIdx.z;
    const int m0 = blockIdx.y << 7, n0 = blockIdx.x << 6;

    float acc[2][4][4];
#pragma unroll
    for (int i = 0; i < 2; i++)
#pragma unroll
        for (int j = 0; j < 4; j++)
#pragma unroll
            for (int l = 0; l < 4; l++) acc[i][j][l] = 0.f;

    hgemm_mainloop(A + (long long)m0 * Kfull + (long long)ks * Ksplit,
                   W + (long long)n0 * Kfull + (long long)ks * Ksplit,
                   smh, Ksplit, Kfull, Kfull, acc);

    float* C = part + (long long)ks * (SEQ * DM);

    const int tid = threadIdx.x, wid = tid >> 5, lane = tid & 31;
    const int wm = wid & 3, wn = wid >> 2, g = lane >> 2, t = lane & 3;

#pragma unroll
    for (int mt = 0; mt < 2; mt++) {
        const int rb = m0 + wm * 32 + mt * 16 + g;
#pragma unroll
        for (int nt = 0; nt < 4; nt++) {
            const int cb = n0 + wn * 32 + nt * 8 + 2 * t;
#pragma unroll
            for (int hf = 0; hf < 2; hf++) {
                const int m = rb + hf * 8;
                *(float2*)&C[(long long)m * DM + cb] =
                    make_float2(acc[mt][nt][hf * 2 + 0], acc[mt][nt][hf * 2 + 1]);
            }
        }
    }
}

// ---------------- fused QKV projection (fp16) ----------------
__global__ void __launch_bounds__(256, 2) hqkv_kernel(
    const __half* __restrict__ h,
    const __half* __restrict__ Wq, const __half* __restrict__ Wk, const __half* __restrict__ Wv,
    const float* __restrict__ bq, const float* __restrict__ bk, const float* __restrict__ bv,
    __half* __restrict__ qo, __half* __restrict__ ko, __half* __restrict__ vto)
{
    extern __shared__ __half smh[];
    const int z = blockIdx.z;
    const __half* W   = (z == 0) ? Wq : (z == 1) ? Wk : Wv;
    const float* bias = (z == 0) ? bq : (z == 1) ? bk : bv;
    __half* out       = (z == 0) ? qo : (z == 1) ? ko : vto;
    const float scale = (z == 0) ? 0.125f : 1.0f;
    const int m0 = blockIdx.y << 7, n0 = blockIdx.x << 6;

    float acc[2][4][4];
#pragma unroll
    for (int i = 0; i < 2; i++)
#pragma unroll
        for (int j = 0; j < 4; j++)
#pragma unroll
            for (int l = 0; l < 4; l++) acc[i][j][l] = 0.f;

    hgemm_mainloop(h + (long long)m0 * DM, W + (long long)n0 * DM, smh, DM, DM, DM, acc);

    const int tid = threadIdx.x, wid = tid >> 5, lane = tid & 31;
    const int wm = wid & 3, wn = wid >> 2, g = lane >> 2, t = lane & 3;

#pragma unroll
    for (int mt = 0; mt < 2; mt++) {
        const int rb = m0 + wm * 32 + mt * 16 + g;
#pragma unroll
        for (int nt = 0; nt < 4; nt++) {
            const int cb = n0 + wn * 32 + nt * 8 + 2 * t;
#pragma unroll
            for (int hf = 0; hf < 2; hf++) {
                const int m = rb + hf * 8;
                float v0 = (acc[mt][nt][hf * 2 + 0] + bias[cb]) * scale;
                float v1 = (acc[mt][nt][hf * 2 + 1] + bias[cb + 1]) * scale;
                if (z < 2) {
                    const long long idx = ((long long)(cb >> 6) << 16) + (long long)m * 64 + (cb & 63);
                    __half2 h2 = __floats2half2_rn(v0, v1);
                    *(__half2*)&out[idx] = h2;
                } else {
                    out[(long long)cb * 1024 + m]       = __float2half(v0);
                    out[(long long)(cb + 1) * 1024 + m] = __float2half(v1);
                }
            }
        }
    }
}

// ---------------- PV split-K GEMM (fp16 probs x fp16 vt -> fp32 partials) ----------------
__global__ void __launch_bounds__(256, 2) hgemm_pv(
    const __half* __restrict__ probs, const __half* __restrict__ vt, float* __restrict__ part)
{
    extern __shared__ __half smh[];
    const int ks = blockIdx.x;
    const int m0 = blockIdx.y << 7;
    const int hd = blockIdx.z;

    float acc[2][4][4];
#pragma unroll
    for (int i = 0; i < 2; i++)
#pragma unroll
        for (int j = 0; j < 4; j++)
#pragma unroll
            for (int l = 0; l < 4; l++) acc[i][j][l] = 0.f;

    hgemm_mainloop(probs + (long long)hd * 1048576 + (long long)m0 * 1024 + ks * 256,
                   vt + (long long)hd * 65536 + ks * 256,
                   smh, 256, 1024, 1024, acc);

    float* C = part + (long long)ks * 786432 + hd * 64;

    const int tid = threadIdx.x, wid = tid >> 5, lane = tid & 31;
    const int wm = wid & 3, wn = wid >> 2, g = lane >> 2, t = lane & 3;

#pragma unroll
    for (int mt = 0; mt < 2; mt++) {
        const int rb = m0 + wm * 32 + mt * 16 + g;
#pragma unroll
        for (int nt = 0; nt < 4; nt++) {
            const int cb = wn * 32 + nt * 8 + 2 * t;
#pragma unroll
            for (int hf = 0; hf < 2; hf++) {
                const int m = rb + hf * 8;
                *(float2*)&C[(long long)m * 768 + cb] =
                    make_float2(acc[mt][nt][hf * 2 + 0], acc[mt][nt][hf * 2 + 1]);
            }
        }
    }
}

// ---------------- PV reduce: ctx(fp16) = sum of 4 fp32 partials ----------------
__global__ void __launch_bounds__(256) pv_reduce(
    const float4* __restrict__ part, uint2* __restrict__ ctx)
{
    const int i = blockIdx.x * 256 + threadIdx.x;
    float4 a = part[i];
    const float4 b = part[i + 196608];
    const float4 c = part[i + 393216];
    const float4 d = part[i + 589824];
    a.x += b.x + c.x + d.x; a.y += b.y + c.y + d.y;
    a.z += b.z + c.z + d.z; a.w += b.w + c.w + d.w;
    ctx[i] = f4_to_h4(a);
}

// ---------------- fused rel-score + mask + softmax (64-row chunks, 6-deep pipeline) ----------------
#define SC_PITCH 1032
#define RS_QPITCH 72
#define RS_RPITCH 72
#define RS_CROWS 64
#define RS_CHUNK_H (RS_CROWS * RS_RPITCH)
#define RS_NBUF 6
#define RS_NCHUNK 16
#define RS_SMEM 111232

__global__ void __launch_bounds__(256) rel_softmax_kernel(
    const __half* __restrict__ rel, const __half* __restrict__ qb,
    const float* __restrict__ scores, __half* __restrict__ probs,
    const float* __restrict__ mask)
{
    extern __shared__ char smc[];
    __half* qs      = (__half*)smc;
    float*  sscores = (float*)(smc + 2304);
    float*  smask   = (float*)(smc + 51840);
    __half* relb    = (__half*)(smc + 55936);

    const int s = blockIdx.x;
    const int tid = threadIdx.x;
    const int wid = tid >> 5, lane = tid & 31;
    const int g = lane >> 2, t = lane & 3;

    // ---- group 0: prefetch 12 fp32 score rows (padded pitch) + mask ----
    {
        const uint32_t ss_s = (uint32_t)__cvta_generic_to_shared(sscores);
#pragma unroll
        for (int p = 0; p < 12; p++) {
            const int idx = tid + 256 * p;
            const int n = idx >> 8, c4 = (idx & 255) << 2;
            cp16(ss_s + (uint32_t)(n * SC_PITCH + c4) * 4u,
                 scores + (((long long)n << 10) + s) * 1024 + c4);
        }
        cp16((uint32_t)__cvta_generic_to_shared(smask) + (uint32_t)(tid << 4),
             mask + (tid << 2));
        asm volatile("cp.async.commit_group;");
    }

    for (int i = tid; i < 16 * 64; i += 256) {
        const int r = i >> 6, c = i & 63;
        qs[r * RS_QPITCH + c] = (r < 12) ? qb[((long long)r << 16) + (s << 6) + c] : __float2half(0.f);
    }

    const __half* relS = rel + ((long long)s << 16);
    const uint32_t relb_s = (uint32_t)__cvta_generic_to_shared(relb);

#pragma unroll
    for (int ch = 0; ch < RS_NBUF - 1; ch++) {
        const uint32_t dstb = relb_s + (uint32_t)(ch * RS_CHUNK_H) * 2u;
        const __half* src = relS + (long long)ch * RS_CROWS * 64;
#pragma unroll
        for (int p = 0; p < 2; p++) {
            const int idx = tid + 256 * p;
            const int r = idx >> 3, c8 = (idx & 7) << 3;
            cp16(dstb + (uint32_t)(r * RS_RPITCH + c8) * 2u, src + (long long)r * 64 + c8);
        }
        asm volatile("cp.async.commit_group;");
    }

    __syncthreads();

    uint32_t afrag[4][4];
#pragma unroll
    for (int ks = 0; ks < 4; ks++) {
        afrag[ks][0] = *(const uint32_t*)&qs[g * RS_QPITCH + ks * 16 + 2 * t];
        afrag[ks][1] = *(const uint32_t*)&qs[(g + 8) * RS_QPITCH + ks * 16 + 2 * t];
        afrag[ks][2] = *(const uint32_t*)&qs[g * RS_QPITCH + ks * 16 + 2 * t + 8];
        afrag[ks][3] = *(const uint32_t*)&qs[(g + 8) * RS_QPITCH + ks * 16 + 2 * t + 8];
    }

    const int lrb = wid * 8;
    const int lr  = lrb + g;

    for (int ch = 0; ch < RS_NCHUNK; ch++) {
        asm volatile("cp.async.wait_group 4;");
        __syncthreads();

        const int pf = ch + RS_NBUF - 1;
        if (pf < RS_NCHUNK) {
            const uint32_t dstb = relb_s + (uint32_t)((pf % RS_NBUF) * RS_CHUNK_H) * 2u;
            const __half* src = relS + (long long)pf * RS_CROWS * 64;
#pragma unroll
            for (int p = 0; p < 2; p++) {
                const int idx = tid + 256 * p;
                const int r = idx >> 3, c8 = (idx & 7) << 3;
                cp16(dstb + (uint32_t)(r * RS_RPITCH + c8) * 2u, src + (long long)r * 64 + c8);
            }
        }
        asm volatile("cp.async.commit_group;");

        const __half* rb = relb + (ch % RS_NBUF) * RS_CHUNK_H;
        float c[4] = {0.f, 0.f, 0.f, 0.f};
#pragma unroll
        for (int ks = 0; ks < 4; ks++) {
            uint32_t bb[2];
            bb[0] = *(const uint32_t*)&rb[lr * RS_RPITCH + ks * 16 + 2 * t];
            bb[1] = *(const uint32_t*)&rb[lr * RS_RPITCH + ks * 16 + 2 * t + 8];
            mma_f16(c, afrag[ks], bb);
        }
        const int kc = ch * RS_CROWS + lrb + 2 * t;
        float2 o0 = *(float2*)&sscores[g * SC_PITCH + kc];
        o0.x += c[0]; o0.y += c[1];
        *(float2*)&sscores[g * SC_PITCH + kc] = o0;
        if (g < 4) {
            float2 o1 = *(float2*)&sscores[(g + 8) * SC_PITCH + kc];
            o1.x += c[2]; o1.y += c[3];
            *(float2*)&sscores[(g + 8) * SC_PITCH + kc] = o1;
        }
    }
    __syncthreads();

    // ---- warp-parallel softmax; write fp16 probs ----
#pragma unroll
    for (int hh = 0; hh < 2; hh++) {
        if (hh == 1 && wid >= 4) break;
        const int n = hh ? (8 + wid) : wid;

        float4 v[8];
        float m = -1e30f;
#pragma unroll
        for (int j = 0; j < 8; j++) {
            const int c4 = (lane + 32 * j) << 2;
            float4 a = *(const float4*)&sscores[n * SC_PITCH + c4];
            const float4 mk = *(const float4*)&smask[c4];
            a.x += mk.x; a.y += mk.y; a.z += mk.z; a.w += mk.w;
            v[j] = a;
            m = fmaxf(m, fmaxf(fmaxf(a.x, a.y), fmaxf(a.z, a.w)));
        }
        m = warpRedMax(m);

        float sum = 0.f;
#pragma unroll
        for (int j = 0; j < 8; j++) {
            v[j].x = __expf(v[j].x - m); v[j].y = __expf(v[j].y - m);
            v[j].z = __expf(v[j].z - m); v[j].w = __expf(v[j].w - m);
            sum += v[j].x + v[j].y + v[j].z + v[j].w;
        }
        sum = warpRedSum(sum);
        const float inv = 1.0f / sum;

        __half* prow = probs + (((long long)n << 10) + s) * 1024;
#pragma unroll
        for (int j = 0; j < 8; j++) {
            const int c4 = (lane + 32 * j) << 2;
            __half2 p0 = __floats2half2_rn(v[j].x * inv, v[j].y * inv);
            __half2 p1 = __floats2half2_rn(v[j].z * inv, v[j].w * inv);
            uint2 o; o.x = *(uint32_t*)&p0; o.y = *(uint32_t*)&p1;
            *(uint2*)&prow[c4] = o;
        }
    }
}

// ---------------- split-K reduce + bias + residual + LayerNorm ----------------
template<int NPART, int F32OUT>
__global__ void __launch_bounds__(256) ln_red_kernel(
    const float* __restrict__ part, const float* __restrict__ bias,
    const __half* __restrict__ res,
    const float* __restrict__ g, const float* __restrict__ b, void* __restrict__ outv)
{
    const int s = blockIdx.x;
    const int tid = threadIdx.x;
    const int lane = tid & 31, wid = tid >> 5;
    __shared__ float red[8];

    float v[3];
    float lsum = 0.f;
#pragma unroll
    for (int i = 0; i < 3; i++) {
        const int idx = tid + i * 256;
        float acc = bias[idx] + __half2float(res[s * 768 + idx]);
#pragma unroll
        for (int p = 0; p < NPART; p++)
            acc += part[(long long)p * (SEQ * DM) + s * 768 + idx];
        v[i] = acc;
        lsum += acc;
    }
    lsum = warpRedSum(lsum);
    if (lane == 0) red[wid] = lsum;
    __syncthreads();
    float tot = 0.f;
#pragma unroll
    for (int i = 0; i < 8; i++) tot += red[i];
    const float mu = tot * (1.0f / 768.0f);
    __syncthreads();

    float ls2 = 0.f;
#pragma unroll
    for (int i = 0; i < 3; i++) { const float d = v[i] - mu; ls2 += d * d; }
    ls2 = warpRedSum(ls2);
    if (lane == 0) red[wid] = ls2;
    __syncthreads();
    float tot2 = 0.f;
#pragma unroll
    for (int i = 0; i < 8; i++) tot2 += red[i];
    const float rs = rsqrtf(tot2 * (1.0f / 768.0f) + 1e-12f);

#pragma unroll
    for (int i = 0; i < 3; i++) {
        const int idx = tid + i * 256;
        const float o = (v[i] - mu) * rs * g[idx] + b[idx];
        if (F32OUT) ((float*)outv)[s * 768 + idx] = o;
        else        ((__half*)outv)[s * 768 + idx] = __float2half(o);
    }
}

// ---------------- launcher ----------------
extern "C" void kernel_launch(void* const* d_in, const int* in_sizes, int n_in,
                              void* d_out, int out_size)
{
    const float* hid  = (const float*)d_in[0];
    const float* mask = (const float*)d_in[1];
    const float* rel  = (const float*)d_in[2];
    const float* rel2 = (const float*)d_in[3];
    const float* rela = (const float*)d_in[4];
    const float* Wq = (const float*)d_in[5];   const float* bq = (const float*)d_in[6];
    const float* Wk = (const float*)d_in[7];   const float* bk = (const float*)d_in[8];
    const float* Wv = (const float*)d_in[9];   const float* bv = (const float*)d_in[10];
    const float* Wo = (const float*)d_in[11];  const float* bo = (const float*)d_in[12];
    const float* g1 = (const float*)d_in[13];  const float* b1 = (const float*)d_in[14];
    const float* Wi = (const float*)d_in[15];  const float* bi = (const float*)d_in[16];
    const float* W2 = (const float*)d_in[17];  const float* b2 = (const float*)d_in[18];
    const float* g2 = (const float*)d_in[19];  const float* b2g = (const float*)d_in[20];

    __half *relsum, *probs, *h16, *hbuf, *q, *k, *vt, *ctx, *attn, *inter;
    __half *wq16, *wk16, *wv16, *wo16, *wi16, *w216;
    float *scores, *part;
    cudaGetSymbolAddress((void**)&relsum, g_relsum);
    cudaGetSymbolAddress((void**)&scores, g_scores);
    cudaGetSymbolAddress((void**)&probs, g_probs);
    cudaGetSymbolAddress((void**)&part, g_part);
    cudaGetSymbolAddress((void**)&h16, g_h16);
    cudaGetSymbolAddress((void**)&hbuf, g_hbuf);
    cudaGetSymbolAddress((void**)&q, g_q);
    cudaGetSymbolAddress((void**)&k, g_k);
    cudaGetSymbolAddress((void**)&vt, g_vt);
    cudaGetSymbolAddress((void**)&ctx, g_ctx);
    cudaGetSymbolAddress((void**)&attn, g_attn);
    cudaGetSymbolAddress((void**)&inter, g_inter);
    cudaGetSymbolAddress((void**)&wq16, g_wq16);
    cudaGetSymbolAddress((void**)&wk16, g_wk16);
    cudaGetSymbolAddress((void**)&wv16, g_wv16);
    cudaGetSymbolAddress((void**)&wo16, g_wo16);
    cudaGetSymbolAddress((void**)&wi16, g_wi16);
    cudaGetSymbolAddress((void**)&w216, g_w216);

    cudaFuncSetAttribute(hgemm_g<0, 0>, cudaFuncAttributeMaxDynamicSharedMemorySize, GEMM_SMEM);
    cudaFuncSetAttribute(hgemm_g<0, 1>, cudaFuncAttributeMaxDynamicSharedMemorySize, GEMM_SMEM);
    cudaFuncSetAttribute(hgemm_g<1, 0>, cudaFuncAttributeMaxDynamicSharedMemorySize, GEMM_SMEM);
    cudaFuncSetAttribute(hgemm_sk, cudaFuncAttributeMaxDynamicSharedMemorySize, GEMM_SMEM);
    cudaFuncSetAttribute(hqkv_kernel, cudaFuncAttributeMaxDynamicSharedMemorySize, GEMM_SMEM);
    cudaFuncSetAttribute(hgemm_pv, cudaFuncAttributeMaxDynamicSharedMemorySize, GEMM_SMEM);
    cudaFuncSetAttribute(rel_softmax_kernel, cudaFuncAttributeMaxDynamicSharedMemorySize, RS_SMEM);

    // side stream + events (created once; reused across calls; graph fork/join pattern)
    static cudaStream_t s_side = nullptr;
    static cudaEvent_t ev_fork = nullptr, ev_join = nullptr;
    if (s_side == nullptr) {
        cudaStreamCreateWithFlags(&s_side, cudaStreamNonBlocking);
        cudaEventCreateWithFlags(&ev_fork, cudaEventDisableTiming);
        cudaEventCreateWithFlags(&ev_join, cudaEventDisableTiming);
    }

    // ---- fork: relsum runs on the side branch, overlapped with f2h + layer-0 qkv/qk ----
    cudaEventRecord(ev_fork, 0);
    cudaStreamWaitEvent(s_side, ev_fork, 0);
    relsum_kernel<<<32768, 256, 0, s_side>>>((const float4*)rel, (const float4*)rel2,
                                             (const float4*)rela, (uint2*)relsum);
    cudaEventRecord(ev_join, s_side);

    // main branch: one-shot fp32 -> fp16 conversions
    f2h1_kernel<<<SEQ * DM / 4 / 256, 256>>>((const float4*)hid, (uint2*)h16);
    f2h4_kernel<<<dim3(NLAYERS * DM * DM / 4 / 256, 1, 4), 256>>>(
        (const float4*)Wq, (const float4*)Wk, (const float4*)Wv, (const float4*)Wo,
        (uint2*)wq16, (uint2*)wk16, (uint2*)wv16, (uint2*)wo16);
    f2h2_kernel<<<dim3(NLAYERS * DFF * DM / 4 / 256, 1, 2), 256>>>(
        (const float4*)Wi, (const float4*)W2, (uint2*)wi16, (uint2*)w216);

    const __half* h = h16;
    for (int l = 0; l < NLAYERS; l++) {
        const size_t wofs  = (size_t)l * DM * DM;
        const size_t wiofs = (size_t)l * DFF * DM;

        // fused Q/K/V projections
        hqkv_kernel<<<dim3(12, 8, 3), 256, GEMM_SMEM>>>(
            h, wq16 + wofs, wk16 + wofs, wv16 + wofs,
            bq + l * 768, bk + l * 768, bv + l * 768, q, k, vt);

        // logits = q @ k^T (fp32 out)
        hgemm_g<0, 1><<<dim3(16, 8, 12), 256, GEMM_SMEM>>>(
            q, k, nullptr, scores, 64, 1024, 65536LL, 65536LL, 1048576LL, 1.0f);

        // join the relsum branch before its first consumer
        if (l == 0) cudaStreamWaitEvent(0, ev_join, 0);

        // + rel term + mask + softmax -> fp16 probs
        rel_softmax_kernel<<<1024, 256, RS_SMEM>>>(relsum, q, scores, probs, mask);

        // ctx = probs @ v  (split-K=4)
        hgemm_pv<<<dim3(4, 8, 12), 256, GEMM_SMEM>>>(probs, vt, part);
        pv_reduce<<<768, 256>>>((const float4*)part, (uint2*)ctx);

        // output projection: split-K=2, reduce+bias+residual+LN fused
        hgemm_sk<<<dim3(12, 8, 2), 256, GEMM_SMEM>>>(ctx, wo16 + wofs, part, 768, 384);
        ln_red_kernel<2, 0><<<1024, 256>>>(part, bo + l * 768, h,
                                           g1 + l * 768, b1 + l * 768, attn);

        // FFN
        hgemm_g<1, 0><<<dim3(48, 8, 1), 256, GEMM_SMEM>>>(
            attn, wi16 + wiofs, bi + l * 3072, inter, 768, 3072, 0, 0, 0, 1.0f);

        // FFN2: split-K=4, reduce+bias+residual+LN fused
        hgemm_sk<<<dim3(12, 8, 4), 256, GEMM_SMEM>>>(inter, w216 + wiofs, part, 3072, 768);
        if (l == NLAYERS - 1) {
            ln_red_kernel<4, 1><<<1024, 256>>>(part, b2 + l * 768, attn,
                                               g2 + l * 768, b2g + l * 768, d_out);
        } else {
            ln_red_kernel<4, 0><<<1024, 256>>>(part, b2 + l * 768, attn,
                                               g2 + l * 768, b2g + l * 768, hbuf);
        }
        h = hbuf;
    }
}

// round 11
// speedup vs baseline: 5.9159x; 1.0208x over previous
#include <cuda_runtime.h>
#include <cuda_fp16.h>
#include <math.h>
#include <stdint.h>

#define SEQ 1024
#define DM  768
#define NHEAD 12
#define HDIM 64
#define NLAYERS 4
#define DFF 3072

// ---------------- scratch (static device memory; no runtime allocs) ----------------
__device__ __half g_relsum[(size_t)SEQ * SEQ * HDIM];         // 128 MB (fp16)
__device__ float  g_scores[(size_t)NHEAD * SEQ * SEQ];        // 48 MB (fp32 logits)
__device__ __half g_probs[(size_t)NHEAD * SEQ * SEQ];         // 24 MB (fp16 probs)
__device__ float  g_part[4 * SEQ * DM];                       // split-K partials
__device__ __half g_h16[SEQ * DM];
__device__ __half g_hbuf[SEQ * DM];
__device__ __half g_q[NHEAD * SEQ * HDIM];
__device__ __half g_k[NHEAD * SEQ * HDIM];
__device__ __half g_vt[NHEAD * HDIM * SEQ];
__device__ __half g_ctx[SEQ * DM];
__device__ __half g_attn[SEQ * DM];
__device__ __half g_inter[SEQ * DFF];
// fp16 weights (converted once per launch)
__device__ __half g_wq16[NLAYERS * DM * DM];
__device__ __half g_wk16[NLAYERS * DM * DM];
__device__ __half g_wv16[NLAYERS * DM * DM];
__device__ __half g_wo16[NLAYERS * DM * DM];
__device__ __half g_wi16[NLAYERS * DFF * DM];
__device__ __half g_w216[NLAYERS * DM * DFF];

// ---------------- helpers ----------------
__device__ __forceinline__ float warpRedMax(float v) {
#pragma unroll
    for (int o = 16; o > 0; o >>= 1) v = fmaxf(v, __shfl_xor_sync(0xffffffffu, v, o));
    return v;
}
__device__ __forceinline__ float warpRedSum(float v) {
#pragma unroll
    for (int o = 16; o > 0; o >>= 1) v += __shfl_xor_sync(0xffffffffu, v, o);
    return v;
}
__device__ __forceinline__ void cp16(uint32_t dst, const void* src) {
    asm volatile("cp.async.cg.shared.global [%0], [%1], 16;" :: "r"(dst), "l"(src));
}
__device__ __forceinline__ void mma_f16(float* c, const uint32_t* a, const uint32_t* b) {
    asm volatile(
        "mma.sync.aligned.m16n8k16.row.col.f32.f16.f16.f32 "
        "{%0,%1,%2,%3}, {%4,%5,%6,%7}, {%8,%9}, {%0,%1,%2,%3};"
        : "+f"(c[0]), "+f"(c[1]), "+f"(c[2]), "+f"(c[3])
        : "r"(a[0]), "r"(a[1]), "r"(a[2]), "r"(a[3]), "r"(b[0]), "r"(b[1]));
}
__device__ __forceinline__ void ldsm_x4(uint32_t& r0, uint32_t& r1, uint32_t& r2, uint32_t& r3,
                                        uint32_t addr) {
    asm volatile("ldmatrix.sync.aligned.m8n8.x4.shared.b16 {%0,%1,%2,%3}, [%4];"
                 : "=r"(r0), "=r"(r1), "=r"(r2), "=r"(r3) : "r"(addr));
}
__device__ __forceinline__ uint2 f4_to_h4(float4 x) {
    __half2 h0 = __floats2half2_rn(x.x, x.y);
    __half2 h1 = __floats2half2_rn(x.z, x.w);
    uint2 o; o.x = *(uint32_t*)&h0; o.y = *(uint32_t*)&h1;
    return o;
}

// ---------------- one-shot fp32 -> fp16 conversions ----------------
__global__ void __launch_bounds__(256) f2h1_kernel(
    const float4* __restrict__ s, uint2* __restrict__ d)
{
    const int i = blockIdx.x * 256 + threadIdx.x;
    d[i] = f4_to_h4(s[i]);
}
__global__ void __launch_bounds__(256) f2h4_kernel(
    const float4* __restrict__ s0, const float4* __restrict__ s1,
    const float4* __restrict__ s2, const float4* __restrict__ s3,
    uint2* __restrict__ d0, uint2* __restrict__ d1,
    uint2* __restrict__ d2, uint2* __restrict__ d3)
{
    const int i = blockIdx.x * 256 + threadIdx.x;
    const int z = blockIdx.z;
    const float4* s = (z == 0) ? s0 : (z == 1) ? s1 : (z == 2) ? s2 : s3;
    uint2* d        = (z == 0) ? d0 : (z == 1) ? d1 : (z == 2) ? d2 : d3;
    d[i] = f4_to_h4(s[i]);
}
__global__ void __launch_bounds__(256) f2h2_kernel(
    const float4* __restrict__ s0, const float4* __restrict__ s1,
    uint2* __restrict__ d0, uint2* __restrict__ d1)
{
    const int i = blockIdx.x * 256 + threadIdx.x;
    const float4* s = blockIdx.z ? s1 : s0;
    uint2* d        = blockIdx.z ? d1 : d0;
    d[i] = f4_to_h4(s[i]);
}

// ---------------- 128x64 fp16 GEMM mainloop (256 threads, ldmatrix, 3-stage) ----------------
#define A_ST 9216    // halves per A stage
#define W_ST 4608    // halves per W stage
#define GEMM_SMEM ((3 * A_ST + 3 * W_ST) * 2)   // 82944 B

__device__ __forceinline__ void hgemm_mainloop(
    const __half* __restrict__ Ag, const __half* __restrict__ Wg,
    __half* __restrict__ sm, int Kloop, int lda, int ldw, float acc[2][4][4])
{
    const int tid = threadIdx.x;
    const int srow = tid >> 3;
    const int scol = (tid & 7) << 3;

    __half* As = sm;
    __half* Ws = sm + 3 * A_ST;

    const uint32_t asB = (uint32_t)__cvta_generic_to_shared(As);
    const uint32_t wsB = (uint32_t)__cvta_generic_to_shared(Ws);
    const uint32_t sa0 = asB + (uint32_t)(srow * 72 + scol) * 2u;
    const uint32_t sw0 = wsB + (uint32_t)(srow * 72 + scol) * 2u;

    const __half* Agp = Ag + (long long)srow * lda + scol;
    const __half* Wgp = Wg + (long long)srow * ldw + scol;

    const int KT = Kloop >> 6;

#pragma unroll
    for (int st = 0; st < 2; st++) {
        if (st < KT) {
#pragma unroll
            for (int p = 0; p < 4; p++)
                cp16(sa0 + (uint32_t)(st * A_ST + p * 32 * 72) * 2u, Agp + (long long)(p * 32) * lda + st * 64);
#pragma unroll
            for (int p = 0; p < 2; p++)
                cp16(sw0 + (uint32_t)(st * W_ST + p * 32 * 72) * 2u, Wgp + (long long)(p * 32) * ldw + st * 64);
        }
        asm volatile("cp.async.commit_group;");
    }

    const int wid = tid >> 5, lane = tid & 31;
    const int wm = wid & 3, wn = wid >> 2;
    const int a_row = wm * 32 + (lane & 15);
    const int a_ko  = (lane >> 4) << 3;
    const int b_row = wn * 32 + (lane & 7) + ((lane >> 4) << 3);
    const int b_ko  = ((lane >> 3) & 1) << 3;

    const uint32_t aF = asB + (uint32_t)(a_row * 72 + a_ko) * 2u;
    const uint32_t wF = wsB + (uint32_t)(b_row * 72 + b_ko) * 2u;

    for (int kt = 0; kt < KT; kt++) {
        asm volatile("cp.async.wait_group 1;");
        __syncthreads();

        const int pf = kt + 2;
        if (pf < KT) {
            const int st = pf % 3;
#pragma unroll
            for (int p = 0; p < 4; p++)
                cp16(sa0 + (uint32_t)(st * A_ST + p * 32 * 72) * 2u, Agp + (long long)(p * 32) * lda + pf * 64);
#pragma unroll
            for (int p = 0; p < 2; p++)
                cp16(sw0 + (uint32_t)(st * W_ST + p * 32 * 72) * 2u, Wgp + (long long)(p * 32) * ldw + pf * 64);
        }
        asm volatile("cp.async.commit_group;");

        const uint32_t aS = aF + (uint32_t)((kt % 3) * A_ST) * 2u;
        const uint32_t wS = wF + (uint32_t)((kt % 3) * W_ST) * 2u;

#pragma unroll
        for (int ks = 0; ks < 4; ks++) {
            uint32_t a[2][4], b[2][4];
#pragma unroll
            for (int mt = 0; mt < 2; mt++)
                ldsm_x4(a[mt][0], a[mt][1], a[mt][2], a[mt][3],
                        aS + (uint32_t)(mt * 16 * 72 + ks * 16) * 2u);
#pragma unroll
            for (int nt2 = 0; nt2 < 2; nt2++)
                ldsm_x4(b[nt2][0], b[nt2][1], b[nt2][2], b[nt2][3],
                        wS + (uint32_t)(nt2 * 16 * 72 + ks * 16) * 2u);
#pragma unroll
            for (int mt = 0; mt < 2; mt++)
#pragma unroll
                for (int nt = 0; nt < 4; nt++) {
                    uint32_t bb[2] = { b[nt >> 1][(nt & 1) * 2], b[nt >> 1][(nt & 1) * 2 + 1] };
                    mma_f16(acc[mt][nt], a[mt], bb);
                }
        }
    }
}

// ---------------- generic fp16 GEMM (z-batched): C = A @ W^T (+bias, GELU, scale) ----------------
template<int EPI, int F32OUT>
__global__ void __launch_bounds__(256, 2) hgemm_g(
    const __half* __restrict__ A, const __half* __restrict__ W,
    const float* __restrict__ bias, void* __restrict__ Cv,
    int K, int ldC, long long sA, long long sW, long long sC, float scale)
{
    extern __shared__ __half smh[];
    const int bz = blockIdx.z;
    const int m0 = blockIdx.y << 7, n0 = blockIdx.x << 6;

    float acc[2][4][4];
#pragma unroll
    for (int i = 0; i < 2; i++)
#pragma unroll
        for (int j = 0; j < 4; j++)
#pragma unroll
            for (int l = 0; l < 4; l++) acc[i][j][l] = 0.f;

    hgemm_mainloop(A + sA * bz + (long long)m0 * K,
                   W + sW * bz + (long long)n0 * K, smh, K, K, K, acc);

    const int tid = threadIdx.x, wid = tid >> 5, lane = tid & 31;
    const int wm = wid & 3, wn = wid >> 2, g = lane >> 2, t = lane & 3;

#pragma unroll
    for (int mt = 0; mt < 2; mt++) {
        const int rb = m0 + wm * 32 + mt * 16 + g;
#pragma unroll
        for (int nt = 0; nt < 4; nt++) {
            const int cb = n0 + wn * 32 + nt * 8 + 2 * t;
#pragma unroll
            for (int hf = 0; hf < 2; hf++) {
                const int m = rb + hf * 8;
                float v0 = acc[mt][nt][hf * 2 + 0];
                float v1 = acc[mt][nt][hf * 2 + 1];
                if (bias) { v0 += bias[cb]; v1 += bias[cb + 1]; }
                if (EPI == 1) {
                    v0 = 0.5f * v0 * (1.0f + erff(v0 * 0.70710678118654752f));
                    v1 = 0.5f * v1 * (1.0f + erff(v1 * 0.70710678118654752f));
                }
                if (F32OUT) {
                    float* C = (float*)Cv + sC * bz;
                    *(float2*)&C[(long long)m * ldC + cb] = make_float2(v0, v1);
                } else {
                    __half* C = (__half*)Cv + sC * bz;
                    __half2 h2 = __floats2half2_rn(v0, v1);
                    *(__half2*)&C[(long long)m * ldC + cb] = h2;
                }
            }
        }
    }
}

// ---------------- split-K GEMM: part[ks] = A[:, ks*Ksplit:+Ksplit] @ W[:, same]^T ----------------
__global__ void __launch_bounds__(256, 2) hgemm_sk(
    const __half* __restrict__ A, const __half* __restrict__ W,
    float* __restrict__ part, int Kfull, int Ksplit)
{
    extern __shared__ __half smh[];
    const int ks = blockIdx.z;
    const int m0 = blockIdx.y << 7, n0 = blockIdx.x << 6;

    float acc[2][4][4];
#pragma unroll
    for (int i = 0; i < 2; i++)
#pragma unroll
        for (int j = 0; j < 4; j++)
#pragma unroll
            for (int l = 0; l < 4; l++) acc[i][j][l] = 0.f;

    hgemm_mainloop(A + (long long)m0 * Kfull + (long long)ks * Ksplit,
                   W + (long long)n0 * Kfull + (long long)ks * Ksplit,
                   smh, Ksplit, Kfull, Kfull, acc);

    float* C = part + (long long)ks * (SEQ * DM);

    const int tid = threadIdx.x, wid = tid >> 5, lane = tid & 31;
    const int wm = wid & 3, wn = wid >> 2, g = lane >> 2, t = lane & 3;

#pragma unroll
    for (int mt = 0; mt < 2; mt++) {
        const int rb = m0 + wm * 32 + mt * 16 + g;
#pragma unroll
        for (int nt = 0; nt < 4; nt++) {
            const int cb = n0 + wn * 32 + nt * 8 + 2 * t;
#pragma unroll
            for (int hf = 0; hf < 2; hf++) {
                const int m = rb + hf * 8;
                *(float2*)&C[(long long)m * DM + cb] =
                    make_float2(acc[mt][nt][hf * 2 + 0], acc[mt][nt][hf * 2 + 1]);
            }
        }
    }
}

// ---------------- fused QKV projection (fp16) ----------------
__global__ void __launch_bounds__(256, 2) hqkv_kernel(
    const __half* __restrict__ h,
    const __half* __restrict__ Wq, const __half* __restrict__ Wk, const __half* __restrict__ Wv,
    const float* __restrict__ bq, const float* __restrict__ bk, const float* __restrict__ bv,
    __half* __restrict__ qo, __half* __restrict__ ko, __half* __restrict__ vto)
{
    extern __shared__ __half smh[];
    const int z = blockIdx.z;
    const __half* W   = (z == 0) ? Wq : (z == 1) ? Wk : Wv;
    const float* bias = (z == 0) ? bq : (z == 1) ? bk : bv;
    __half* out       = (z == 0) ? qo : (z == 1) ? ko : vto;
    const float scale = (z == 0) ? 0.125f : 1.0f;
    const int m0 = blockIdx.y << 7, n0 = blockIdx.x << 6;

    float acc[2][4][4];
#pragma unroll
    for (int i = 0; i < 2; i++)
#pragma unroll
        for (int j = 0; j < 4; j++)
#pragma unroll
            for (int l = 0; l < 4; l++) acc[i][j][l] = 0.f;

    hgemm_mainloop(h + (long long)m0 * DM, W + (long long)n0 * DM, smh, DM, DM, DM, acc);

    const int tid = threadIdx.x, wid = tid >> 5, lane = tid & 31;
    const int wm = wid & 3, wn = wid >> 2, g = lane >> 2, t = lane & 3;

#pragma unroll
    for (int mt = 0; mt < 2; mt++) {
        const int rb = m0 + wm * 32 + mt * 16 + g;
#pragma unroll
        for (int nt = 0; nt < 4; nt++) {
            const int cb = n0 + wn * 32 + nt * 8 + 2 * t;
#pragma unroll
            for (int hf = 0; hf < 2; hf++) {
                const int m = rb + hf * 8;
                float v0 = (acc[mt][nt][hf * 2 + 0] + bias[cb]) * scale;
                float v1 = (acc[mt][nt][hf * 2 + 1] + bias[cb + 1]) * scale;
                if (z < 2) {
                    const long long idx = ((long long)(cb >> 6) << 16) + (long long)m * 64 + (cb & 63);
                    __half2 h2 = __floats2half2_rn(v0, v1);
                    *(__half2*)&out[idx] = h2;
                } else {
                    out[(long long)cb * 1024 + m]       = __float2half(v0);
                    out[(long long)(cb + 1) * 1024 + m] = __float2half(v1);
                }
            }
        }
    }
}

// ---------------- PV split-K GEMM (fp16 probs x fp16 vt -> fp32 partials) ----------------
__global__ void __launch_bounds__(256, 2) hgemm_pv(
    const __half* __restrict__ probs, const __half* __restrict__ vt, float* __restrict__ part)
{
    extern __shared__ __half smh[];
    const int ks = blockIdx.x;
    const int m0 = blockIdx.y << 7;
    const int hd = blockIdx.z;

    float acc[2][4][4];
#pragma unroll
    for (int i = 0; i < 2; i++)
#pragma unroll
        for (int j = 0; j < 4; j++)
#pragma unroll
            for (int l = 0; l < 4; l++) acc[i][j][l] = 0.f;

    hgemm_mainloop(probs + (long long)hd * 1048576 + (long long)m0 * 1024 + ks * 256,
                   vt + (long long)hd * 65536 + ks * 256,
                   smh, 256, 1024, 1024, acc);

    float* C = part + (long long)ks * 786432 + hd * 64;

    const int tid = threadIdx.x, wid = tid >> 5, lane = tid & 31;
    const int wm = wid & 3, wn = wid >> 2, g = lane >> 2, t = lane & 3;

#pragma unroll
    for (int mt = 0; mt < 2; mt++) {
        const int rb = m0 + wm * 32 + mt * 16 + g;
#pragma unroll
        for (int nt = 0; nt < 4; nt++) {
            const int cb = wn * 32 + nt * 8 + 2 * t;
#pragma unroll
            for (int hf = 0; hf < 2; hf++) {
                const int m = rb + hf * 8;
                *(float2*)&C[(long long)m * 768 + cb] =
                    make_float2(acc[mt][nt][hf * 2 + 0], acc[mt][nt][hf * 2 + 1]);
            }
        }
    }
}

// ---------------- PV reduce: ctx(fp16) = sum of 4 fp32 partials ----------------
__global__ void __launch_bounds__(256) pv_reduce(
    const float4* __restrict__ part, uint2* __restrict__ ctx)
{
    const int i = blockIdx.x * 256 + threadIdx.x;
    float4 a = part[i];
    const float4 b = part[i + 196608];
    const float4 c = part[i + 393216];
    const float4 d = part[i + 589824];
    a.x += b.x + c.x + d.x; a.y += b.y + c.y + d.y;
    a.z += b.z + c.z + d.z; a.w += b.w + c.w + d.w;
    ctx[i] = f4_to_h4(a);
}

// ---------------- shared softmax epilogue (warp-parallel) ----------------
#define SC_PITCH 1032
#define RS_QPITCH 72
#define RS_RPITCH 72

__device__ __forceinline__ void softmax_epilogue(
    const float* __restrict__ sscores, const float* __restrict__ smask,
    __half* __restrict__ probs, int s, int wid, int lane)
{
#pragma unroll
    for (int hh = 0; hh < 2; hh++) {
        if (hh == 1 && wid >= 4) break;
        const int n = hh ? (8 + wid) : wid;

        float4 v[8];
        float m = -1e30f;
#pragma unroll
        for (int j = 0; j < 8; j++) {
            const int c4 = (lane + 32 * j) << 2;
            float4 a = *(const float4*)&sscores[n * SC_PITCH + c4];
            const float4 mk = *(const float4*)&smask[c4];
            a.x += mk.x; a.y += mk.y; a.z += mk.z; a.w += mk.w;
            v[j] = a;
            m = fmaxf(m, fmaxf(fmaxf(a.x, a.y), fmaxf(a.z, a.w)));
        }
        m = warpRedMax(m);

        float sum = 0.f;
#pragma unroll
        for (int j = 0; j < 8; j++) {
            v[j].x = __expf(v[j].x - m); v[j].y = __expf(v[j].y - m);
            v[j].z = __expf(v[j].z - m); v[j].w = __expf(v[j].w - m);
            sum += v[j].x + v[j].y + v[j].z + v[j].w;
        }
        sum = warpRedSum(sum);
        const float inv = 1.0f / sum;

        __half* prow = probs + (((long long)n << 10) + s) * 1024;
#pragma unroll
        for (int j = 0; j < 8; j++) {
            const int c4 = (lane + 32 * j) << 2;
            __half2 p0 = __floats2half2_rn(v[j].x * inv, v[j].y * inv);
            __half2 p1 = __floats2half2_rn(v[j].z * inv, v[j].w * inv);
            uint2 o; o.x = *(uint32_t*)&p0; o.y = *(uint32_t*)&p1;
            *(uint2*)&prow[c4] = o;
        }
    }
}

// ---------------- layer-0 fused: relsum build + rel-score + mask + softmax ----------------
// Reads the three fp32 rel tensors (register-staged), writes fp16 relsum (for layers 1-3),
// accumulates the rel MMA into prefetched scores, then softmax -> probs.
// smem: qs 2304 | sscores 49536 | smask 4096 | relb 2x64x72 fp16 = 18432  -> 74368 B
#define RS0_SMEM 74368

__global__ void __launch_bounds__(256) rs0_kernel(
    const float4* __restrict__ r0, const float4* __restrict__ r1,
    const float4* __restrict__ r2, uint2* __restrict__ rsum,
    const __half* __restrict__ qb, const float* __restrict__ scores,
    __half* __restrict__ probs, const float* __restrict__ mask)
{
    extern __shared__ char smc[];
    __half* qs      = (__half*)smc;
    float*  sscores = (float*)(smc + 2304);
    float*  smask   = (float*)(smc + 51840);
    __half* relb    = (__half*)(smc + 55936);

    const int s = blockIdx.x;
    const int tid = threadIdx.x;
    const int wid = tid >> 5, lane = tid & 31;
    const int g = lane >> 2, t = lane & 3;

    // prefetch 12 fp32 score rows + mask via cp.async
    {
        const uint32_t ss_s = (uint32_t)__cvta_generic_to_shared(sscores);
#pragma unroll
        for (int p = 0; p < 12; p++) {
            const int idx = tid + 256 * p;
            const int n = idx >> 8, c4 = (idx & 255) << 2;
            cp16(ss_s + (uint32_t)(n * SC_PITCH + c4) * 4u,
                 scores + (((long long)n << 10) + s) * 1024 + c4);
        }
        cp16((uint32_t)__cvta_generic_to_shared(smask) + (uint32_t)(tid << 4),
             mask + (tid << 2));
        asm volatile("cp.async.commit_group;");
    }

    // q tile (fp16, rows 12..15 zero)
    for (int i = tid; i < 16 * 64; i += 256) {
        const int r = i >> 6, c = i & 63;
        qs[r * RS_QPITCH + c] = (r < 12) ? qb[((long long)r << 16) + (s << 6) + c] : __float2half(0.f);
    }

    // preload chunk 0 (64 rel rows = 1024 float4 per tensor; 4 float4/tensor/thread)
    const long long base = ((long long)s << 14);   // float4 index base: s*16384
    float4 ra[4], rb4[4], rc[4];
#pragma unroll
    for (int p = 0; p < 4; p++) {
        const long long idx = base + tid + 256 * p;
        ra[p] = r0[idx]; rb4[p] = r1[idx]; rc[p] = r2[idx];
    }

    asm volatile("cp.async.wait_group 0;");
    __syncthreads();

    uint32_t afrag[4][4];
#pragma unroll
    for (int ks = 0; ks < 4; ks++) {
        afrag[ks][0] = *(const uint32_t*)&qs[g * RS_QPITCH + ks * 16 + 2 * t];
        afrag[ks][1] = *(const uint32_t*)&qs[(g + 8) * RS_QPITCH + ks * 16 + 2 * t];
        afrag[ks][2] = *(const uint32_t*)&qs[g * RS_QPITCH + ks * 16 + 2 * t + 8];
        afrag[ks][3] = *(const uint32_t*)&qs[(g + 8) * RS_QPITCH + ks * 16 + 2 * t + 8];
    }

    const int lrb = wid * 8;
    const int lr  = lrb + g;

    for (int ch = 0; ch < 16; ch++) {
        // convert + store chunk to smem buffer and global relsum
        __half* rbuf = relb + (ch & 1) * (64 * RS_RPITCH);
#pragma unroll
        for (int p = 0; p < 4; p++) {
            float4 x = ra[p];
            x.x += rb4[p].x + rc[p].x; x.y += rb4[p].y + rc[p].y;
            x.z += rb4[p].z + rc[p].z; x.w += rb4[p].w + rc[p].w;
            const uint2 hv = f4_to_h4(x);
            const int il = tid + 256 * p;
            const int r = il >> 4, c4 = (il & 15) << 2;
            *(uint2*)&rbuf[r * RS_RPITCH + c4] = hv;
            rsum[base + (long long)ch * 1024 + il] = hv;
        }
        __syncthreads();

        // issue loads for next chunk (overlap with MMA below)
        if (ch + 1 < 16) {
#pragma unroll
            for (int p = 0; p < 4; p++) {
                const long long idx = base + (long long)(ch + 1) * 1024 + tid + 256 * p;
                ra[p] = r0[idx]; rb4[p] = r1[idx]; rc[p] = r2[idx];
            }
        }

        float c[4] = {0.f, 0.f, 0.f, 0.f};
#pragma unroll
        for (int ks = 0; ks < 4; ks++) {
            uint32_t bb[2];
            bb[0] = *(const uint32_t*)&rbuf[lr * RS_RPITCH + ks * 16 + 2 * t];
            bb[1] = *(const uint32_t*)&rbuf[lr * RS_RPITCH + ks * 16 + 2 * t + 8];
            mma_f16(c, afrag[ks], bb);
        }
        const int kc = ch * 64 + lrb + 2 * t;
        float2 o0 = *(float2*)&sscores[g * SC_PITCH + kc];
        o0.x += c[0]; o0.y += c[1];
        *(float2*)&sscores[g * SC_PITCH + kc] = o0;
        if (g < 4) {
            float2 o1 = *(float2*)&sscores[(g + 8) * SC_PITCH + kc];
            o1.x += c[2]; o1.y += c[3];
            *(float2*)&sscores[(g + 8) * SC_PITCH + kc] = o1;
        }
    }
    __syncthreads();

    softmax_epilogue(sscores, smask, probs, s, wid, lane);
}

// ---------------- layers 1-3: rel-score + mask + softmax (fp16 relsum, 6-deep pipeline) ----------------
#define RS_CROWS 64
#define RS_CHUNK_H (RS_CROWS * RS_RPITCH)
#define RS_NBUF 6
#define RS_NCHUNK 16
#define RS_SMEM 111232

__global__ void __launch_bounds__(256) rel_softmax_kernel(
    const __half* __restrict__ rel, const __half* __restrict__ qb,
    const float* __restrict__ scores, __half* __restrict__ probs,
    const float* __restrict__ mask)
{
    extern __shared__ char smc[];
    __half* qs      = (__half*)smc;
    float*  sscores = (float*)(smc + 2304);
    float*  smask   = (float*)(smc + 51840);
    __half* relb    = (__half*)(smc + 55936);

    const int s = blockIdx.x;
    const int tid = threadIdx.x;
    const int wid = tid >> 5, lane = tid & 31;
    const int g = lane >> 2, t = lane & 3;

    {
        const uint32_t ss_s = (uint32_t)__cvta_generic_to_shared(sscores);
#pragma unroll
        for (int p = 0; p < 12; p++) {
            const int idx = tid + 256 * p;
            const int n = idx >> 8, c4 = (idx & 255) << 2;
            cp16(ss_s + (uint32_t)(n * SC_PITCH + c4) * 4u,
                 scores + (((long long)n << 10) + s) * 1024 + c4);
        }
        cp16((uint32_t)__cvta_generic_to_shared(smask) + (uint32_t)(tid << 4),
             mask + (tid << 2));
        asm volatile("cp.async.commit_group;");
    }

    for (int i = tid; i < 16 * 64; i += 256) {
        const int r = i >> 6, c = i & 63;
        qs[r * RS_QPITCH + c] = (r < 12) ? qb[((long long)r << 16) + (s << 6) + c] : __float2half(0.f);
    }

    const __half* relS = rel + ((long long)s << 16);
    const uint32_t relb_s = (uint32_t)__cvta_generic_to_shared(relb);

#pragma unroll
    for (int ch = 0; ch < RS_NBUF - 1; ch++) {
        const uint32_t dstb = relb_s + (uint32_t)(ch * RS_CHUNK_H) * 2u;
        const __half* src = relS + (long long)ch * RS_CROWS * 64;
#pragma unroll
        for (int p = 0; p < 2; p++) {
            const int idx = tid + 256 * p;
            const int r = idx >> 3, c8 = (idx & 7) << 3;
            cp16(dstb + (uint32_t)(r * RS_RPITCH + c8) * 2u, src + (long long)r * 64 + c8);
        }
        asm volatile("cp.async.commit_group;");
    }

    __syncthreads();

    uint32_t afrag[4][4];
#pragma unroll
    for (int ks = 0; ks < 4; ks++) {
        afrag[ks][0] = *(const uint32_t*)&qs[g * RS_QPITCH + ks * 16 + 2 * t];
        afrag[ks][1] = *(const uint32_t*)&qs[(g + 8) * RS_QPITCH + ks * 16 + 2 * t];
        afrag[ks][2] = *(const uint32_t*)&qs[g * RS_QPITCH + ks * 16 + 2 * t + 8];
        afrag[ks][3] = *(const uint32_t*)&qs[(g + 8) * RS_QPITCH + ks * 16 + 2 * t + 8];
    }

    const int lrb = wid * 8;
    const int lr  = lrb + g;

    for (int ch = 0; ch < RS_NCHUNK; ch++) {
        asm volatile("cp.async.wait_group 4;");
        __syncthreads();

        const int pf = ch + RS_NBUF - 1;
        if (pf < RS_NCHUNK) {
            const uint32_t dstb = relb_s + (uint32_t)((pf % RS_NBUF) * RS_CHUNK_H) * 2u;
            const __half* src = relS + (long long)pf * RS_CROWS * 64;
#pragma unroll
            for (int p = 0; p < 2; p++) {
                const int idx = tid + 256 * p;
                const int r = idx >> 3, c8 = (idx & 7) << 3;
                cp16(dstb + (uint32_t)(r * RS_RPITCH + c8) * 2u, src + (long long)r * 64 + c8);
            }
        }
        asm volatile("cp.async.commit_group;");

        const __half* rb = relb + (ch % RS_NBUF) * RS_CHUNK_H;
        float c[4] = {0.f, 0.f, 0.f, 0.f};
#pragma unroll
        for (int ks = 0; ks < 4; ks++) {
            uint32_t bb[2];
            bb[0] = *(const uint32_t*)&rb[lr * RS_RPITCH + ks * 16 + 2 * t];
            bb[1] = *(const uint32_t*)&rb[lr * RS_RPITCH + ks * 16 + 2 * t + 8];
            mma_f16(c, afrag[ks], bb);
        }
        const int kc = ch * RS_CROWS + lrb + 2 * t;
        float2 o0 = *(float2*)&sscores[g * SC_PITCH + kc];
        o0.x += c[0]; o0.y += c[1];
        *(float2*)&sscores[g * SC_PITCH + kc] = o0;
        if (g < 4) {
            float2 o1 = *(float2*)&sscores[(g + 8) * SC_PITCH + kc];
            o1.x += c[2]; o1.y += c[3];
            *(float2*)&sscores[(g + 8) * SC_PITCH + kc] = o1;
        }
    }
    __syncthreads();

    softmax_epilogue(sscores, smask, probs, s, wid, lane);
}

// ---------------- split-K reduce + bias + residual + LayerNorm ----------------
template<int NPART, int F32OUT>
__global__ void __launch_bounds__(256) ln_red_kernel(
    const float* __restrict__ part, const float* __restrict__ bias,
    const __half* __restrict__ res,
    const float* __restrict__ g, const float* __restrict__ b, void* __restrict__ outv)
{
    const int s = blockIdx.x;
    const int tid = threadIdx.x;
    const int lane = tid & 31, wid = tid >> 5;
    __shared__ float red[8];

    float v[3];
    float lsum = 0.f;
#pragma unroll
    for (int i = 0; i < 3; i++) {
        const int idx = tid + i * 256;
        float acc = bias[idx] + __half2float(res[s * 768 + idx]);
#pragma unroll
        for (int p = 0; p < NPART; p++)
            acc += part[(long long)p * (SEQ * DM) + s * 768 + idx];
        v[i] = acc;
        lsum += acc;
    }
    lsum = warpRedSum(lsum);
    if (lane == 0) red[wid] = lsum;
    __syncthreads();
    float tot = 0.f;
#pragma unroll
    for (int i = 0; i < 8; i++) tot += red[i];
    const float mu = tot * (1.0f / 768.0f);
    __syncthreads();

    float ls2 = 0.f;
#pragma unroll
    for (int i = 0; i < 3; i++) { const float d = v[i] - mu; ls2 += d * d; }
    ls2 = warpRedSum(ls2);
    if (lane == 0) red[wid] = ls2;
    __syncthreads();
    float tot2 = 0.f;
#pragma unroll
    for (int i = 0; i < 8; i++) tot2 += red[i];
    const float rs = rsqrtf(tot2 * (1.0f / 768.0f) + 1e-12f);

#pragma unroll
    for (int i = 0; i < 3; i++) {
        const int idx = tid + i * 256;
        const float o = (v[i] - mu) * rs * g[idx] + b[idx];
        if (F32OUT) ((float*)outv)[s * 768 + idx] = o;
        else        ((__half*)outv)[s * 768 + idx] = __float2half(o);
    }
}

// ---------------- launcher ----------------
extern "C" void kernel_launch(void* const* d_in, const int* in_sizes, int n_in,
                              void* d_out, int out_size)
{
    const float* hid  = (const float*)d_in[0];
    const float* mask = (const float*)d_in[1];
    const float* rel  = (const float*)d_in[2];
    const float* rel2 = (const float*)d_in[3];
    const float* rela = (const float*)d_in[4];
    const float* Wq = (const float*)d_in[5];   const float* bq = (const float*)d_in[6];
    const float* Wk = (const float*)d_in[7];   const float* bk = (const float*)d_in[8];
    const float* Wv = (const float*)d_in[9];   const float* bv = (const float*)d_in[10];
    const float* Wo = (const float*)d_in[11];  const float* bo = (const float*)d_in[12];
    const float* g1 = (const float*)d_in[13];  const float* b1 = (const float*)d_in[14];
    const float* Wi = (const float*)d_in[15];  const float* bi = (const float*)d_in[16];
    const float* W2 = (const float*)d_in[17];  const float* b2 = (const float*)d_in[18];
    const float* g2 = (const float*)d_in[19];  const float* b2g = (const float*)d_in[20];

    __half *relsum, *probs, *h16, *hbuf, *q, *k, *vt, *ctx, *attn, *inter;
    __half *wq16, *wk16, *wv16, *wo16, *wi16, *w216;
    float *scores, *part;
    cudaGetSymbolAddress((void**)&relsum, g_relsum);
    cudaGetSymbolAddress((void**)&scores, g_scores);
    cudaGetSymbolAddress((void**)&probs, g_probs);
    cudaGetSymbolAddress((void**)&part, g_part);
    cudaGetSymbolAddress((void**)&h16, g_h16);
    cudaGetSymbolAddress((void**)&hbuf, g_hbuf);
    cudaGetSymbolAddress((void**)&q, g_q);
    cudaGetSymbolAddress((void**)&k, g_k);
    cudaGetSymbolAddress((void**)&vt, g_vt);
    cudaGetSymbolAddress((void**)&ctx, g_ctx);
    cudaGetSymbolAddress((void**)&attn, g_attn);
    cudaGetSymbolAddress((void**)&inter, g_inter);
    cudaGetSymbolAddress((void**)&wq16, g_wq16);
    cudaGetSymbolAddress((void**)&wk16, g_wk16);
    cudaGetSymbolAddress((void**)&wv16, g_wv16);
    cudaGetSymbolAddress((void**)&wo16, g_wo16);
    cudaGetSymbolAddress((void**)&wi16, g_wi16);
    cudaGetSymbolAddress((void**)&w216, g_w216);

    cudaFuncSetAttribute(hgemm_g<0, 0>, cudaFuncAttributeMaxDynamicSharedMemorySize, GEMM_SMEM);
    cudaFuncSetAttribute(hgemm_g<0, 1>, cudaFuncAttributeMaxDynamicSharedMemorySize, GEMM_SMEM);
    cudaFuncSetAttribute(hgemm_g<1, 0>, cudaFuncAttributeMaxDynamicSharedMemorySize, GEMM_SMEM);
    cudaFuncSetAttribute(hgemm_sk, cudaFuncAttributeMaxDynamicSharedMemorySize, GEMM_SMEM);
    cudaFuncSetAttribute(hqkv_kernel, cudaFuncAttributeMaxDynamicSharedMemorySize, GEMM_SMEM);
    cudaFuncSetAttribute(hgemm_pv, cudaFuncAttributeMaxDynamicSharedMemorySize, GEMM_SMEM);
    cudaFuncSetAttribute(rel_softmax_kernel, cudaFuncAttributeMaxDynamicSharedMemorySize, RS_SMEM);
    cudaFuncSetAttribute(rs0_kernel, cudaFuncAttributeMaxDynamicSharedMemorySize, RS0_SMEM);

    // side stream + events (created once; reused; graph fork/join pattern)
    static cudaStream_t s_side = nullptr;
    static cudaEvent_t ev_fork = nullptr, ev_join = nullptr;
    if (s_side == nullptr) {
        cudaStreamCreateWithFlags(&s_side, cudaStreamNonBlocking);
        cudaEventCreateWithFlags(&ev_fork, cudaEventDisableTiming);
        cudaEventCreateWithFlags(&ev_join, cudaEventDisableTiming);
    }

    // fork: FFN weight conversion on side stream (hidden under layer-0 qkv/qk/rs0)
    cudaEventRecord(ev_fork, 0);
    cudaStreamWaitEvent(s_side, ev_fork, 0);
    f2h2_kernel<<<dim3(NLAYERS * DFF * DM / 4 / 256, 1, 2), 256, 0, s_side>>>(
        (const float4*)Wi, (const float4*)W2, (uint2*)wi16, (uint2*)w216);
    cudaEventRecord(ev_join, s_side);

    // main: hidden + attention weights (needed immediately by layer-0 qkv)
    f2h1_kernel<<<SEQ * DM / 4 / 256, 256>>>((const float4*)hid, (uint2*)h16);
    f2h4_kernel<<<dim3(NLAYERS * DM * DM / 4 / 256, 1, 4), 256>>>(
        (const float4*)Wq, (const float4*)Wk, (const float4*)Wv, (const float4*)Wo,
        (uint2*)wq16, (uint2*)wk16, (uint2*)wv16, (uint2*)wo16);

    const __half* h = h16;
    for (int l = 0; l < NLAYERS; l++) {
        const size_t wofs  = (size_t)l * DM * DM;
        const size_t wiofs = (size_t)l * DFF * DM;

        // fused Q/K/V projections
        hqkv_kernel<<<dim3(12, 8, 3), 256, GEMM_SMEM>>>(
            h, wq16 + wofs, wk16 + wofs, wv16 + wofs,
            bq + l * 768, bk + l * 768, bv + l * 768, q, k, vt);

        // logits = q @ k^T (fp32 out)
        hgemm_g<0, 1><<<dim3(16, 8, 12), 256, GEMM_SMEM>>>(
            q, k, nullptr, scores, 64, 1024, 65536LL, 65536LL, 1048576LL, 1.0f);

        // + rel term + mask + softmax -> fp16 probs
        if (l == 0) {
            // fused: build relsum from the 3 fp32 tensors while computing layer-0 rel term
            rs0_kernel<<<1024, 256, RS0_SMEM>>>(
                (const float4*)rel, (const float4*)rel2, (const float4*)rela,
                (uint2*)relsum, q, scores, probs, mask);
        } else {
            rel_softmax_kernel<<<1024, 256, RS_SMEM>>>(relsum, q, scores, probs, mask);
        }

        // ctx = probs @ v  (split-K=4)
        hgemm_pv<<<dim3(4, 8, 12), 256, GEMM_SMEM>>>(probs, vt, part);
        pv_reduce<<<768, 256>>>((const float4*)part, (uint2*)ctx);

        // output projection: split-K=2, reduce+bias+residual+LN fused
        hgemm_sk<<<dim3(12, 8, 2), 256, GEMM_SMEM>>>(ctx, wo16 + wofs, part, 768, 384);
        ln_red_kernel<2, 0><<<1024, 256>>>(part, bo + l * 768, h,
                                           g1 + l * 768, b1 + l * 768, attn);

        // join FFN-weight conversion before first use
        if (l == 0) cudaStreamWaitEvent(0, ev_join, 0);

        // FFN
        hgemm_g<1, 0><<<dim3(48, 8, 1), 256, GEMM_SMEM>>>(
            attn, wi16 + wiofs, bi + l * 3072, inter, 768, 3072, 0, 0, 0, 1.0f);

        // FFN2: split-K=4, reduce+bias+residual+LN fused
        hgemm_sk<<<dim3(12, 8, 4), 256, GEMM_SMEM>>>(inter, w216 + wiofs, part, 3072, 768);
        if (l == NLAYERS - 1) {
            ln_red_kernel<4, 1><<<1024, 256>>>(part, b2 + l * 768, attn,
                                               g2 + l * 768, b2g + l * 768, d_out);
        } else {
            ln_red_kernel<4, 0><<<1024, 256>>>(part, b2 + l * 768, attn,
                                               g2 + l * 768, b2g + l * 768, hbuf);
        }
        h = hbuf;
    }
}